// round 2
// baseline (speedup 1.0000x reference)
#include <cuda_runtime.h>
#include <cuda_bf16.h>
#include <cstddef>

// Problem constants
#define NHh 8
#define NLl 4
#define NPp 4
#define HDd 32
#define Dm  256
#define Bb  2
#define Ss  13294          // 100*100 + 50*50 + 25*25 + 13*13
#define LQ  13294
#define MROWS (Bb * LQ)    // 26588

// Scratch (allocation-free: __device__ globals)
__device__ float g_val [Bb * Ss * Dm];   // projected value, (B,S,NH,HD) flattened
__device__ float g_off [Bb * LQ * Dm];   // sampling offsets, (B,L,256)
__device__ float g_attn[Bb * LQ * 128];  // attention logits, (B,L,128)
__device__ float g_acc [Bb * LQ * Dm];   // pre-output accumulator, (B,L,256)

// ---------------------------------------------------------------------------
// Tiled fp32 GEMM: C[M,N] = A[M,K] @ B[K,N] + bias[N]
// (measured at ~fp32 FFMA issue roofline — do not touch; tensor-core path is
//  the next-round replacement)
// ---------------------------------------------------------------------------
__global__ __launch_bounds__(256) void gemm_bias_kernel(
    const float* __restrict__ A, const float* __restrict__ Bw,
    const float* __restrict__ bias, float* __restrict__ C,
    int M, int N, int K)
{
    __shared__ float As[16][65];   // [k][m]
    __shared__ float Bs[16][68];   // [k][n]

    const int tid = threadIdx.x;
    const int tx  = tid & 15;
    const int ty  = tid >> 4;
    const int bm  = blockIdx.y * 64;
    const int bn  = blockIdx.x * 64;

    const int aRow = tid >> 2, aC4 = tid & 3;
    const int bRow = tid >> 4, bC4 = tid & 15;

    float acc[4][4] = {};

    for (int k0 = 0; k0 < K; k0 += 16) {
        float4 av = make_float4(0.f, 0.f, 0.f, 0.f);
        const int gr = bm + aRow;
        if (gr < M)
            av = *reinterpret_cast<const float4*>(A + (size_t)gr * K + k0 + aC4 * 4);
        As[aC4 * 4 + 0][aRow] = av.x;
        As[aC4 * 4 + 1][aRow] = av.y;
        As[aC4 * 4 + 2][aRow] = av.z;
        As[aC4 * 4 + 3][aRow] = av.w;

        const float4 bv = *reinterpret_cast<const float4*>(
            Bw + (size_t)(k0 + bRow) * N + bn + bC4 * 4);
        *reinterpret_cast<float4*>(&Bs[bRow][bC4 * 4]) = bv;

        __syncthreads();

        #pragma unroll
        for (int k = 0; k < 16; k++) {
            float a[4], bf[4];
            #pragma unroll
            for (int i = 0; i < 4; i++) a[i]  = As[k][ty * 4 + i];
            #pragma unroll
            for (int j = 0; j < 4; j++) bf[j] = Bs[k][tx * 4 + j];
            #pragma unroll
            for (int i = 0; i < 4; i++)
                #pragma unroll
                for (int j = 0; j < 4; j++)
                    acc[i][j] += a[i] * bf[j];
        }
        __syncthreads();
    }

    #pragma unroll
    for (int i = 0; i < 4; i++) {
        const int r = bm + ty * 4 + i;
        if (r < M) {
            #pragma unroll
            for (int j = 0; j < 4; j++) {
                const int c = bn + tx * 4 + j;
                C[(size_t)r * N + c] = acc[i][j] + bias[c];
            }
        }
    }
}

// ---------------------------------------------------------------------------
// Sampling kernel v2: one warp per (b, q); lanes cover 4 heads x 8 channel-
// quads (float4). Two passes over head-halves. Coordinate math for 4 heads
// runs in parallel across lane groups (4x fewer issued instructions vs v1).
// Branchless bilinear (clamp + mask) avoids lane-group divergence.
// ---------------------------------------------------------------------------
__global__ __launch_bounds__(256) void sample_kernel(
    const float* __restrict__ refp,   // (B, L, NL, 2)
    const float* __restrict__ val,    // (B, S, 256)
    const float* __restrict__ off,    // (B, L, 256)
    const float* __restrict__ attn,   // (B, L, 128)
    float* __restrict__ out_acc)      // (B, L, 256)
{
    const int bq = blockIdx.x * 8 + (threadIdx.x >> 5);
    if (bq >= Bb * LQ) return;
    const int lane = threadIdx.x & 31;
    const int hg   = lane >> 3;          // head subgroup 0..3
    const int c    = (lane & 7) * 4;     // channel offset within head
    const int b    = bq / LQ;

    // reference points (identical across lanes; L1 broadcast)
    float rx0 = refp[(size_t)bq * 8 + 0] * 100.f - 0.5f;
    float ry0 = refp[(size_t)bq * 8 + 1] * 100.f - 0.5f;
    float rx1 = refp[(size_t)bq * 8 + 2] * 50.f  - 0.5f;
    float ry1 = refp[(size_t)bq * 8 + 3] * 50.f  - 0.5f;
    float rx2 = refp[(size_t)bq * 8 + 4] * 25.f  - 0.5f;
    float ry2 = refp[(size_t)bq * 8 + 5] * 25.f  - 0.5f;
    float rx3 = refp[(size_t)bq * 8 + 6] * 13.f  - 0.5f;
    float ry3 = refp[(size_t)bq * 8 + 7] * 13.f  - 0.5f;
    const float rxl[4] = {rx0, rx1, rx2, rx3};
    const float ryl[4] = {ry0, ry1, ry2, ry3};

    for (int half = 0; half < 2; half++) {
        const int h = half * 4 + hg;

        // ---- softmax over this head's 16 logits (uniform within 8-lane group)
        const float4* at4 = reinterpret_cast<const float4*>(
            attn + (size_t)bq * 128 + h * 16);
        float lg[16];
        {
            float4 t0 = at4[0], t1 = at4[1], t2 = at4[2], t3 = at4[3];
            lg[0]=t0.x; lg[1]=t0.y; lg[2]=t0.z; lg[3]=t0.w;
            lg[4]=t1.x; lg[5]=t1.y; lg[6]=t1.z; lg[7]=t1.w;
            lg[8]=t2.x; lg[9]=t2.y; lg[10]=t2.z; lg[11]=t2.w;
            lg[12]=t3.x; lg[13]=t3.y; lg[14]=t3.z; lg[15]=t3.w;
        }
        float mx = lg[0];
        #pragma unroll
        for (int j = 1; j < 16; j++) mx = fmaxf(mx, lg[j]);
        float e[16], s = 0.f;
        #pragma unroll
        for (int j = 0; j < 16; j++) { e[j] = __expf(lg[j] - mx); s += e[j]; }
        const float inv = 1.0f / s;

        const float* of = off + (size_t)bq * 256 + h * 32;
        float4 acc = make_float4(0.f, 0.f, 0.f, 0.f);

        const int lWc[4] = {100, 50, 25, 13};
        const int lHc[4] = {100, 50, 25, 13};
        const int lSc[4] = {0, 10000, 12500, 13125};

        #pragma unroll
        for (int l = 0; l < 4; l++) {
            const int W = lWc[l], H = lHc[l];
            const float* vb = val + ((size_t)(b * Ss + lSc[l])) * 256 + h * 32 + c;
            const float rx = rxl[l], ry = ryl[l];
            const float4 o01 = reinterpret_cast<const float4*>(of + l * 8)[0];
            const float4 o23 = reinterpret_cast<const float4*>(of + l * 8)[1];
            const float ox[4] = {o01.x, o01.z, o23.x, o23.z};
            const float oy[4] = {o01.y, o01.w, o23.y, o23.w};

            #pragma unroll
            for (int p = 0; p < 4; p++) {
                const float x = rx + ox[p];
                const float y = ry + oy[p];
                const float wgt = e[l * 4 + p] * inv;

                const float fx0 = floorf(x), fy0 = floorf(y);
                const int x0 = (int)fx0, y0 = (int)fy0;
                const float wx1 = x - fx0, wy1 = y - fy0;
                const float wx0 = 1.f - wx1, wy0 = 1.f - wy1;

                const float mx0 = (x0 >= 0     && x0 < W)     ? 1.f : 0.f;
                const float mx1 = (x0 + 1 >= 0 && x0 + 1 < W) ? 1.f : 0.f;
                const float my0 = (y0 >= 0     && y0 < H)     ? 1.f : 0.f;
                const float my1 = (y0 + 1 >= 0 && y0 + 1 < H) ? 1.f : 0.f;

                const int xc0 = min(max(x0, 0), W - 1);
                const int xc1 = min(max(x0 + 1, 0), W - 1);
                const int yc0 = min(max(y0, 0), H - 1);
                const int yc1 = min(max(y0 + 1, 0), H - 1);

                const float w00 = wgt * wx0 * wy0 * mx0 * my0;
                const float w10 = wgt * wx1 * wy0 * mx1 * my0;
                const float w01 = wgt * wx0 * wy1 * mx0 * my1;
                const float w11 = wgt * wx1 * wy1 * mx1 * my1;

                const float4 v00 = *reinterpret_cast<const float4*>(vb + (size_t)(yc0 * W + xc0) * 256);
                const float4 v10 = *reinterpret_cast<const float4*>(vb + (size_t)(yc0 * W + xc1) * 256);
                const float4 v01 = *reinterpret_cast<const float4*>(vb + (size_t)(yc1 * W + xc0) * 256);
                const float4 v11 = *reinterpret_cast<const float4*>(vb + (size_t)(yc1 * W + xc1) * 256);

                acc.x += w00 * v00.x + w10 * v10.x + w01 * v01.x + w11 * v11.x;
                acc.y += w00 * v00.y + w10 * v10.y + w01 * v01.y + w11 * v11.y;
                acc.z += w00 * v00.z + w10 * v10.z + w01 * v01.z + w11 * v11.z;
                acc.w += w00 * v00.w + w10 * v10.w + w01 * v01.w + w11 * v11.w;
            }
        }

        *reinterpret_cast<float4*>(out_acc + (size_t)bq * 256 + h * 32 + c) = acc;
    }
}

// ---------------------------------------------------------------------------
// Launch
// ---------------------------------------------------------------------------
extern "C" void kernel_launch(void* const* d_in, const int* in_sizes, int n_in,
                              void* d_out, int out_size)
{
    const float* query  = (const float*)d_in[0];
    const float* refp   = (const float*)d_in[1];
    const float* value  = (const float*)d_in[2];
    const float* W_val  = (const float*)d_in[3];
    const float* b_val  = (const float*)d_in[4];
    const float* W_off  = (const float*)d_in[5];
    const float* b_off  = (const float*)d_in[6];
    const float* W_attn = (const float*)d_in[7];
    const float* b_attn = (const float*)d_in[8];
    const float* W_out  = (const float*)d_in[9];
    const float* b_out  = (const float*)d_in[10];
    float* out = (float*)d_out;

    float *pval, *poff, *pattn, *pacc;
    cudaGetSymbolAddress((void**)&pval,  g_val);
    cudaGetSymbolAddress((void**)&poff,  g_off);
    cudaGetSymbolAddress((void**)&pattn, g_attn);
    cudaGetSymbolAddress((void**)&pacc,  g_acc);

    const dim3 blk(256);
    const dim3 g256(256 / 64, (MROWS + 63) / 64);
    const dim3 g128(128 / 64, (MROWS + 63) / 64);

    // 1. val = value @ W_val + b_val          (B*S, 256)
    gemm_bias_kernel<<<g256, blk>>>(value, W_val, b_val, pval, MROWS, 256, 256);
    // 2. offsets = query @ W_off + b_off      (B*L, 256)
    gemm_bias_kernel<<<g256, blk>>>(query, W_off, b_off, poff, MROWS, 256, 256);
    // 3. attn logits = query @ W_attn + b_attn (B*L, 128)
    gemm_bias_kernel<<<g128, blk>>>(query, W_attn, b_attn, pattn, MROWS, 128, 256);
    // 4. softmax + deformable bilinear sampling -> g_acc  (warp per (b,q))
    sample_kernel<<<(MROWS + 7) / 8, blk>>>(refp, pval, poff, pattn, pacc);
    // 5. out = g_acc @ W_out + b_out
    gemm_bias_kernel<<<g256, blk>>>(pacc, W_out, b_out, out, MROWS, 256, 256);
}

// round 3
// speedup vs baseline: 2.8185x; 2.8185x over previous
#include <cuda_runtime.h>
#include <cuda_bf16.h>
#include <cstdint>
#include <cstddef>

// Problem constants
#define NHh 8
#define NLl 4
#define NPp 4
#define HDd 32
#define Dm  256
#define Bb  2
#define Ss  13294          // 100*100 + 50*50 + 25*25 + 13*13
#define LQ  13294
#define MROWS (Bb * LQ)    // 26588

// Scratch (allocation-free: __device__ globals)
__device__ float g_val [Bb * Ss * Dm];
__device__ float g_off [Bb * LQ * Dm];
__device__ float g_attn[Bb * LQ * 128];
__device__ float g_acc [Bb * LQ * Dm];

__device__ __forceinline__ uint32_t f2tf32(float f) {
    uint32_t r;
    asm("cvt.rna.tf32.f32 %0, %1;" : "=r"(r) : "f"(f));
    return r;
}

// ---------------------------------------------------------------------------
// TF32 tensor-core GEMM: C[M,N] = A[M,K] @ B[K,N] + bias[N]
// BM=128, BN=128, BK=32; 256 threads = 8 warps (2 along M x 4 along N);
// warp tile 64x32 = 4x4 m16n8k8 mma tiles. K, N multiples of 32/128.
// ---------------------------------------------------------------------------
#define ASTRIDE 36    // A smem row stride (floats): frag banks = lane id (conflict-free)
#define BSTRIDE 136   // B smem row stride: banks = tig*8+gid (conflict-free)

__global__ __launch_bounds__(256) void gemm_tf32_kernel(
    const float* __restrict__ A, const float* __restrict__ Bw,
    const float* __restrict__ bias, float* __restrict__ C,
    int M, int N, int K)
{
    __shared__ uint32_t As[128 * ASTRIDE];   // [m][k] tf32
    __shared__ uint32_t Bs[32 * BSTRIDE];    // [k][n] tf32

    const int tid  = threadIdx.x;
    const int wid  = tid >> 5;
    const int lane = tid & 31;
    const int gid  = lane >> 2;      // 0..7
    const int tig  = lane & 3;       // 0..3

    const int warpM = wid >> 2;      // 0..1  -> M offset *64
    const int warpN = wid & 3;       // 0..3  -> N offset *32

    const int bm = blockIdx.y * 128;
    const int bn = blockIdx.x * 128;

    // global->shared load indexing
    const int aRow = tid >> 3;       // 0..31 (+ i*32)
    const int aC4  = (tid & 7) * 4;  // k offset
    const int bRowL = tid >> 5;      // 0..7 (+ i*8)
    const int bC4   = (tid & 31) * 4;

    float c[4][4][4];
    #pragma unroll
    for (int i = 0; i < 4; i++)
        #pragma unroll
        for (int j = 0; j < 4; j++)
            #pragma unroll
            for (int r = 0; r < 4; r++) c[i][j][r] = 0.f;

    for (int k0 = 0; k0 < K; k0 += 32) {
        // load A tile 128x32
        #pragma unroll
        for (int i = 0; i < 4; i++) {
            const int r = i * 32 + aRow;
            float4 v = make_float4(0.f, 0.f, 0.f, 0.f);
            if (bm + r < M)
                v = *reinterpret_cast<const float4*>(A + (size_t)(bm + r) * K + k0 + aC4);
            uint32_t* dst = &As[r * ASTRIDE + aC4];
            dst[0] = f2tf32(v.x); dst[1] = f2tf32(v.y);
            dst[2] = f2tf32(v.z); dst[3] = f2tf32(v.w);
        }
        // load B tile 32x128
        #pragma unroll
        for (int i = 0; i < 4; i++) {
            const int kk = i * 8 + bRowL;
            const float4 v = *reinterpret_cast<const float4*>(
                Bw + (size_t)(k0 + kk) * N + bn + bC4);
            uint32_t* dst = &Bs[kk * BSTRIDE + bC4];
            dst[0] = f2tf32(v.x); dst[1] = f2tf32(v.y);
            dst[2] = f2tf32(v.z); dst[3] = f2tf32(v.w);
        }
        __syncthreads();

        #pragma unroll
        for (int ks = 0; ks < 4; ks++) {
            const int kb = ks * 8;
            // A fragments: 4 m-tiles
            uint32_t a[4][4];
            #pragma unroll
            for (int mt = 0; mt < 4; mt++) {
                const int m0 = warpM * 64 + mt * 16 + gid;
                a[mt][0] = As[(m0    ) * ASTRIDE + kb + tig    ];
                a[mt][1] = As[(m0 + 8) * ASTRIDE + kb + tig    ];
                a[mt][2] = As[(m0    ) * ASTRIDE + kb + tig + 4];
                a[mt][3] = As[(m0 + 8) * ASTRIDE + kb + tig + 4];
            }
            // B fragments: 4 n-tiles
            uint32_t b[4][2];
            #pragma unroll
            for (int nt = 0; nt < 4; nt++) {
                const int n0 = warpN * 32 + nt * 8 + gid;
                b[nt][0] = Bs[(kb + tig    ) * BSTRIDE + n0];
                b[nt][1] = Bs[(kb + tig + 4) * BSTRIDE + n0];
            }
            #pragma unroll
            for (int mt = 0; mt < 4; mt++)
                #pragma unroll
                for (int nt = 0; nt < 4; nt++) {
                    asm volatile(
                        "mma.sync.aligned.m16n8k8.row.col.f32.tf32.tf32.f32 "
                        "{%0,%1,%2,%3}, {%4,%5,%6,%7}, {%8,%9}, {%0,%1,%2,%3};"
                        : "+f"(c[mt][nt][0]), "+f"(c[mt][nt][1]),
                          "+f"(c[mt][nt][2]), "+f"(c[mt][nt][3])
                        : "r"(a[mt][0]), "r"(a[mt][1]), "r"(a[mt][2]), "r"(a[mt][3]),
                          "r"(b[nt][0]), "r"(b[nt][1]));
                }
        }
        __syncthreads();
    }

    // epilogue: C[r][c] = acc + bias[c]
    #pragma unroll
    for (int mt = 0; mt < 4; mt++) {
        const int r0 = bm + warpM * 64 + mt * 16 + gid;
        #pragma unroll
        for (int nt = 0; nt < 4; nt++) {
            const int cc = bn + warpN * 32 + nt * 8 + tig * 2;
            const float bz0 = bias[cc], bz1 = bias[cc + 1];
            if (r0 < M) {
                float2 v = make_float2(c[mt][nt][0] + bz0, c[mt][nt][1] + bz1);
                *reinterpret_cast<float2*>(C + (size_t)r0 * N + cc) = v;
            }
            if (r0 + 8 < M) {
                float2 v = make_float2(c[mt][nt][2] + bz0, c[mt][nt][3] + bz1);
                *reinterpret_cast<float2*>(C + (size_t)(r0 + 8) * N + cc) = v;
            }
        }
    }
}

// ---------------------------------------------------------------------------
// Sampling kernel: one warp per (b, q); lanes cover 4 heads x 8 channel-quads
// (float4). Two passes over head-halves. Branchless bilinear.
// ---------------------------------------------------------------------------
__global__ __launch_bounds__(256) void sample_kernel(
    const float* __restrict__ refp,   // (B, L, NL, 2)
    const float* __restrict__ val,    // (B, S, 256)
    const float* __restrict__ off,    // (B, L, 256)
    const float* __restrict__ attn,   // (B, L, 128)
    float* __restrict__ out_acc)      // (B, L, 256)
{
    const int bq = blockIdx.x * 8 + (threadIdx.x >> 5);
    if (bq >= Bb * LQ) return;
    const int lane = threadIdx.x & 31;
    const int hg   = lane >> 3;
    const int c    = (lane & 7) * 4;
    const int b    = bq / LQ;

    float rx0 = refp[(size_t)bq * 8 + 0] * 100.f - 0.5f;
    float ry0 = refp[(size_t)bq * 8 + 1] * 100.f - 0.5f;
    float rx1 = refp[(size_t)bq * 8 + 2] * 50.f  - 0.5f;
    float ry1 = refp[(size_t)bq * 8 + 3] * 50.f  - 0.5f;
    float rx2 = refp[(size_t)bq * 8 + 4] * 25.f  - 0.5f;
    float ry2 = refp[(size_t)bq * 8 + 5] * 25.f  - 0.5f;
    float rx3 = refp[(size_t)bq * 8 + 6] * 13.f  - 0.5f;
    float ry3 = refp[(size_t)bq * 8 + 7] * 13.f  - 0.5f;
    const float rxl[4] = {rx0, rx1, rx2, rx3};
    const float ryl[4] = {ry0, ry1, ry2, ry3};

    for (int half = 0; half < 2; half++) {
        const int h = half * 4 + hg;

        const float4* at4 = reinterpret_cast<const float4*>(
            attn + (size_t)bq * 128 + h * 16);
        float lg[16];
        {
            float4 t0 = at4[0], t1 = at4[1], t2 = at4[2], t3 = at4[3];
            lg[0]=t0.x; lg[1]=t0.y; lg[2]=t0.z; lg[3]=t0.w;
            lg[4]=t1.x; lg[5]=t1.y; lg[6]=t1.z; lg[7]=t1.w;
            lg[8]=t2.x; lg[9]=t2.y; lg[10]=t2.z; lg[11]=t2.w;
            lg[12]=t3.x; lg[13]=t3.y; lg[14]=t3.z; lg[15]=t3.w;
        }
        float mx = lg[0];
        #pragma unroll
        for (int j = 1; j < 16; j++) mx = fmaxf(mx, lg[j]);
        float e[16], s = 0.f;
        #pragma unroll
        for (int j = 0; j < 16; j++) { e[j] = __expf(lg[j] - mx); s += e[j]; }
        const float inv = 1.0f / s;

        const float* of = off + (size_t)bq * 256 + h * 32;
        float4 acc = make_float4(0.f, 0.f, 0.f, 0.f);

        const int lWc[4] = {100, 50, 25, 13};
        const int lHc[4] = {100, 50, 25, 13};
        const int lSc[4] = {0, 10000, 12500, 13125};

        #pragma unroll
        for (int l = 0; l < 4; l++) {
            const int W = lWc[l], H = lHc[l];
            const float* vb = val + ((size_t)(b * Ss + lSc[l])) * 256 + h * 32 + c;
            const float rx = rxl[l], ry = ryl[l];
            const float4 o01 = reinterpret_cast<const float4*>(of + l * 8)[0];
            const float4 o23 = reinterpret_cast<const float4*>(of + l * 8)[1];
            const float ox[4] = {o01.x, o01.z, o23.x, o23.z};
            const float oy[4] = {o01.y, o01.w, o23.y, o23.w};

            #pragma unroll
            for (int p = 0; p < 4; p++) {
                const float x = rx + ox[p];
                const float y = ry + oy[p];
                const float wgt = e[l * 4 + p] * inv;

                const float fx0 = floorf(x), fy0 = floorf(y);
                const int x0 = (int)fx0, y0 = (int)fy0;
                const float wx1 = x - fx0, wy1 = y - fy0;
                const float wx0 = 1.f - wx1, wy0 = 1.f - wy1;

                const float mx0 = (x0 >= 0     && x0 < W)     ? 1.f : 0.f;
                const float mx1 = (x0 + 1 >= 0 && x0 + 1 < W) ? 1.f : 0.f;
                const float my0 = (y0 >= 0     && y0 < H)     ? 1.f : 0.f;
                const float my1 = (y0 + 1 >= 0 && y0 + 1 < H) ? 1.f : 0.f;

                const int xc0 = min(max(x0, 0), W - 1);
                const int xc1 = min(max(x0 + 1, 0), W - 1);
                const int yc0 = min(max(y0, 0), H - 1);
                const int yc1 = min(max(y0 + 1, 0), H - 1);

                const float w00 = wgt * wx0 * wy0 * mx0 * my0;
                const float w10 = wgt * wx1 * wy0 * mx1 * my0;
                const float w01 = wgt * wx0 * wy1 * mx0 * my1;
                const float w11 = wgt * wx1 * wy1 * mx1 * my1;

                const float4 v00 = *reinterpret_cast<const float4*>(vb + (size_t)(yc0 * W + xc0) * 256);
                const float4 v10 = *reinterpret_cast<const float4*>(vb + (size_t)(yc0 * W + xc1) * 256);
                const float4 v01 = *reinterpret_cast<const float4*>(vb + (size_t)(yc1 * W + xc0) * 256);
                const float4 v11 = *reinterpret_cast<const float4*>(vb + (size_t)(yc1 * W + xc1) * 256);

                acc.x += w00 * v00.x + w10 * v10.x + w01 * v01.x + w11 * v11.x;
                acc.y += w00 * v00.y + w10 * v10.y + w01 * v01.y + w11 * v11.y;
                acc.z += w00 * v00.z + w10 * v10.z + w01 * v01.z + w11 * v11.z;
                acc.w += w00 * v00.w + w10 * v10.w + w01 * v01.w + w11 * v11.w;
            }
        }

        *reinterpret_cast<float4*>(out_acc + (size_t)bq * 256 + h * 32 + c) = acc;
    }
}

// ---------------------------------------------------------------------------
// Launch
// ---------------------------------------------------------------------------
extern "C" void kernel_launch(void* const* d_in, const int* in_sizes, int n_in,
                              void* d_out, int out_size)
{
    const float* query  = (const float*)d_in[0];
    const float* refp   = (const float*)d_in[1];
    const float* value  = (const float*)d_in[2];
    const float* W_val  = (const float*)d_in[3];
    const float* b_val  = (const float*)d_in[4];
    const float* W_off  = (const float*)d_in[5];
    const float* b_off  = (const float*)d_in[6];
    const float* W_attn = (const float*)d_in[7];
    const float* b_attn = (const float*)d_in[8];
    const float* W_out  = (const float*)d_in[9];
    const float* b_out  = (const float*)d_in[10];
    float* out = (float*)d_out;

    float *pval, *poff, *pattn, *pacc;
    cudaGetSymbolAddress((void**)&pval,  g_val);
    cudaGetSymbolAddress((void**)&poff,  g_off);
    cudaGetSymbolAddress((void**)&pattn, g_attn);
    cudaGetSymbolAddress((void**)&pacc,  g_acc);

    const dim3 blk(256);
    const dim3 g256(2, (MROWS + 127) / 128);   // N=256
    const dim3 g128(1, (MROWS + 127) / 128);   // N=128

    gemm_tf32_kernel<<<g256, blk>>>(value, W_val, b_val, pval, MROWS, 256, 256);
    gemm_tf32_kernel<<<g256, blk>>>(query, W_off, b_off, poff, MROWS, 256, 256);
    gemm_tf32_kernel<<<g128, blk>>>(query, W_attn, b_attn, pattn, MROWS, 128, 256);
    sample_kernel<<<(MROWS + 7) / 8, blk>>>(refp, pval, poff, pattn, pacc);
    gemm_tf32_kernel<<<g256, blk>>>(pacc, W_out, b_out, out, MROWS, 256, 256);
}

// round 5
// speedup vs baseline: 3.0557x; 1.0842x over previous
#include <cuda_runtime.h>
#include <cuda_bf16.h>
#include <cstdint>
#include <cstddef>

// Problem constants
#define NHh 8
#define NLl 4
#define NPp 4
#define HDd 32
#define Dm  256
#define Bb  2
#define Ss  13294          // 100*100 + 50*50 + 25*25 + 13*13
#define LQ  13294
#define MROWS (Bb * LQ)    // 26588

// Scratch (allocation-free: __device__ globals)
__device__ float g_val [Bb * Ss * Dm];
__device__ float g_off [Bb * LQ * Dm];
__device__ float g_attn[Bb * LQ * 128];
__device__ float g_acc [Bb * LQ * Dm];

__device__ __forceinline__ uint32_t f2tf32(float f) {
    uint32_t r;
    asm("cvt.rna.tf32.f32 %0, %1;" : "=r"(r) : "f"(f));
    return r;
}

__device__ __forceinline__ void cp16(float* s, const float* g, bool p) {
    uint32_t sa = (uint32_t)__cvta_generic_to_shared(s);
    const int sz = p ? 16 : 0;
    asm volatile("cp.async.ca.shared.global [%0], [%1], 16, %2;"
                 :: "r"(sa), "l"(g), "r"(sz));
}

// ---------------------------------------------------------------------------
// TF32 tensor-core GEMM with cp.async 2-stage pipeline.
// C[M,N] = A[M,K] @ B[K,N] + bias[N]
// BM=128, BN=128, BK=32; 256 threads = 8 warps (2 M x 4 N); warp tile 64x32.
// Raw fp32 staged in smem; tf32 conversion at fragment read (same numerics
// as converting at store). Dynamic smem: 2 stages x 35840 B = 71680 B.
// ---------------------------------------------------------------------------
#define ASTRIDE 36    // A smem row stride (floats) — conflict-free fragments
#define BSTRIDE 136   // B smem row stride — conflict-free fragments
#define A_TILE_F (128 * ASTRIDE)            // 4608 floats
#define B_TILE_F (32 * BSTRIDE)             // 4352 floats
#define STAGE_F  (A_TILE_F + B_TILE_F)      // 8960 floats = 35840 B
#define GEMM_SMEM (2 * STAGE_F * 4)         // 71680 B

__global__ __launch_bounds__(256, 2) void gemm_tf32_kernel(
    const float* __restrict__ A, const float* __restrict__ Bw,
    const float* __restrict__ bias, float* __restrict__ C,
    int M, int N, int K)
{
    extern __shared__ float smem[];

    const int tid  = threadIdx.x;
    const int wid  = tid >> 5;
    const int lane = tid & 31;
    const int gid  = lane >> 2;      // 0..7
    const int tig  = lane & 3;       // 0..3

    const int warpM = wid >> 2;      // 0..1
    const int warpN = wid & 3;       // 0..3

    const int bm = blockIdx.y * 128;
    const int bn = blockIdx.x * 128;

    float c[4][4][4];
    #pragma unroll
    for (int i = 0; i < 4; i++)
        #pragma unroll
        for (int j = 0; j < 4; j++)
            #pragma unroll
            for (int r = 0; r < 4; r++) c[i][j][r] = 0.f;

    const int NT = K >> 5;   // 8 K-tiles

    // ---- tile copy via cp.async: A 128x32 (4 ops/thread), B 32x128 (4 ops/thread)
    auto copy_tile = [&](int kt, float* sA, float* sB) {
        const int k0 = kt * 32;
        #pragma unroll
        for (int i = 0; i < 4; i++) {
            const int o = tid * 4 + i;
            const int row = o >> 3, seg = o & 7;            // seg: 4-float chunk of k
            cp16(&sA[row * ASTRIDE + seg * 4],
                 A + (size_t)(bm + row) * K + k0 + seg * 4,
                 bm + row < M);
        }
        #pragma unroll
        for (int i = 0; i < 4; i++) {
            const int o = tid * 4 + i;
            const int row = o >> 5, seg = o & 31;           // seg: 4-float chunk of n
            cp16(&sB[row * BSTRIDE + seg * 4],
                 Bw + (size_t)(k0 + row) * N + bn + seg * 4,
                 true);
        }
    };

    copy_tile(0, smem, smem + A_TILE_F);
    asm volatile("cp.async.commit_group;");

    for (int it = 0; it < NT; it++) {
        const int cur = it & 1;
        float* sA = smem + cur * STAGE_F;
        float* sB = sA + A_TILE_F;

        if (it + 1 < NT) {
            float* nA = smem + (cur ^ 1) * STAGE_F;
            copy_tile(it + 1, nA, nA + A_TILE_F);
            asm volatile("cp.async.commit_group;");
            asm volatile("cp.async.wait_group 1;");
        } else {
            asm volatile("cp.async.wait_group 0;");
        }
        __syncthreads();

        #pragma unroll
        for (int ks = 0; ks < 4; ks++) {
            const int kb = ks * 8;
            uint32_t a[4][4];
            #pragma unroll
            for (int mt = 0; mt < 4; mt++) {
                const int m0 = warpM * 64 + mt * 16 + gid;
                a[mt][0] = f2tf32(sA[(m0    ) * ASTRIDE + kb + tig    ]);
                a[mt][1] = f2tf32(sA[(m0 + 8) * ASTRIDE + kb + tig    ]);
                a[mt][2] = f2tf32(sA[(m0    ) * ASTRIDE + kb + tig + 4]);
                a[mt][3] = f2tf32(sA[(m0 + 8) * ASTRIDE + kb + tig + 4]);
            }
            uint32_t b[4][2];
            #pragma unroll
            for (int nt = 0; nt < 4; nt++) {
                const int n0 = warpN * 32 + nt * 8 + gid;
                b[nt][0] = f2tf32(sB[(kb + tig    ) * BSTRIDE + n0]);
                b[nt][1] = f2tf32(sB[(kb + tig + 4) * BSTRIDE + n0]);
            }
            #pragma unroll
            for (int mt = 0; mt < 4; mt++)
                #pragma unroll
                for (int nt = 0; nt < 4; nt++) {
                    asm volatile(
                        "mma.sync.aligned.m16n8k8.row.col.f32.tf32.tf32.f32 "
                        "{%0,%1,%2,%3}, {%4,%5,%6,%7}, {%8,%9}, {%0,%1,%2,%3};"
                        : "+f"(c[mt][nt][0]), "+f"(c[mt][nt][1]),
                          "+f"(c[mt][nt][2]), "+f"(c[mt][nt][3])
                        : "r"(a[mt][0]), "r"(a[mt][1]), "r"(a[mt][2]), "r"(a[mt][3]),
                          "r"(b[nt][0]), "r"(b[nt][1]));
                }
        }
        __syncthreads();
    }

    // epilogue
    #pragma unroll
    for (int mt = 0; mt < 4; mt++) {
        const int r0 = bm + warpM * 64 + mt * 16 + gid;
        #pragma unroll
        for (int nt = 0; nt < 4; nt++) {
            const int cc = bn + warpN * 32 + nt * 8 + tig * 2;
            const float bz0 = bias[cc], bz1 = bias[cc + 1];
            if (r0 < M) {
                float2 v = make_float2(c[mt][nt][0] + bz0, c[mt][nt][1] + bz1);
                *reinterpret_cast<float2*>(C + (size_t)r0 * N + cc) = v;
            }
            if (r0 + 8 < M) {
                float2 v = make_float2(c[mt][nt][2] + bz0, c[mt][nt][3] + bz1);
                *reinterpret_cast<float2*>(C + (size_t)(r0 + 8) * N + cc) = v;
            }
        }
    }
}

// ---------------------------------------------------------------------------
// Sampling kernel v3: one warp per (b, q, head-half). Lanes cover 4 heads x
// 8 channel-quads (float4). Branchless bilinear. Twice the warps of v2 and
// fewer live registers per warp -> higher occupancy to hide gather latency.
// ---------------------------------------------------------------------------
__global__ __launch_bounds__(256) void sample_kernel(
    const float* __restrict__ refp,   // (B, L, NL, 2)
    const float* __restrict__ val,    // (B, S, 256)
    const float* __restrict__ off,    // (B, L, 256)
    const float* __restrict__ attn,   // (B, L, 128)
    float* __restrict__ out_acc)      // (B, L, 256)
{
    const int g = blockIdx.x * 8 + (threadIdx.x >> 5);
    if (g >= Bb * LQ * 2) return;
    const int bq   = g >> 1;
    const int half = g & 1;
    const int lane = threadIdx.x & 31;
    const int hg   = lane >> 3;
    const int c    = (lane & 7) * 4;
    const int b    = bq / LQ;
    const int h    = half * 4 + hg;

    // softmax over this head's 16 logits
    const float4* at4 = reinterpret_cast<const float4*>(
        attn + (size_t)bq * 128 + h * 16);
    float lg[16];
    {
        float4 t0 = at4[0], t1 = at4[1], t2 = at4[2], t3 = at4[3];
        lg[0]=t0.x; lg[1]=t0.y; lg[2]=t0.z; lg[3]=t0.w;
        lg[4]=t1.x; lg[5]=t1.y; lg[6]=t1.z; lg[7]=t1.w;
        lg[8]=t2.x; lg[9]=t2.y; lg[10]=t2.z; lg[11]=t2.w;
        lg[12]=t3.x; lg[13]=t3.y; lg[14]=t3.z; lg[15]=t3.w;
    }
    float mx = lg[0];
    #pragma unroll
    for (int j = 1; j < 16; j++) mx = fmaxf(mx, lg[j]);
    float s = 0.f;
    #pragma unroll
    for (int j = 0; j < 16; j++) { lg[j] = __expf(lg[j] - mx); s += lg[j]; }
    const float inv = 1.0f / s;

    const float* of = off + (size_t)bq * 256 + h * 32;
    const float* rp = refp + (size_t)bq * 8;
    float4 acc = make_float4(0.f, 0.f, 0.f, 0.f);

    const int   lWc[4] = {100, 50, 25, 13};
    const int   lHc[4] = {100, 50, 25, 13};
    const int   lSc[4] = {0, 10000, 12500, 13125};

    #pragma unroll
    for (int l = 0; l < 4; l++) {
        const int W = lWc[l], H = lHc[l];
        const float* vb = val + ((size_t)(b * Ss + lSc[l])) * 256 + h * 32 + c;
        const float rx = rp[l * 2 + 0] * (float)W - 0.5f;
        const float ry = rp[l * 2 + 1] * (float)H - 0.5f;
        const float4 o01 = reinterpret_cast<const float4*>(of + l * 8)[0];
        const float4 o23 = reinterpret_cast<const float4*>(of + l * 8)[1];
        const float ox[4] = {o01.x, o01.z, o23.x, o23.z};
        const float oy[4] = {o01.y, o01.w, o23.y, o23.w};

        #pragma unroll
        for (int p = 0; p < 4; p++) {
            const float x = rx + ox[p];
            const float y = ry + oy[p];
            const float wgt = lg[l * 4 + p] * inv;

            const float fx0 = floorf(x), fy0 = floorf(y);
            const int x0 = (int)fx0, y0 = (int)fy0;
            const float wx1 = x - fx0, wy1 = y - fy0;
            const float wx0 = 1.f - wx1, wy0 = 1.f - wy1;

            const float mx0 = (x0 >= 0     && x0 < W)     ? 1.f : 0.f;
            const float mx1 = (x0 + 1 >= 0 && x0 + 1 < W) ? 1.f : 0.f;
            const float my0 = (y0 >= 0     && y0 < H)     ? 1.f : 0.f;
            const float my1 = (y0 + 1 >= 0 && y0 + 1 < H) ? 1.f : 0.f;

            const int xc0 = min(max(x0, 0), W - 1);
            const int xc1 = min(max(x0 + 1, 0), W - 1);
            const int yc0 = min(max(y0, 0), H - 1);
            const int yc1 = min(max(y0 + 1, 0), H - 1);

            const float w00 = wgt * wx0 * wy0 * mx0 * my0;
            const float w10 = wgt * wx1 * wy0 * mx1 * my0;
            const float w01 = wgt * wx0 * wy1 * mx0 * my1;
            const float w11 = wgt * wx1 * wy1 * mx1 * my1;

            const float4 v00 = *reinterpret_cast<const float4*>(vb + (size_t)(yc0 * W + xc0) * 256);
            const float4 v10 = *reinterpret_cast<const float4*>(vb + (size_t)(yc0 * W + xc1) * 256);
            const float4 v01 = *reinterpret_cast<const float4*>(vb + (size_t)(yc1 * W + xc0) * 256);
            const float4 v11 = *reinterpret_cast<const float4*>(vb + (size_t)(yc1 * W + xc1) * 256);

            acc.x += w00 * v00.x + w10 * v10.x + w01 * v01.x + w11 * v11.x;
            acc.y += w00 * v00.y + w10 * v10.y + w01 * v01.y + w11 * v11.y;
            acc.z += w00 * v00.z + w10 * v10.z + w01 * v01.z + w11 * v11.z;
            acc.w += w00 * v00.w + w10 * v10.w + w01 * v01.w + w11 * v11.w;
        }
    }

    *reinterpret_cast<float4*>(out_acc + (size_t)bq * 256 + h * 32 + c) = acc;
}

// ---------------------------------------------------------------------------
// Launch
// ---------------------------------------------------------------------------
extern "C" void kernel_launch(void* const* d_in, const int* in_sizes, int n_in,
                              void* d_out, int out_size)
{
    const float* query  = (const float*)d_in[0];
    const float* refp   = (const float*)d_in[1];
    const float* value  = (const float*)d_in[2];
    const float* W_val  = (const float*)d_in[3];
    const float* b_val  = (const float*)d_in[4];
    const float* W_off  = (const float*)d_in[5];
    const float* b_off  = (const float*)d_in[6];
    const float* W_attn = (const float*)d_in[7];
    const float* b_attn = (const float*)d_in[8];
    const float* W_out  = (const float*)d_in[9];
    const float* b_out  = (const float*)d_in[10];
    float* out = (float*)d_out;

    float *pval, *poff, *pattn, *pacc;
    cudaGetSymbolAddress((void**)&pval,  g_val);
    cudaGetSymbolAddress((void**)&poff,  g_off);
    cudaGetSymbolAddress((void**)&pattn, g_attn);
    cudaGetSymbolAddress((void**)&pacc,  g_acc);

    cudaFuncSetAttribute(gemm_tf32_kernel,
                         cudaFuncAttributeMaxDynamicSharedMemorySize, GEMM_SMEM);

    const dim3 blk(256);
    const dim3 g256(2, (MROWS + 127) / 128);   // N=256
    const dim3 g128(1, (MROWS + 127) / 128);   // N=128

    gemm_tf32_kernel<<<g256, blk, GEMM_SMEM>>>(value, W_val, b_val, pval, MROWS, 256, 256);
    gemm_tf32_kernel<<<g256, blk, GEMM_SMEM>>>(query, W_off, b_off, poff, MROWS, 256, 256);
    gemm_tf32_kernel<<<g128, blk, GEMM_SMEM>>>(query, W_attn, b_attn, pattn, MROWS, 128, 256);
    sample_kernel<<<(MROWS * 2 + 7) / 8, blk>>>(refp, pval, poff, pattn, pacc);
    gemm_tf32_kernel<<<g256, blk, GEMM_SMEM>>>(pacc, W_out, b_out, out, MROWS, 256, 256);
}

// round 6
// speedup vs baseline: 3.2385x; 1.0598x over previous
#include <cuda_runtime.h>
#include <cuda_bf16.h>
#include <cuda_fp16.h>
#include <cstdint>
#include <cstddef>

// Problem constants
#define NHh 8
#define Dm  256
#define Bb  2
#define Ss  13294          // 100*100 + 50*50 + 25*25 + 13*13
#define LQ  13294
#define MROWS (Bb * LQ)    // 26588

// Scratch (allocation-free: __device__ globals)
__device__ float g_val [Bb * Ss * Dm];
__device__ float g_off [Bb * LQ * Dm];
__device__ float g_attn[Bb * LQ * 128];
__device__ float g_acc [Bb * LQ * Dm];

__device__ __forceinline__ uint32_t pack_h2(float lo, float hi) {
    uint32_t r;
    asm("cvt.rn.f16x2.f32 %0, %1, %2;" : "=r"(r) : "f"(hi), "f"(lo));
    return r;
}

__device__ __forceinline__ void cp16(float* s, const float* g, bool p) {
    uint32_t sa = (uint32_t)__cvta_generic_to_shared(s);
    const int sz = p ? 16 : 0;
    asm volatile("cp.async.ca.shared.global [%0], [%1], 16, %2;"
                 :: "r"(sa), "l"(g), "r"(sz));
}

// ---------------------------------------------------------------------------
// FP16 tensor-core GEMM (m16n8k16), cp.async 2-stage pipeline, fp32 smem,
// convert-to-half at fragment read (fp16 mantissa == tf32 mantissa; fp32
// accumulate -> same error model as tf32 path).
// Split-output: columns [0,N1) -> C1/bias1 from B1; [N1,N1+N2) -> C2/bias2
// from B2 (fuses the two query GEMMs). N2=0 for plain GEMMs. K fixed = 256.
// BM=128, BN=128, BK=32; 256 threads = 8 warps (2 M x 4 N); warp tile 64x32.
// ---------------------------------------------------------------------------
#define ASTRIDE 40    // floats; LDS.64 A fragments conflict-free
#define BSTRIDE 132   // floats; LDS.32 B fragments conflict-free
#define A_TILE_F (128 * ASTRIDE)            // 5120 floats
#define B_TILE_F (32 * BSTRIDE)             // 4224 floats
#define STAGE_F  (A_TILE_F + B_TILE_F)      // 9344 floats
#define GEMM_SMEM (2 * STAGE_F * 4)         // 74752 B

__global__ __launch_bounds__(256, 2) void gemm_f16_kernel(
    const float* __restrict__ A,
    const float* __restrict__ B1, const float* __restrict__ bias1, float* __restrict__ C1,
    const float* __restrict__ B2, const float* __restrict__ bias2, float* __restrict__ C2,
    int M, int N1, int N2)
{
    extern __shared__ float smem[];

    const int tid  = threadIdx.x;
    const int wid  = tid >> 5;
    const int lane = tid & 31;
    const int gid  = lane >> 2;      // 0..7
    const int tig  = lane & 3;       // 0..3

    const int warpM = wid >> 2;      // 0..1
    const int warpN = wid & 3;       // 0..3

    const int bm = blockIdx.y * 128;
    const int bn = blockIdx.x * 128;

    float c[4][4][4];
    #pragma unroll
    for (int i = 0; i < 4; i++)
        #pragma unroll
        for (int j = 0; j < 4; j++)
            #pragma unroll
            for (int r = 0; r < 4; r++) c[i][j][r] = 0.f;

    const int K = 256, NT = 8;

    auto copy_tile = [&](int kt, float* sA, float* sB) {
        const int k0 = kt * 32;
        #pragma unroll
        for (int i = 0; i < 4; i++) {
            const int o = tid * 4 + i;
            const int row = o >> 3, seg = o & 7;
            cp16(&sA[row * ASTRIDE + seg * 4],
                 A + (size_t)(bm + row) * K + k0 + seg * 4,
                 bm + row < M);
        }
        #pragma unroll
        for (int i = 0; i < 4; i++) {
            const int o = tid * 4 + i;
            const int row = o >> 5, seg = o & 31;
            const int n = bn + seg * 4;
            const float* src = (n < N1)
                ? B1 + (size_t)(k0 + row) * N1 + n
                : B2 + (size_t)(k0 + row) * N2 + (n - N1);
            cp16(&sB[row * BSTRIDE + seg * 4], src, true);
        }
    };

    copy_tile(0, smem, smem + A_TILE_F);
    asm volatile("cp.async.commit_group;");

    for (int it = 0; it < NT; it++) {
        const int cur = it & 1;
        float* sA = smem + cur * STAGE_F;
        float* sB = sA + A_TILE_F;

        if (it + 1 < NT) {
            float* nA = smem + (cur ^ 1) * STAGE_F;
            copy_tile(it + 1, nA, nA + A_TILE_F);
            asm volatile("cp.async.commit_group;");
            asm volatile("cp.async.wait_group 1;");
        } else {
            asm volatile("cp.async.wait_group 0;");
        }
        __syncthreads();

        #pragma unroll
        for (int ks = 0; ks < 2; ks++) {      // two k16 steps per 32-K tile
            const int kb = ks * 16;
            uint32_t a[4][4];
            #pragma unroll
            for (int mt = 0; mt < 4; mt++) {
                const int m0 = warpM * 64 + mt * 16 + gid;
                const float2 f0 = *reinterpret_cast<const float2*>(&sA[(m0    ) * ASTRIDE + kb + tig * 2    ]);
                const float2 f1 = *reinterpret_cast<const float2*>(&sA[(m0 + 8) * ASTRIDE + kb + tig * 2    ]);
                const float2 f2 = *reinterpret_cast<const float2*>(&sA[(m0    ) * ASTRIDE + kb + tig * 2 + 8]);
                const float2 f3 = *reinterpret_cast<const float2*>(&sA[(m0 + 8) * ASTRIDE + kb + tig * 2 + 8]);
                a[mt][0] = pack_h2(f0.x, f0.y);
                a[mt][1] = pack_h2(f1.x, f1.y);
                a[mt][2] = pack_h2(f2.x, f2.y);
                a[mt][3] = pack_h2(f3.x, f3.y);
            }
            uint32_t b[4][2];
            #pragma unroll
            for (int nt = 0; nt < 4; nt++) {
                const int n0 = warpN * 32 + nt * 8 + gid;
                const float b0l = sB[(kb + tig * 2    ) * BSTRIDE + n0];
                const float b0h = sB[(kb + tig * 2 + 1) * BSTRIDE + n0];
                const float b1l = sB[(kb + tig * 2 + 8) * BSTRIDE + n0];
                const float b1h = sB[(kb + tig * 2 + 9) * BSTRIDE + n0];
                b[nt][0] = pack_h2(b0l, b0h);
                b[nt][1] = pack_h2(b1l, b1h);
            }
            #pragma unroll
            for (int mt = 0; mt < 4; mt++)
                #pragma unroll
                for (int nt = 0; nt < 4; nt++) {
                    asm volatile(
                        "mma.sync.aligned.m16n8k16.row.col.f32.f16.f16.f32 "
                        "{%0,%1,%2,%3}, {%4,%5,%6,%7}, {%8,%9}, {%0,%1,%2,%3};"
                        : "+f"(c[mt][nt][0]), "+f"(c[mt][nt][1]),
                          "+f"(c[mt][nt][2]), "+f"(c[mt][nt][3])
                        : "r"(a[mt][0]), "r"(a[mt][1]), "r"(a[mt][2]), "r"(a[mt][3]),
                          "r"(b[nt][0]), "r"(b[nt][1]));
                }
        }
        __syncthreads();
    }

    // epilogue with column routing (warp N-tiles never straddle N1=mult of 32)
    #pragma unroll
    for (int mt = 0; mt < 4; mt++) {
        const int r0 = bm + warpM * 64 + mt * 16 + gid;
        #pragma unroll
        for (int nt = 0; nt < 4; nt++) {
            const int cc = bn + warpN * 32 + nt * 8 + tig * 2;
            float* Cp; const float* bp; int Np, col;
            if (cc < N1) { Cp = C1; bp = bias1; Np = N1; col = cc; }
            else         { Cp = C2; bp = bias2; Np = N2; col = cc - N1; }
            const float bz0 = bp[col], bz1 = bp[col + 1];
            if (r0 < M) {
                float2 v = make_float2(c[mt][nt][0] + bz0, c[mt][nt][1] + bz1);
                *reinterpret_cast<float2*>(Cp + (size_t)r0 * Np + col) = v;
            }
            if (r0 + 8 < M) {
                float2 v = make_float2(c[mt][nt][2] + bz0, c[mt][nt][3] + bz1);
                *reinterpret_cast<float2*>(Cp + (size_t)(r0 + 8) * Np + col) = v;
            }
        }
    }
}

// ---------------------------------------------------------------------------
// Sampling kernel: one warp per (b, q, head-half); lanes = 4 heads x 8
// channel-quads (float4). Branchless bilinear.
// ---------------------------------------------------------------------------
__global__ __launch_bounds__(256) void sample_kernel(
    const float* __restrict__ refp,   // (B, L, NL, 2)
    const float* __restrict__ val,    // (B, S, 256)
    const float* __restrict__ off,    // (B, L, 256)
    const float* __restrict__ attn,   // (B, L, 128)
    float* __restrict__ out_acc)      // (B, L, 256)
{
    const int g = blockIdx.x * 8 + (threadIdx.x >> 5);
    if (g >= Bb * LQ * 2) return;
    const int bq   = g >> 1;
    const int half = g & 1;
    const int lane = threadIdx.x & 31;
    const int hg   = lane >> 3;
    const int c    = (lane & 7) * 4;
    const int b    = bq / LQ;
    const int h    = half * 4 + hg;

    const float4* at4 = reinterpret_cast<const float4*>(
        attn + (size_t)bq * 128 + h * 16);
    float lg[16];
    {
        float4 t0 = at4[0], t1 = at4[1], t2 = at4[2], t3 = at4[3];
        lg[0]=t0.x; lg[1]=t0.y; lg[2]=t0.z; lg[3]=t0.w;
        lg[4]=t1.x; lg[5]=t1.y; lg[6]=t1.z; lg[7]=t1.w;
        lg[8]=t2.x; lg[9]=t2.y; lg[10]=t2.z; lg[11]=t2.w;
        lg[12]=t3.x; lg[13]=t3.y; lg[14]=t3.z; lg[15]=t3.w;
    }
    float mx = lg[0];
    #pragma unroll
    for (int j = 1; j < 16; j++) mx = fmaxf(mx, lg[j]);
    float s = 0.f;
    #pragma unroll
    for (int j = 0; j < 16; j++) { lg[j] = __expf(lg[j] - mx); s += lg[j]; }
    const float inv = 1.0f / s;

    const float* of = off + (size_t)bq * 256 + h * 32;
    const float* rp = refp + (size_t)bq * 8;
    float4 acc = make_float4(0.f, 0.f, 0.f, 0.f);

    const int lWc[4] = {100, 50, 25, 13};
    const int lHc[4] = {100, 50, 25, 13};
    const int lSc[4] = {0, 10000, 12500, 13125};

    #pragma unroll
    for (int l = 0; l < 4; l++) {
        const int W = lWc[l], H = lHc[l];
        const float* vb = val + ((size_t)(b * Ss + lSc[l])) * 256 + h * 32 + c;
        const float rx = rp[l * 2 + 0] * (float)W - 0.5f;
        const float ry = rp[l * 2 + 1] * (float)H - 0.5f;
        const float4 o01 = reinterpret_cast<const float4*>(of + l * 8)[0];
        const float4 o23 = reinterpret_cast<const float4*>(of + l * 8)[1];
        const float ox[4] = {o01.x, o01.z, o23.x, o23.z};
        const float oy[4] = {o01.y, o01.w, o23.y, o23.w};

        #pragma unroll
        for (int p = 0; p < 4; p++) {
            const float x = rx + ox[p];
            const float y = ry + oy[p];
            const float wgt = lg[l * 4 + p] * inv;

            const float fx0 = floorf(x), fy0 = floorf(y);
            const int x0 = (int)fx0, y0 = (int)fy0;
            const float wx1 = x - fx0, wy1 = y - fy0;
            const float wx0 = 1.f - wx1, wy0 = 1.f - wy1;

            const float mx0 = (x0 >= 0     && x0 < W)     ? 1.f : 0.f;
            const float mx1 = (x0 + 1 >= 0 && x0 + 1 < W) ? 1.f : 0.f;
            const float my0 = (y0 >= 0     && y0 < H)     ? 1.f : 0.f;
            const float my1 = (y0 + 1 >= 0 && y0 + 1 < H) ? 1.f : 0.f;

            const int xc0 = min(max(x0, 0), W - 1);
            const int xc1 = min(max(x0 + 1, 0), W - 1);
            const int yc0 = min(max(y0, 0), H - 1);
            const int yc1 = min(max(y0 + 1, 0), H - 1);

            const float w00 = wgt * wx0 * wy0 * mx0 * my0;
            const float w10 = wgt * wx1 * wy0 * mx1 * my0;
            const float w01 = wgt * wx0 * wy1 * mx0 * my1;
            const float w11 = wgt * wx1 * wy1 * mx1 * my1;

            const float4 v00 = *reinterpret_cast<const float4*>(vb + (size_t)(yc0 * W + xc0) * 256);
            const float4 v10 = *reinterpret_cast<const float4*>(vb + (size_t)(yc0 * W + xc1) * 256);
            const float4 v01 = *reinterpret_cast<const float4*>(vb + (size_t)(yc1 * W + xc0) * 256);
            const float4 v11 = *reinterpret_cast<const float4*>(vb + (size_t)(yc1 * W + xc1) * 256);

            acc.x += w00 * v00.x + w10 * v10.x + w01 * v01.x + w11 * v11.x;
            acc.y += w00 * v00.y + w10 * v10.y + w01 * v01.y + w11 * v11.y;
            acc.z += w00 * v00.z + w10 * v10.z + w01 * v01.z + w11 * v11.z;
            acc.w += w00 * v00.w + w10 * v10.w + w01 * v01.w + w11 * v11.w;
        }
    }

    *reinterpret_cast<float4*>(out_acc + (size_t)bq * 256 + h * 32 + c) = acc;
}

// ---------------------------------------------------------------------------
// Launch
// ---------------------------------------------------------------------------
extern "C" void kernel_launch(void* const* d_in, const int* in_sizes, int n_in,
                              void* d_out, int out_size)
{
    const float* query  = (const float*)d_in[0];
    const float* refp   = (const float*)d_in[1];
    const float* value  = (const float*)d_in[2];
    const float* W_val  = (const float*)d_in[3];
    const float* b_val  = (const float*)d_in[4];
    const float* W_off  = (const float*)d_in[5];
    const float* b_off  = (const float*)d_in[6];
    const float* W_attn = (const float*)d_in[7];
    const float* b_attn = (const float*)d_in[8];
    const float* W_out  = (const float*)d_in[9];
    const float* b_out  = (const float*)d_in[10];
    float* out = (float*)d_out;

    float *pval, *poff, *pattn, *pacc;
    cudaGetSymbolAddress((void**)&pval,  g_val);
    cudaGetSymbolAddress((void**)&poff,  g_off);
    cudaGetSymbolAddress((void**)&pattn, g_attn);
    cudaGetSymbolAddress((void**)&pacc,  g_acc);

    cudaFuncSetAttribute(gemm_f16_kernel,
                         cudaFuncAttributeMaxDynamicSharedMemorySize, GEMM_SMEM);

    const dim3 blk(256);
    const int  gy = (MROWS + 127) / 128;
    const dim3 g256(2, gy);   // N = 256
    const dim3 g384(3, gy);   // N = 256 + 128 fused

    // 1. val = value @ W_val + b_val
    gemm_f16_kernel<<<g256, blk, GEMM_SMEM>>>(
        value, W_val, b_val, pval, W_val, b_val, pval, MROWS, 256, 0);
    // 2+3. fused: offsets (N1=256) and attn logits (N2=128) from query
    gemm_f16_kernel<<<g384, blk, GEMM_SMEM>>>(
        query, W_off, b_off, poff, W_attn, b_attn, pattn, MROWS, 256, 128);
    // 4. softmax + deformable bilinear sampling -> g_acc
    sample_kernel<<<(MROWS * 2 + 7) / 8, blk>>>(refp, pval, poff, pattn, pacc);
    // 5. out = g_acc @ W_out + b_out
    gemm_f16_kernel<<<g256, blk, GEMM_SMEM>>>(
        pacc, W_out, b_out, out, W_out, b_out, out, MROWS, 256, 0);
}

// round 7
// speedup vs baseline: 3.7065x; 1.1445x over previous
#include <cuda_runtime.h>
#include <cuda_bf16.h>
#include <cuda_fp16.h>
#include <cstdint>
#include <cstddef>

// Problem constants
#define NHh 8
#define Dm  256
#define Bb  2
#define Ss  13294          // 100*100 + 50*50 + 25*25 + 13*13
#define LQ  13294
#define MROWS (Bb * LQ)    // 26588

// Scratch (allocation-free: __device__ globals)
__device__ float  g_val    [Bb * Ss * Dm];      // projected value (fp32)
__device__ float  g_offattn[MROWS * 384];       // fused offsets(256) + attn(128)
__device__ __half g_acc    [MROWS * Dm];        // sampled output (half)
__device__ __half g_bt_val [256 * 256];         // W_val^T  half [n][k]
__device__ __half g_bt_oa  [384 * 256];         // [W_off|W_attn]^T half [n][k]
__device__ __half g_bt_out [256 * 256];         // W_out^T  half [n][k]
__device__ float  g_bias_oa[384];               // fused b_off|b_attn

__device__ __forceinline__ uint32_t pack_h2(float lo, float hi) {
    uint32_t r;
    asm("cvt.rn.f16x2.f32 %0, %1, %2;" : "=r"(r) : "f"(hi), "f"(lo));
    return r;
}

__device__ __forceinline__ void cp16(void* s, const void* g, bool p) {
    uint32_t sa = (uint32_t)__cvta_generic_to_shared(s);
    const int sz = p ? 16 : 0;
    asm volatile("cp.async.ca.shared.global [%0], [%1], 16, %2;"
                 :: "r"(sa), "l"(g), "r"(sz));
}

// ---------------------------------------------------------------------------
// prep: convert + transpose weights to half [n][k]; fuse W_off|W_attn + biases
// ---------------------------------------------------------------------------
__global__ __launch_bounds__(256) void prep_kernel(
    const float* __restrict__ W_val, const float* __restrict__ W_off,
    const float* __restrict__ W_attn, const float* __restrict__ W_out,
    const float* __restrict__ b_off, const float* __restrict__ b_attn)
{
    const int t = blockIdx.x * 256 + threadIdx.x;   // grid covers 98304
    if (t < 65536) {
        const int n = t >> 8, k = t & 255;
        g_bt_val[t] = __float2half(W_val[k * 256 + n]);
        g_bt_out[t] = __float2half(W_out[k * 256 + n]);
    }
    if (t < 98304) {
        const int n = t >> 8, k = t & 255;
        const float v = (n < 256) ? W_off[k * 256 + n] : W_attn[k * 128 + (n - 256)];
        g_bt_oa[t] = __float2half(v);
    }
    if (t < 384)
        g_bias_oa[t] = (t < 256) ? b_off[t] : b_attn[t - 256];
}

// ---------------------------------------------------------------------------
// FP16 tensor-core GEMM (m16n8k16), cp.async 3-stage pipeline.
// B is half [n][k] (pre-transposed), XOR-swizzled in smem -> fragment = 1 LDS.32.
// A: template — fp32 global (padded-stride smem + pack at read) or half global
// (swizzled smem, fragment = 1 LDS.32, no packs).
// BM=128, BN=128, BK=32; 256 threads = 8 warps (2 M x 4 N); warp tile 64x32.
// K fixed = 256.
// ---------------------------------------------------------------------------
#define AS32 40                               // fp32 A smem row stride (floats)
#define STAGES 3
template<bool AH>
__global__ __launch_bounds__(256, 2) void gemm_h_kernel(
    const void* __restrict__ Av, const __half* __restrict__ Bt,
    const float* __restrict__ bias, float* __restrict__ C,
    int M, int N)
{
    extern __shared__ char smem[];
    constexpr int A_BYTES = AH ? 128 * 32 * 2 : 128 * AS32 * 4;
    constexpr int B_BYTES = 128 * 32 * 2;
    constexpr int STAGE_BYTES = A_BYTES + B_BYTES;

    const int tid  = threadIdx.x;
    const int wid  = tid >> 5;
    const int lane = tid & 31;
    const int gid  = lane >> 2;      // 0..7
    const int tig  = lane & 3;       // 0..3
    const int warpM = wid >> 2;      // 0..1
    const int warpN = wid & 3;       // 0..3
    const int bm = blockIdx.y * 128;
    const int bn = blockIdx.x * 128;
    const int sw = (gid >> 1) << 2;  // XOR swizzle (4-byte units): 0,4,8,12

    float c[4][4][4];
    #pragma unroll
    for (int i = 0; i < 4; i++)
        #pragma unroll
        for (int j = 0; j < 4; j++)
            #pragma unroll
            for (int r = 0; r < 4; r++) c[i][j][r] = 0.f;

    const int K = 256, NT = 8;

    auto copy_tile = [&](int kt, char* stg) {
        const int k0 = kt * 32;
        if (AH) {
            const __half* A = (const __half*)Av;
            __half* sA = (__half*)stg;
            #pragma unroll
            for (int i = 0; i < 2; i++) {
                const int o = tid * 2 + i;
                const int row = o >> 2, ch = o & 3;
                const int dst = row * 32 + ((((ch * 4) ^ (((row >> 1) & 3) * 4))) << 1);
                cp16(&sA[dst], A + (size_t)(bm + row) * K + k0 + ch * 8, bm + row < M);
            }
        } else {
            const float* A = (const float*)Av;
            float* sA = (float*)stg;
            #pragma unroll
            for (int i = 0; i < 4; i++) {
                const int o = tid * 4 + i;
                const int row = o >> 3, seg = o & 7;
                cp16(&sA[row * AS32 + seg * 4],
                     A + (size_t)(bm + row) * K + k0 + seg * 4, bm + row < M);
            }
        }
        __half* sB = (__half*)(stg + A_BYTES);
        #pragma unroll
        for (int i = 0; i < 2; i++) {
            const int o = tid * 2 + i;
            const int row = o >> 2, ch = o & 3;
            const int dst = row * 32 + ((((ch * 4) ^ (((row >> 1) & 3) * 4))) << 1);
            cp16(&sB[dst], Bt + (size_t)(bn + row) * K + k0 + ch * 8, true);
        }
    };

    copy_tile(0, smem);
    asm volatile("cp.async.commit_group;");
    copy_tile(1, smem + STAGE_BYTES);
    asm volatile("cp.async.commit_group;");

    for (int it = 0; it < NT; it++) {
        if (it < NT - 1) asm volatile("cp.async.wait_group 1;");
        else             asm volatile("cp.async.wait_group 0;");
        __syncthreads();

        char* stg = smem + (it % STAGES) * STAGE_BYTES;
        const __half* sB = (const __half*)(stg + A_BYTES);

        #pragma unroll
        for (int ks = 0; ks < 2; ks++) {
            const int c0 = ks * 8;              // unit base: 0 or 8
            const int u0 = ((c0    ) ^ sw) + tig;
            const int u1 = ((c0 + 4) ^ sw) + tig;

            uint32_t a[4][4];
            if (AH) {
                const __half* sA = (const __half*)stg;
                #pragma unroll
                for (int mt = 0; mt < 4; mt++) {
                    const int m0 = warpM * 64 + mt * 16 + gid;
                    a[mt][0] = *(const uint32_t*)&sA[(m0    ) * 32 + (u0 << 1)];
                    a[mt][1] = *(const uint32_t*)&sA[(m0 + 8) * 32 + (u0 << 1)];
                    a[mt][2] = *(const uint32_t*)&sA[(m0    ) * 32 + (u1 << 1)];
                    a[mt][3] = *(const uint32_t*)&sA[(m0 + 8) * 32 + (u1 << 1)];
                }
            } else {
                const float* sA = (const float*)stg;
                const int kb = ks * 16;
                #pragma unroll
                for (int mt = 0; mt < 4; mt++) {
                    const int m0 = warpM * 64 + mt * 16 + gid;
                    const float2 f0 = *(const float2*)&sA[(m0    ) * AS32 + kb + tig * 2    ];
                    const float2 f1 = *(const float2*)&sA[(m0 + 8) * AS32 + kb + tig * 2    ];
                    const float2 f2 = *(const float2*)&sA[(m0    ) * AS32 + kb + tig * 2 + 8];
                    const float2 f3 = *(const float2*)&sA[(m0 + 8) * AS32 + kb + tig * 2 + 8];
                    a[mt][0] = pack_h2(f0.x, f0.y);
                    a[mt][1] = pack_h2(f1.x, f1.y);
                    a[mt][2] = pack_h2(f2.x, f2.y);
                    a[mt][3] = pack_h2(f3.x, f3.y);
                }
            }
            uint32_t b[4][2];
            #pragma unroll
            for (int nt = 0; nt < 4; nt++) {
                const int n0 = warpN * 32 + nt * 8 + gid;
                b[nt][0] = *(const uint32_t*)&sB[n0 * 32 + (u0 << 1)];
                b[nt][1] = *(const uint32_t*)&sB[n0 * 32 + (u1 << 1)];
            }
            #pragma unroll
            for (int mt = 0; mt < 4; mt++)
                #pragma unroll
                for (int nt = 0; nt < 4; nt++) {
                    asm volatile(
                        "mma.sync.aligned.m16n8k16.row.col.f32.f16.f16.f32 "
                        "{%0,%1,%2,%3}, {%4,%5,%6,%7}, {%8,%9}, {%0,%1,%2,%3};"
                        : "+f"(c[mt][nt][0]), "+f"(c[mt][nt][1]),
                          "+f"(c[mt][nt][2]), "+f"(c[mt][nt][3])
                        : "r"(a[mt][0]), "r"(a[mt][1]), "r"(a[mt][2]), "r"(a[mt][3]),
                          "r"(b[nt][0]), "r"(b[nt][1]));
                }
        }
        if (it + 2 < NT) {
            copy_tile(it + 2, smem + ((it + 2) % STAGES) * STAGE_BYTES);
            asm volatile("cp.async.commit_group;");
        }
    }

    #pragma unroll
    for (int mt = 0; mt < 4; mt++) {
        const int r0 = bm + warpM * 64 + mt * 16 + gid;
        #pragma unroll
        for (int nt = 0; nt < 4; nt++) {
            const int cc = bn + warpN * 32 + nt * 8 + tig * 2;
            const float bz0 = bias[cc], bz1 = bias[cc + 1];
            if (r0 < M) {
                float2 v = make_float2(c[mt][nt][0] + bz0, c[mt][nt][1] + bz1);
                *reinterpret_cast<float2*>(C + (size_t)r0 * N + cc) = v;
            }
            if (r0 + 8 < M) {
                float2 v = make_float2(c[mt][nt][2] + bz0, c[mt][nt][3] + bz1);
                *reinterpret_cast<float2*>(C + (size_t)(r0 + 8) * N + cc) = v;
            }
        }
    }
}

// ---------------------------------------------------------------------------
// Sampling: one warp per (b, q, head-half); lanes = 4 heads x 8 channel-quads.
// Reads fused off/attn buffer (row stride 384); writes g_acc as half.
// ---------------------------------------------------------------------------
__global__ __launch_bounds__(256) void sample_kernel(
    const float* __restrict__ refp,    // (B, L, NL, 2)
    const float* __restrict__ val,     // (B, S, 256) fp32
    const float* __restrict__ offattn, // (B, L, 384)
    __half* __restrict__ out_acc)      // (B, L, 256) half
{
    const int g = blockIdx.x * 8 + (threadIdx.x >> 5);
    if (g >= Bb * LQ * 2) return;
    const int bq   = g >> 1;
    const int half = g & 1;
    const int lane = threadIdx.x & 31;
    const int hg   = lane >> 3;
    const int c    = (lane & 7) * 4;
    const int b    = bq / LQ;
    const int h    = half * 4 + hg;

    const float4* at4 = reinterpret_cast<const float4*>(
        offattn + (size_t)bq * 384 + 256 + h * 16);
    float lg[16];
    {
        float4 t0 = at4[0], t1 = at4[1], t2 = at4[2], t3 = at4[3];
        lg[0]=t0.x; lg[1]=t0.y; lg[2]=t0.z; lg[3]=t0.w;
        lg[4]=t1.x; lg[5]=t1.y; lg[6]=t1.z; lg[7]=t1.w;
        lg[8]=t2.x; lg[9]=t2.y; lg[10]=t2.z; lg[11]=t2.w;
        lg[12]=t3.x; lg[13]=t3.y; lg[14]=t3.z; lg[15]=t3.w;
    }
    float mx = lg[0];
    #pragma unroll
    for (int j = 1; j < 16; j++) mx = fmaxf(mx, lg[j]);
    float s = 0.f;
    #pragma unroll
    for (int j = 0; j < 16; j++) { lg[j] = __expf(lg[j] - mx); s += lg[j]; }
    const float inv = 1.0f / s;

    const float* of = offattn + (size_t)bq * 384 + h * 32;
    const float* rp = refp + (size_t)bq * 8;
    float4 acc = make_float4(0.f, 0.f, 0.f, 0.f);

    const int lWc[4] = {100, 50, 25, 13};
    const int lHc[4] = {100, 50, 25, 13};
    const int lSc[4] = {0, 10000, 12500, 13125};

    #pragma unroll
    for (int l = 0; l < 4; l++) {
        const int W = lWc[l], H = lHc[l];
        const float* vb = val + ((size_t)(b * Ss + lSc[l])) * 256 + h * 32 + c;
        const float rx = rp[l * 2 + 0] * (float)W - 0.5f;
        const float ry = rp[l * 2 + 1] * (float)H - 0.5f;
        const float4 o01 = reinterpret_cast<const float4*>(of + l * 8)[0];
        const float4 o23 = reinterpret_cast<const float4*>(of + l * 8)[1];
        const float ox[4] = {o01.x, o01.z, o23.x, o23.z};
        const float oy[4] = {o01.y, o01.w, o23.y, o23.w};

        #pragma unroll
        for (int p = 0; p < 4; p++) {
            const float x = rx + ox[p];
            const float y = ry + oy[p];
            const float wgt = lg[l * 4 + p] * inv;

            const float fx0 = floorf(x), fy0 = floorf(y);
            const int x0 = (int)fx0, y0 = (int)fy0;
            const float wx1 = x - fx0, wy1 = y - fy0;
            const float wx0 = 1.f - wx1, wy0 = 1.f - wy1;

            const float mx0 = (x0 >= 0     && x0 < W)     ? 1.f : 0.f;
            const float mx1 = (x0 + 1 >= 0 && x0 + 1 < W) ? 1.f : 0.f;
            const float my0 = (y0 >= 0     && y0 < H)     ? 1.f : 0.f;
            const float my1 = (y0 + 1 >= 0 && y0 + 1 < H) ? 1.f : 0.f;

            const int xc0 = min(max(x0, 0), W - 1);
            const int xc1 = min(max(x0 + 1, 0), W - 1);
            const int yc0 = min(max(y0, 0), H - 1);
            const int yc1 = min(max(y0 + 1, 0), H - 1);

            const float w00 = wgt * wx0 * wy0 * mx0 * my0;
            const float w10 = wgt * wx1 * wy0 * mx1 * my0;
            const float w01 = wgt * wx0 * wy1 * mx0 * my1;
            const float w11 = wgt * wx1 * wy1 * mx1 * my1;

            const float4 v00 = *reinterpret_cast<const float4*>(vb + (size_t)(yc0 * W + xc0) * 256);
            const float4 v10 = *reinterpret_cast<const float4*>(vb + (size_t)(yc0 * W + xc1) * 256);
            const float4 v01 = *reinterpret_cast<const float4*>(vb + (size_t)(yc1 * W + xc0) * 256);
            const float4 v11 = *reinterpret_cast<const float4*>(vb + (size_t)(yc1 * W + xc1) * 256);

            acc.x += w00 * v00.x + w10 * v10.x + w01 * v01.x + w11 * v11.x;
            acc.y += w00 * v00.y + w10 * v10.y + w01 * v01.y + w11 * v11.y;
            acc.z += w00 * v00.z + w10 * v10.z + w01 * v01.z + w11 * v11.z;
            acc.w += w00 * v00.w + w10 * v10.w + w01 * v01.w + w11 * v11.w;
        }
    }

    const uint32_t h01 = pack_h2(acc.x, acc.y);
    const uint32_t h23 = pack_h2(acc.z, acc.w);
    *reinterpret_cast<uint2*>(out_acc + (size_t)bq * 256 + h * 32 + c) =
        make_uint2(h01, h23);
}

// ---------------------------------------------------------------------------
// Launch
// ---------------------------------------------------------------------------
#define SMEM_A32 (STAGES * (128 * AS32 * 4 + 128 * 32 * 2))   // 86016
#define SMEM_A16 (STAGES * (128 * 32 * 2 + 128 * 32 * 2))     // 49152

extern "C" void kernel_launch(void* const* d_in, const int* in_sizes, int n_in,
                              void* d_out, int out_size)
{
    const float* query  = (const float*)d_in[0];
    const float* refp   = (const float*)d_in[1];
    const float* value  = (const float*)d_in[2];
    const float* W_val  = (const float*)d_in[3];
    const float* b_val  = (const float*)d_in[4];
    const float* W_off  = (const float*)d_in[5];
    const float* b_off  = (const float*)d_in[6];
    const float* W_attn = (const float*)d_in[7];
    const float* b_attn = (const float*)d_in[8];
    const float* W_out  = (const float*)d_in[9];
    const float* b_out  = (const float*)d_in[10];
    float* out = (float*)d_out;

    float  *pval, *poa, *pbias_oa;
    __half *pacc, *pbtv, *pbtoa, *pbto;
    cudaGetSymbolAddress((void**)&pval,     g_val);
    cudaGetSymbolAddress((void**)&poa,      g_offattn);
    cudaGetSymbolAddress((void**)&pacc,     g_acc);
    cudaGetSymbolAddress((void**)&pbtv,     g_bt_val);
    cudaGetSymbolAddress((void**)&pbtoa,    g_bt_oa);
    cudaGetSymbolAddress((void**)&pbto,     g_bt_out);
    cudaGetSymbolAddress((void**)&pbias_oa, g_bias_oa);

    cudaFuncSetAttribute(gemm_h_kernel<false>,
                         cudaFuncAttributeMaxDynamicSharedMemorySize, SMEM_A32);
    cudaFuncSetAttribute(gemm_h_kernel<true>,
                         cudaFuncAttributeMaxDynamicSharedMemorySize, SMEM_A16);

    const dim3 blk(256);
    const int  gy = (MROWS + 127) / 128;

    // 0. weight transpose/convert + bias fuse
    prep_kernel<<<384, blk>>>(W_val, W_off, W_attn, W_out, b_off, b_attn);
    // 1. val = value @ W_val + b_val            (fp32 A)
    gemm_h_kernel<false><<<dim3(2, gy), blk, SMEM_A32>>>(
        value, pbtv, b_val, pval, MROWS, 256);
    // 2+3. [offsets | attn] = query @ [W_off|W_attn] + fused bias   (fp32 A)
    gemm_h_kernel<false><<<dim3(3, gy), blk, SMEM_A32>>>(
        query, pbtoa, pbias_oa, poa, MROWS, 384);
    // 4. softmax + deformable bilinear sampling -> g_acc (half)
    sample_kernel<<<(MROWS * 2 + 7) / 8, blk>>>(refp, pval, poa, pacc);
    // 5. out = g_acc @ W_out + b_out            (half A)
    gemm_h_kernel<true><<<dim3(2, gy), blk, SMEM_A16>>>(
        pacc, pbto, b_out, out, MROWS, 256);
}

// round 8
// speedup vs baseline: 3.7366x; 1.0081x over previous
#include <cuda_runtime.h>
#include <cuda_bf16.h>
#include <cuda_fp16.h>
#include <cstdint>
#include <cstddef>

// Problem constants
#define NHh 8
#define Dm  256
#define Bb  2
#define Ss  13294          // 100*100 + 50*50 + 25*25 + 13*13
#define LQ  13294
#define MROWS (Bb * LQ)    // 26588

// Scratch (allocation-free: __device__ globals)
__device__ float  g_val    [Bb * Ss * Dm];      // projected value (fp32)
__device__ float  g_offattn[MROWS * 384];       // fused offsets(256) + attn(128)
__device__ __half g_acc    [MROWS * Dm];        // sampled output (half)
__device__ __half g_query_h[MROWS * Dm];        // query converted to half
__device__ __half g_value_h[MROWS * Dm];        // value converted to half
__device__ __half g_bt_val [256 * 256];         // W_val^T  half [n][k]
__device__ __half g_bt_oa  [384 * 256];         // [W_off|W_attn]^T half [n][k]
__device__ __half g_bt_out [256 * 256];         // W_out^T  half [n][k]
__device__ float  g_bias_oa[384];               // fused b_off|b_attn

__device__ __forceinline__ uint32_t pack_h2(float lo, float hi) {
    uint32_t r;
    asm("cvt.rn.f16x2.f32 %0, %1, %2;" : "=r"(r) : "f"(hi), "f"(lo));
    return r;
}

__device__ __forceinline__ void cp16(void* s, const void* g, bool p) {
    uint32_t sa = (uint32_t)__cvta_generic_to_shared(s);
    const int sz = p ? 16 : 0;
    asm volatile("cp.async.ca.shared.global [%0], [%1], 16, %2;"
                 :: "r"(sa), "l"(g), "r"(sz));
}

// packed f32x2 helpers (sm_10x FFMA2)
__device__ __forceinline__ void ffma2(unsigned long long& acc,
                                      unsigned long long v,
                                      unsigned long long w) {
    asm("fma.rn.f32x2 %0, %1, %2, %0;" : "+l"(acc) : "l"(v), "l"(w));
}
__device__ __forceinline__ unsigned long long bcast2(float w) {
    unsigned long long r;
    const uint32_t u = __float_as_uint(w);
    asm("mov.b64 %0, {%1, %1};" : "=l"(r) : "r"(u));
    return r;
}

// ---------------------------------------------------------------------------
// prep: weights -> half [n][k] transposed; fuse W_off|W_attn + biases
// ---------------------------------------------------------------------------
__global__ __launch_bounds__(256) void prep_kernel(
    const float* __restrict__ W_val, const float* __restrict__ W_off,
    const float* __restrict__ W_attn, const float* __restrict__ W_out,
    const float* __restrict__ b_off, const float* __restrict__ b_attn)
{
    const int t = blockIdx.x * 256 + threadIdx.x;   // grid covers 98304
    if (t < 65536) {
        const int n = t >> 8, k = t & 255;
        g_bt_val[t] = __float2half(W_val[k * 256 + n]);
        g_bt_out[t] = __float2half(W_out[k * 256 + n]);
    }
    if (t < 98304) {
        const int n = t >> 8, k = t & 255;
        const float v = (n < 256) ? W_off[k * 256 + n] : W_attn[k * 128 + (n - 256)];
        g_bt_oa[t] = __float2half(v);
    }
    if (t < 384)
        g_bias_oa[t] = (t < 256) ? b_off[t] : b_attn[t - 256];
}

// ---------------------------------------------------------------------------
// convert: query & value fp32 -> half (vectorized, pure bandwidth)
// ---------------------------------------------------------------------------
__global__ __launch_bounds__(256) void convert_kernel(
    const float* __restrict__ query, const float* __restrict__ value)
{
    const size_t i = (size_t)blockIdx.x * 256 + threadIdx.x;   // float4 index
    const size_t n4 = (size_t)MROWS * 64;                      // MROWS*256/4
    if (i >= n4) return;
    const float4 q = reinterpret_cast<const float4*>(query)[i];
    const float4 v = reinterpret_cast<const float4*>(value)[i];
    reinterpret_cast<uint2*>(g_query_h)[i] =
        make_uint2(pack_h2(q.x, q.y), pack_h2(q.z, q.w));
    reinterpret_cast<uint2*>(g_value_h)[i] =
        make_uint2(pack_h2(v.x, v.y), pack_h2(v.z, v.w));
}

// ---------------------------------------------------------------------------
// FP16 tensor-core GEMM (m16n8k16): A half [m][k], B half [n][k] pre-transposed,
// both XOR-swizzled in smem -> every fragment = 1 LDS.32, zero packs.
// cp.async 3-stage pipeline. BM=128, BN=128, BK=32; 8 warps (2Mx4N), 64x32
// warp tile. K fixed = 256. fp32 accumulate, fp32 bias/output.
// ---------------------------------------------------------------------------
#define STAGES 3
#define STAGE_BYTES (128 * 32 * 2 * 2)                 // A 8KB + B 8KB
#define GEMM_SMEM (STAGES * STAGE_BYTES)               // 49152

__global__ __launch_bounds__(256, 2) void gemm_h_kernel(
    const __half* __restrict__ A, const __half* __restrict__ Bt,
    const float* __restrict__ bias, float* __restrict__ C,
    int M, int N)
{
    extern __shared__ char smem[];
    constexpr int A_BYTES = 128 * 32 * 2;

    const int tid  = threadIdx.x;
    const int wid  = tid >> 5;
    const int lane = tid & 31;
    const int gid  = lane >> 2;      // 0..7
    const int tig  = lane & 3;       // 0..3
    const int warpM = wid >> 2;      // 0..1
    const int warpN = wid & 3;       // 0..3
    const int bm = blockIdx.y * 128;
    const int bn = blockIdx.x * 128;
    const int sw = (gid >> 1) << 2;  // XOR swizzle (4B units): 0,4,8,12

    float c[4][4][4];
    #pragma unroll
    for (int i = 0; i < 4; i++)
        #pragma unroll
        for (int j = 0; j < 4; j++)
            #pragma unroll
            for (int r = 0; r < 4; r++) c[i][j][r] = 0.f;

    const int K = 256, NT = 8;

    auto copy_tile = [&](int kt, char* stg) {
        const int k0 = kt * 32;
        __half* sA = (__half*)stg;
        __half* sB = (__half*)(stg + A_BYTES);
        #pragma unroll
        for (int i = 0; i < 2; i++) {
            const int o = tid * 2 + i;
            const int row = o >> 2, ch = o & 3;
            const int dst = row * 32 + ((((ch * 4) ^ (((row >> 1) & 3) * 4))) << 1);
            cp16(&sA[dst], A + (size_t)(bm + row) * K + k0 + ch * 8, bm + row < M);
            cp16(&sB[dst], Bt + (size_t)(bn + row) * K + k0 + ch * 8, true);
        }
    };

    copy_tile(0, smem);
    asm volatile("cp.async.commit_group;");
    copy_tile(1, smem + STAGE_BYTES);
    asm volatile("cp.async.commit_group;");

    for (int it = 0; it < NT; it++) {
        if (it < NT - 1) asm volatile("cp.async.wait_group 1;");
        else             asm volatile("cp.async.wait_group 0;");
        __syncthreads();

        char* stg = smem + (it % STAGES) * STAGE_BYTES;
        const __half* sA = (const __half*)stg;
        const __half* sB = (const __half*)(stg + A_BYTES);

        #pragma unroll
        for (int ks = 0; ks < 2; ks++) {
            const int c0 = ks * 8;
            const int u0 = ((c0    ) ^ sw) + tig;
            const int u1 = ((c0 + 4) ^ sw) + tig;

            uint32_t a[4][4];
            #pragma unroll
            for (int mt = 0; mt < 4; mt++) {
                const int m0 = warpM * 64 + mt * 16 + gid;
                a[mt][0] = *(const uint32_t*)&sA[(m0    ) * 32 + (u0 << 1)];
                a[mt][1] = *(const uint32_t*)&sA[(m0 + 8) * 32 + (u0 << 1)];
                a[mt][2] = *(const uint32_t*)&sA[(m0    ) * 32 + (u1 << 1)];
                a[mt][3] = *(const uint32_t*)&sA[(m0 + 8) * 32 + (u1 << 1)];
            }
            uint32_t b[4][2];
            #pragma unroll
            for (int nt = 0; nt < 4; nt++) {
                const int n0 = warpN * 32 + nt * 8 + gid;
                b[nt][0] = *(const uint32_t*)&sB[n0 * 32 + (u0 << 1)];
                b[nt][1] = *(const uint32_t*)&sB[n0 * 32 + (u1 << 1)];
            }
            #pragma unroll
            for (int mt = 0; mt < 4; mt++)
                #pragma unroll
                for (int nt = 0; nt < 4; nt++) {
                    asm volatile(
                        "mma.sync.aligned.m16n8k16.row.col.f32.f16.f16.f32 "
                        "{%0,%1,%2,%3}, {%4,%5,%6,%7}, {%8,%9}, {%0,%1,%2,%3};"
                        : "+f"(c[mt][nt][0]), "+f"(c[mt][nt][1]),
                          "+f"(c[mt][nt][2]), "+f"(c[mt][nt][3])
                        : "r"(a[mt][0]), "r"(a[mt][1]), "r"(a[mt][2]), "r"(a[mt][3]),
                          "r"(b[nt][0]), "r"(b[nt][1]));
                }
        }
        if (it + 2 < NT) {
            copy_tile(it + 2, smem + ((it + 2) % STAGES) * STAGE_BYTES);
            asm volatile("cp.async.commit_group;");
        }
    }

    #pragma unroll
    for (int mt = 0; mt < 4; mt++) {
        const int r0 = bm + warpM * 64 + mt * 16 + gid;
        #pragma unroll
        for (int nt = 0; nt < 4; nt++) {
            const int cc = bn + warpN * 32 + nt * 8 + tig * 2;
            const float bz0 = bias[cc], bz1 = bias[cc + 1];
            if (r0 < M) {
                float2 v = make_float2(c[mt][nt][0] + bz0, c[mt][nt][1] + bz1);
                *reinterpret_cast<float2*>(C + (size_t)r0 * N + cc) = v;
            }
            if (r0 + 8 < M) {
                float2 v = make_float2(c[mt][nt][2] + bz0, c[mt][nt][3] + bz1);
                *reinterpret_cast<float2*>(C + (size_t)(r0 + 8) * N + cc) = v;
            }
        }
    }
}

// ---------------------------------------------------------------------------
// Sampling: one warp per (b, q, head-half); lanes = 4 heads x 8 channel-quads.
// Accumulation uses packed f32x2 FFMA2 (half the FMA instructions); corner
// weights factored (row-weight x col-weight). Writes g_acc as half.
// ---------------------------------------------------------------------------
__global__ __launch_bounds__(256) void sample_kernel(
    const float* __restrict__ refp,    // (B, L, NL, 2)
    const float* __restrict__ val,     // (B, S, 256) fp32
    const float* __restrict__ offattn, // (B, L, 384)
    __half* __restrict__ out_acc)      // (B, L, 256) half
{
    const int g = blockIdx.x * 8 + (threadIdx.x >> 5);
    if (g >= Bb * LQ * 2) return;
    const int bq   = g >> 1;
    const int half = g & 1;
    const int lane = threadIdx.x & 31;
    const int hg   = lane >> 3;
    const int c    = (lane & 7) * 4;
    const int b    = bq / LQ;
    const int h    = half * 4 + hg;

    const float4* at4 = reinterpret_cast<const float4*>(
        offattn + (size_t)bq * 384 + 256 + h * 16);
    float lg[16];
    {
        float4 t0 = at4[0], t1 = at4[1], t2 = at4[2], t3 = at4[3];
        lg[0]=t0.x; lg[1]=t0.y; lg[2]=t0.z; lg[3]=t0.w;
        lg[4]=t1.x; lg[5]=t1.y; lg[6]=t1.z; lg[7]=t1.w;
        lg[8]=t2.x; lg[9]=t2.y; lg[10]=t2.z; lg[11]=t2.w;
        lg[12]=t3.x; lg[13]=t3.y; lg[14]=t3.z; lg[15]=t3.w;
    }
    float mx = lg[0];
    #pragma unroll
    for (int j = 1; j < 16; j++) mx = fmaxf(mx, lg[j]);
    float s = 0.f;
    #pragma unroll
    for (int j = 0; j < 16; j++) { lg[j] = __expf(lg[j] - mx); s += lg[j]; }
    const float inv = 1.0f / s;

    const float* of = offattn + (size_t)bq * 384 + h * 32;
    const float* rp = refp + (size_t)bq * 8;
    unsigned long long acc01 = 0ull, acc23 = 0ull;   // packed f32x2 zeros

    const int lWc[4] = {100, 50, 25, 13};
    const int lHc[4] = {100, 50, 25, 13};
    const int lSc[4] = {0, 10000, 12500, 13125};

    #pragma unroll
    for (int l = 0; l < 4; l++) {
        const int W = lWc[l], H = lHc[l];
        const float* vb = val + ((size_t)(b * Ss + lSc[l])) * 256 + h * 32 + c;
        const float rx = rp[l * 2 + 0] * (float)W - 0.5f;
        const float ry = rp[l * 2 + 1] * (float)H - 0.5f;
        const float4 o01 = reinterpret_cast<const float4*>(of + l * 8)[0];
        const float4 o23 = reinterpret_cast<const float4*>(of + l * 8)[1];
        const float ox[4] = {o01.x, o01.z, o23.x, o23.z};
        const float oy[4] = {o01.y, o01.w, o23.y, o23.w};

        #pragma unroll
        for (int p = 0; p < 4; p++) {
            const float x = rx + ox[p];
            const float y = ry + oy[p];
            const float wgt = lg[l * 4 + p] * inv;

            const float fx0 = floorf(x), fy0 = floorf(y);
            const int x0 = (int)fx0, y0 = (int)fy0;
            const float wx1 = x - fx0, wy1 = y - fy0;
            const float wx0 = 1.f - wx1, wy0 = 1.f - wy1;

            const float mx0 = (x0 >= 0     && x0 < W)     ? 1.f : 0.f;
            const float mx1 = (x0 + 1 >= 0 && x0 + 1 < W) ? 1.f : 0.f;
            const float my0 = (y0 >= 0     && y0 < H)     ? 1.f : 0.f;
            const float my1 = (y0 + 1 >= 0 && y0 + 1 < H) ? 1.f : 0.f;

            const int xc0 = min(max(x0, 0), W - 1);
            const int xc1 = min(max(x0 + 1, 0), W - 1);
            const int yc0 = min(max(y0, 0), H - 1);
            const int yc1 = min(max(y0 + 1, 0), H - 1);

            // factored weights: row weight (wgt*wy*my), col weight (wx*mx)
            const float wy0g = wgt * wy0 * my0;
            const float wy1g = wgt * wy1 * my1;
            const float wx0m = wx0 * mx0;
            const float wx1m = wx1 * mx1;

            const unsigned long long w00 = bcast2(wx0m * wy0g);
            const unsigned long long w10 = bcast2(wx1m * wy0g);
            const unsigned long long w01 = bcast2(wx0m * wy1g);
            const unsigned long long w11 = bcast2(wx1m * wy1g);

            const ulonglong2 v00 = *reinterpret_cast<const ulonglong2*>(vb + (size_t)(yc0 * W + xc0) * 256);
            const ulonglong2 v10 = *reinterpret_cast<const ulonglong2*>(vb + (size_t)(yc0 * W + xc1) * 256);
            const ulonglong2 v01 = *reinterpret_cast<const ulonglong2*>(vb + (size_t)(yc1 * W + xc0) * 256);
            const ulonglong2 v11 = *reinterpret_cast<const ulonglong2*>(vb + (size_t)(yc1 * W + xc1) * 256);

            ffma2(acc01, v00.x, w00); ffma2(acc23, v00.y, w00);
            ffma2(acc01, v10.x, w10); ffma2(acc23, v10.y, w10);
            ffma2(acc01, v01.x, w01); ffma2(acc23, v01.y, w01);
            ffma2(acc01, v11.x, w11); ffma2(acc23, v11.y, w11);
        }
    }

    uint32_t a0, a1, a2, a3;
    asm("mov.b64 {%0, %1}, %2;" : "=r"(a0), "=r"(a1) : "l"(acc01));
    asm("mov.b64 {%0, %1}, %2;" : "=r"(a2), "=r"(a3) : "l"(acc23));
    const uint32_t h01 = pack_h2(__uint_as_float(a0), __uint_as_float(a1));
    const uint32_t h23 = pack_h2(__uint_as_float(a2), __uint_as_float(a3));
    *reinterpret_cast<uint2*>(out_acc + (size_t)bq * 256 + h * 32 + c) =
        make_uint2(h01, h23);
}

// ---------------------------------------------------------------------------
// Launch
// ---------------------------------------------------------------------------
extern "C" void kernel_launch(void* const* d_in, const int* in_sizes, int n_in,
                              void* d_out, int out_size)
{
    const float* query  = (const float*)d_in[0];
    const float* refp   = (const float*)d_in[1];
    const float* value  = (const float*)d_in[2];
    const float* W_val  = (const float*)d_in[3];
    const float* b_val  = (const float*)d_in[4];
    const float* W_off  = (const float*)d_in[5];
    const float* b_off  = (const float*)d_in[6];
    const float* W_attn = (const float*)d_in[7];
    const float* b_attn = (const float*)d_in[8];
    const float* W_out  = (const float*)d_in[9];
    const float* b_out  = (const float*)d_in[10];
    float* out = (float*)d_out;

    float  *pval, *poa, *pbias_oa;
    __half *pacc, *pqh, *pvh, *pbtv, *pbtoa, *pbto;
    cudaGetSymbolAddress((void**)&pval,     g_val);
    cudaGetSymbolAddress((void**)&poa,      g_offattn);
    cudaGetSymbolAddress((void**)&pacc,     g_acc);
    cudaGetSymbolAddress((void**)&pqh,      g_query_h);
    cudaGetSymbolAddress((void**)&pvh,      g_value_h);
    cudaGetSymbolAddress((void**)&pbtv,     g_bt_val);
    cudaGetSymbolAddress((void**)&pbtoa,    g_bt_oa);
    cudaGetSymbolAddress((void**)&pbto,     g_bt_out);
    cudaGetSymbolAddress((void**)&pbias_oa, g_bias_oa);

    cudaFuncSetAttribute(gemm_h_kernel,
                         cudaFuncAttributeMaxDynamicSharedMemorySize, GEMM_SMEM);

    const dim3 blk(256);
    const int  gy = (MROWS + 127) / 128;
    const int  n4 = MROWS * 64;                       // float4 count per tensor

    // 0a. weight transpose/convert + bias fuse
    prep_kernel<<<384, blk>>>(W_val, W_off, W_attn, W_out, b_off, b_attn);
    // 0b. query/value -> half
    convert_kernel<<<(n4 + 255) / 256, blk>>>(query, value);
    // 1. val = value @ W_val + b_val            (half A, fp32 out)
    gemm_h_kernel<<<dim3(2, gy), blk, GEMM_SMEM>>>(pvh, pbtv, b_val, pval, MROWS, 256);
    // 2+3. [offsets | attn] = query @ [W_off|W_attn] + fused bias
    gemm_h_kernel<<<dim3(3, gy), blk, GEMM_SMEM>>>(pqh, pbtoa, pbias_oa, poa, MROWS, 384);
    // 4. softmax + deformable bilinear sampling -> g_acc (half)
    sample_kernel<<<(MROWS * 2 + 7) / 8, blk>>>(refp, pval, poa, pacc);
    // 5. out = g_acc @ W_out + b_out            (half A)
    gemm_h_kernel<<<dim3(2, gy), blk, GEMM_SMEM>>>(pacc, pbto, b_out, out, MROWS, 256);
}

// round 9
// speedup vs baseline: 3.9199x; 1.0491x over previous
#include <cuda_runtime.h>
#include <cuda_bf16.h>
#include <cuda_fp16.h>
#include <cstdint>
#include <cstddef>

// Problem constants
#define NHh 8
#define Dm  256
#define Bb  2
#define Ss  13294          // 100*100 + 50*50 + 25*25 + 13*13
#define LQ  13294
#define MROWS (Bb * LQ)    // 26588

// Scratch (allocation-free: __device__ globals)
__device__ float  g_val    [Bb * Ss * Dm];      // projected value (fp32)
__device__ float  g_offattn[MROWS * 384];       // fused offsets(256) + attn(128)
__device__ __half g_acc    [MROWS * Dm];        // sampled output (half)
__device__ __half g_query_h[MROWS * Dm];        // query converted to half
__device__ __half g_value_h[MROWS * Dm];        // value converted to half
__device__ __half g_bt_val [256 * 256];         // W_val^T  half [n][k]
__device__ __half g_bt_oa  [384 * 256];         // [W_off|W_attn]^T half [n][k]
__device__ __half g_bt_out [256 * 256];         // W_out^T  half [n][k]
__device__ float  g_bias_oa[384];               // fused b_off|b_attn

__device__ __forceinline__ uint32_t pack_h2(float lo, float hi) {
    uint32_t r;
    asm("cvt.rn.f16x2.f32 %0, %1, %2;" : "=r"(r) : "f"(hi), "f"(lo));
    return r;
}

__device__ __forceinline__ void cp16(void* s, const void* g, bool p) {
    uint32_t sa = (uint32_t)__cvta_generic_to_shared(s);
    const int sz = p ? 16 : 0;
    asm volatile("cp.async.ca.shared.global [%0], [%1], 16, %2;"
                 :: "r"(sa), "l"(g), "r"(sz));
}

// packed f32x2 helpers (sm_10x FFMA2)
__device__ __forceinline__ void ffma2(unsigned long long& acc,
                                      unsigned long long v,
                                      unsigned long long w) {
    asm("fma.rn.f32x2 %0, %1, %2, %0;" : "+l"(acc) : "l"(v), "l"(w));
}
__device__ __forceinline__ void fmul2(unsigned long long& acc,
                                      unsigned long long w) {
    asm("mul.rn.f32x2 %0, %0, %1;" : "+l"(acc) : "l"(w));
}
__device__ __forceinline__ unsigned long long bcast2(float w) {
    unsigned long long r;
    const uint32_t u = __float_as_uint(w);
    asm("mov.b64 %0, {%1, %1};" : "=l"(r) : "r"(u));
    return r;
}

// ---------------------------------------------------------------------------
// prep+convert fused: weights -> half [n][k] transposed; biases fused;
// query & value fp32 -> half
// ---------------------------------------------------------------------------
__global__ __launch_bounds__(256) void prep_convert_kernel(
    const float* __restrict__ W_val, const float* __restrict__ W_off,
    const float* __restrict__ W_attn, const float* __restrict__ W_out,
    const float* __restrict__ b_off, const float* __restrict__ b_attn,
    const float* __restrict__ query, const float* __restrict__ value)
{
    const size_t t = (size_t)blockIdx.x * 256 + threadIdx.x;
    if (t < 65536) {
        const int n = (int)t >> 8, k = (int)t & 255;
        g_bt_val[t] = __float2half(W_val[k * 256 + n]);
        g_bt_out[t] = __float2half(W_out[k * 256 + n]);
    }
    if (t < 98304) {
        const int n = (int)t >> 8, k = (int)t & 255;
        const float v = (n < 256) ? W_off[k * 256 + n] : W_attn[k * 128 + (n - 256)];
        g_bt_oa[t] = __float2half(v);
    }
    if (t < 384)
        g_bias_oa[t] = (t < 256) ? b_off[t] : b_attn[t - 256];

    const size_t n4 = (size_t)MROWS * 64;          // float4 count per tensor
    if (t < n4) {
        const float4 q = reinterpret_cast<const float4*>(query)[t];
        const float4 v = reinterpret_cast<const float4*>(value)[t];
        reinterpret_cast<uint2*>(g_query_h)[t] =
            make_uint2(pack_h2(q.x, q.y), pack_h2(q.z, q.w));
        reinterpret_cast<uint2*>(g_value_h)[t] =
            make_uint2(pack_h2(v.x, v.y), pack_h2(v.z, v.w));
    }
}

// ---------------------------------------------------------------------------
// FP16 tensor-core GEMM (m16n8k16): A half [m][k], B half [n][k] pre-transposed,
// both XOR-swizzled in smem -> every fragment = 1 LDS.32, zero packs.
// cp.async 3-stage pipeline. BM=128, BN=128, BK=32; 8 warps (2Mx4N), 64x32
// warp tile. K fixed = 256. fp32 accumulate, fp32 bias/output.
// ---------------------------------------------------------------------------
#define STAGES 3
#define STAGE_BYTES (128 * 32 * 2 * 2)                 // A 8KB + B 8KB
#define GEMM_SMEM (STAGES * STAGE_BYTES)               // 49152

__global__ __launch_bounds__(256, 2) void gemm_h_kernel(
    const __half* __restrict__ A, const __half* __restrict__ Bt,
    const float* __restrict__ bias, float* __restrict__ C,
    int M, int N)
{
    extern __shared__ char smem[];
    constexpr int A_BYTES = 128 * 32 * 2;

    const int tid  = threadIdx.x;
    const int wid  = tid >> 5;
    const int lane = tid & 31;
    const int gid  = lane >> 2;      // 0..7
    const int tig  = lane & 3;       // 0..3
    const int warpM = wid >> 2;      // 0..1
    const int warpN = wid & 3;       // 0..3
    const int bm = blockIdx.y * 128;
    const int bn = blockIdx.x * 128;
    const int sw = (gid >> 1) << 2;  // XOR swizzle (4B units): 0,4,8,12

    float c[4][4][4];
    #pragma unroll
    for (int i = 0; i < 4; i++)
        #pragma unroll
        for (int j = 0; j < 4; j++)
            #pragma unroll
            for (int r = 0; r < 4; r++) c[i][j][r] = 0.f;

    const int K = 256, NT = 8;

    auto copy_tile = [&](int kt, char* stg) {
        const int k0 = kt * 32;
        __half* sA = (__half*)stg;
        __half* sB = (__half*)(stg + A_BYTES);
        #pragma unroll
        for (int i = 0; i < 2; i++) {
            const int o = tid * 2 + i;
            const int row = o >> 2, ch = o & 3;
            const int dst = row * 32 + ((((ch * 4) ^ (((row >> 1) & 3) * 4))) << 1);
            cp16(&sA[dst], A + (size_t)(bm + row) * K + k0 + ch * 8, bm + row < M);
            cp16(&sB[dst], Bt + (size_t)(bn + row) * K + k0 + ch * 8, true);
        }
    };

    copy_tile(0, smem);
    asm volatile("cp.async.commit_group;");
    copy_tile(1, smem + STAGE_BYTES);
    asm volatile("cp.async.commit_group;");

    for (int it = 0; it < NT; it++) {
        if (it < NT - 1) asm volatile("cp.async.wait_group 1;");
        else             asm volatile("cp.async.wait_group 0;");
        __syncthreads();

        char* stg = smem + (it % STAGES) * STAGE_BYTES;
        const __half* sA = (const __half*)stg;
        const __half* sB = (const __half*)(stg + A_BYTES);

        #pragma unroll
        for (int ks = 0; ks < 2; ks++) {
            const int c0 = ks * 8;
            const int u0 = ((c0    ) ^ sw) + tig;
            const int u1 = ((c0 + 4) ^ sw) + tig;

            uint32_t a[4][4];
            #pragma unroll
            for (int mt = 0; mt < 4; mt++) {
                const int m0 = warpM * 64 + mt * 16 + gid;
                a[mt][0] = *(const uint32_t*)&sA[(m0    ) * 32 + (u0 << 1)];
                a[mt][1] = *(const uint32_t*)&sA[(m0 + 8) * 32 + (u0 << 1)];
                a[mt][2] = *(const uint32_t*)&sA[(m0    ) * 32 + (u1 << 1)];
                a[mt][3] = *(const uint32_t*)&sA[(m0 + 8) * 32 + (u1 << 1)];
            }
            uint32_t b[4][2];
            #pragma unroll
            for (int nt = 0; nt < 4; nt++) {
                const int n0 = warpN * 32 + nt * 8 + gid;
                b[nt][0] = *(const uint32_t*)&sB[n0 * 32 + (u0 << 1)];
                b[nt][1] = *(const uint32_t*)&sB[n0 * 32 + (u1 << 1)];
            }
            #pragma unroll
            for (int mt = 0; mt < 4; mt++)
                #pragma unroll
                for (int nt = 0; nt < 4; nt++) {
                    asm volatile(
                        "mma.sync.aligned.m16n8k16.row.col.f32.f16.f16.f32 "
                        "{%0,%1,%2,%3}, {%4,%5,%6,%7}, {%8,%9}, {%0,%1,%2,%3};"
                        : "+f"(c[mt][nt][0]), "+f"(c[mt][nt][1]),
                          "+f"(c[mt][nt][2]), "+f"(c[mt][nt][3])
                        : "r"(a[mt][0]), "r"(a[mt][1]), "r"(a[mt][2]), "r"(a[mt][3]),
                          "r"(b[nt][0]), "r"(b[nt][1]));
                }
        }
        if (it + 2 < NT) {
            copy_tile(it + 2, smem + ((it + 2) % STAGES) * STAGE_BYTES);
            asm volatile("cp.async.commit_group;");
        }
    }

    #pragma unroll
    for (int mt = 0; mt < 4; mt++) {
        const int r0 = bm + warpM * 64 + mt * 16 + gid;
        #pragma unroll
        for (int nt = 0; nt < 4; nt++) {
            const int cc = bn + warpN * 32 + nt * 8 + tig * 2;
            const float bz0 = bias[cc], bz1 = bias[cc + 1];
            if (r0 < M) {
                float2 v = make_float2(c[mt][nt][0] + bz0, c[mt][nt][1] + bz1);
                *reinterpret_cast<float2*>(C + (size_t)r0 * N + cc) = v;
            }
            if (r0 + 8 < M) {
                float2 v = make_float2(c[mt][nt][2] + bz0, c[mt][nt][3] + bz1);
                *reinterpret_cast<float2*>(C + (size_t)(r0 + 8) * N + cc) = v;
            }
        }
    }
}

// ---------------------------------------------------------------------------
// Sampling v4: one warp per (b, q, head-half); lanes = 4 heads x 8 channel-
// quads. 128-thread blocks with __launch_bounds__(128,10) to force regs <=51
// -> 40-warp occupancy cap. Softmax normalization deferred to the final
// accumulator (linear). Packed f32x2 FFMA2 accumulation.
// ---------------------------------------------------------------------------
__global__ __launch_bounds__(128, 10) void sample_kernel(
    const float* __restrict__ refp,    // (B, L, NL, 2)
    const float* __restrict__ val,     // (B, S, 256) fp32
    const float* __restrict__ offattn, // (B, L, 384)
    __half* __restrict__ out_acc)      // (B, L, 256) half
{
    const int g = blockIdx.x * 4 + (threadIdx.x >> 5);
    if (g >= Bb * LQ * 2) return;
    const int bq   = g >> 1;
    const int half = g & 1;
    const int lane = threadIdx.x & 31;
    const int hg   = lane >> 3;
    const int c    = (lane & 7) * 4;
    const int b    = bq / LQ;
    const int h    = half * 4 + hg;

    // softmax logits -> unnormalized exp weights; inv applied at the end
    const float4* at4 = reinterpret_cast<const float4*>(
        offattn + (size_t)bq * 384 + 256 + h * 16);
    float lg[16];
    {
        float4 t0 = at4[0], t1 = at4[1], t2 = at4[2], t3 = at4[3];
        lg[0]=t0.x; lg[1]=t0.y; lg[2]=t0.z; lg[3]=t0.w;
        lg[4]=t1.x; lg[5]=t1.y; lg[6]=t1.z; lg[7]=t1.w;
        lg[8]=t2.x; lg[9]=t2.y; lg[10]=t2.z; lg[11]=t2.w;
        lg[12]=t3.x; lg[13]=t3.y; lg[14]=t3.z; lg[15]=t3.w;
    }
    float mxv = lg[0];
    #pragma unroll
    for (int j = 1; j < 16; j++) mxv = fmaxf(mxv, lg[j]);
    float s = 0.f;
    #pragma unroll
    for (int j = 0; j < 16; j++) { lg[j] = __expf(lg[j] - mxv); s += lg[j]; }
    const float inv = 1.0f / s;

    const float* of = offattn + (size_t)bq * 384 + h * 32;
    const float* rp = refp + (size_t)bq * 8;
    unsigned long long acc01 = 0ull, acc23 = 0ull;   // packed f32x2 zeros

    const int lWc[4] = {100, 50, 25, 13};
    const int lHc[4] = {100, 50, 25, 13};
    const int lSc[4] = {0, 10000, 12500, 13125};

    #pragma unroll
    for (int l = 0; l < 4; l++) {
        const int W = lWc[l], H = lHc[l];
        const float* vb = val + ((size_t)(b * Ss + lSc[l])) * 256 + h * 32 + c;
        const float rx = rp[l * 2 + 0] * (float)W - 0.5f;
        const float ry = rp[l * 2 + 1] * (float)H - 0.5f;
        const float4 o01 = reinterpret_cast<const float4*>(of + l * 8)[0];
        const float4 o23 = reinterpret_cast<const float4*>(of + l * 8)[1];
        const float ox[4] = {o01.x, o01.z, o23.x, o23.z};
        const float oy[4] = {o01.y, o01.w, o23.y, o23.w};

        #pragma unroll
        for (int p = 0; p < 4; p++) {
            const float x = rx + ox[p];
            const float y = ry + oy[p];
            const float wgt = lg[l * 4 + p];     // unnormalized

            const int x0 = __float2int_rd(x);
            const int y0 = __float2int_rd(y);
            const float wx1 = x - (float)x0, wy1 = y - (float)y0;
            const float wx0 = 1.f - wx1, wy0 = 1.f - wy1;

            const float mx0 = (x0 >= 0     && x0 < W)     ? 1.f : 0.f;
            const float mx1 = (x0 + 1 >= 0 && x0 + 1 < W) ? 1.f : 0.f;
            const float my0 = (y0 >= 0     && y0 < H)     ? 1.f : 0.f;
            const float my1 = (y0 + 1 >= 0 && y0 + 1 < H) ? 1.f : 0.f;

            const int xc0 = min(max(x0, 0), W - 1);
            const int xc1 = min(max(x0 + 1, 0), W - 1);
            const int yc0 = min(max(y0, 0), H - 1);
            const int yc1 = min(max(y0 + 1, 0), H - 1);

            const float wy0g = wgt * wy0 * my0;
            const float wy1g = wgt * wy1 * my1;
            const float wx0m = wx0 * mx0;
            const float wx1m = wx1 * mx1;

            const unsigned long long w00 = bcast2(wx0m * wy0g);
            const unsigned long long w10 = bcast2(wx1m * wy0g);
            const unsigned long long w01 = bcast2(wx0m * wy1g);
            const unsigned long long w11 = bcast2(wx1m * wy1g);

            const ulonglong2 v00 = *reinterpret_cast<const ulonglong2*>(vb + (size_t)(yc0 * W + xc0) * 256);
            const ulonglong2 v10 = *reinterpret_cast<const ulonglong2*>(vb + (size_t)(yc0 * W + xc1) * 256);
            const ulonglong2 v01 = *reinterpret_cast<const ulonglong2*>(vb + (size_t)(yc1 * W + xc0) * 256);
            const ulonglong2 v11 = *reinterpret_cast<const ulonglong2*>(vb + (size_t)(yc1 * W + xc1) * 256);

            ffma2(acc01, v00.x, w00); ffma2(acc23, v00.y, w00);
            ffma2(acc01, v10.x, w10); ffma2(acc23, v10.y, w10);
            ffma2(acc01, v01.x, w01); ffma2(acc23, v01.y, w01);
            ffma2(acc01, v11.x, w11); ffma2(acc23, v11.y, w11);
        }
    }

    // apply deferred softmax normalization
    const unsigned long long inv2 = bcast2(inv);
    fmul2(acc01, inv2);
    fmul2(acc23, inv2);

    uint32_t a0, a1, a2, a3;
    asm("mov.b64 {%0, %1}, %2;" : "=r"(a0), "=r"(a1) : "l"(acc01));
    asm("mov.b64 {%0, %1}, %2;" : "=r"(a2), "=r"(a3) : "l"(acc23));
    const uint32_t h01 = pack_h2(__uint_as_float(a0), __uint_as_float(a1));
    const uint32_t h23 = pack_h2(__uint_as_float(a2), __uint_as_float(a3));
    *reinterpret_cast<uint2*>(out_acc + (size_t)bq * 256 + h * 32 + c) =
        make_uint2(h01, h23);
}

// ---------------------------------------------------------------------------
// Launch
// ---------------------------------------------------------------------------
extern "C" void kernel_launch(void* const* d_in, const int* in_sizes, int n_in,
                              void* d_out, int out_size)
{
    const float* query  = (const float*)d_in[0];
    const float* refp   = (const float*)d_in[1];
    const float* value  = (const float*)d_in[2];
    const float* W_val  = (const float*)d_in[3];
    const float* b_val  = (const float*)d_in[4];
    const float* W_off  = (const float*)d_in[5];
    const float* b_off  = (const float*)d_in[6];
    const float* W_attn = (const float*)d_in[7];
    const float* b_attn = (const float*)d_in[8];
    const float* W_out  = (const float*)d_in[9];
    const float* b_out  = (const float*)d_in[10];
    float* out = (float*)d_out;

    float  *pval, *poa, *pbias_oa;
    __half *pacc, *pqh, *pvh, *pbtv, *pbtoa, *pbto;
    cudaGetSymbolAddress((void**)&pval,     g_val);
    cudaGetSymbolAddress((void**)&poa,      g_offattn);
    cudaGetSymbolAddress((void**)&pacc,     g_acc);
    cudaGetSymbolAddress((void**)&pqh,      g_query_h);
    cudaGetSymbolAddress((void**)&pvh,      g_value_h);
    cudaGetSymbolAddress((void**)&pbtv,     g_bt_val);
    cudaGetSymbolAddress((void**)&pbtoa,    g_bt_oa);
    cudaGetSymbolAddress((void**)&pbto,     g_bt_out);
    cudaGetSymbolAddress((void**)&pbias_oa, g_bias_oa);

    cudaFuncSetAttribute(gemm_h_kernel,
                         cudaFuncAttributeMaxDynamicSharedMemorySize, GEMM_SMEM);

    const dim3 blk(256);
    const int  gy = (MROWS + 127) / 128;
    const int  n4 = MROWS * 64;                       // float4 count per tensor

    // 0. weights -> half^T, bias fuse, query/value -> half (one kernel)
    prep_convert_kernel<<<(n4 + 255) / 256, blk>>>(
        W_val, W_off, W_attn, W_out, b_off, b_attn, query, value);
    // 1. val = value @ W_val + b_val            (half A, fp32 out)
    gemm_h_kernel<<<dim3(2, gy), blk, GEMM_SMEM>>>(pvh, pbtv, b_val, pval, MROWS, 256);
    // 2+3. [offsets | attn] = query @ [W_off|W_attn] + fused bias
    gemm_h_kernel<<<dim3(3, gy), blk, GEMM_SMEM>>>(pqh, pbtoa, pbias_oa, poa, MROWS, 384);
    // 4. softmax + deformable bilinear sampling -> g_acc (half)
    sample_kernel<<<(MROWS * 2 + 3) / 4, dim3(128)>>>(refp, pval, poa, pacc);
    // 5. out = g_acc @ W_out + b_out            (half A)
    gemm_h_kernel<<<dim3(2, gy), blk, GEMM_SMEM>>>(pacc, pbto, b_out, out, MROWS, 256);
}

// round 12
// speedup vs baseline: 3.9265x; 1.0017x over previous
#include <cuda_runtime.h>
#include <cuda_bf16.h>
#include <cuda_fp16.h>
#include <cstdint>
#include <cstddef>

// Problem constants
#define NHh 8
#define Dm  256
#define Bb  2
#define Ss  13294          // 100*100 + 50*50 + 25*25 + 13*13
#define LQ  13294
#define MROWS (Bb * LQ)    // 26588
#define PADB 14062         // padded rows/batch: 102*102 + 52*52 + 27*27 + 15*15

// Scratch (allocation-free: __device__ globals)
__device__ float  g_valp   [Bb * PADB * Dm];    // projected value, PADDED layout
__device__ float  g_offattn[MROWS * 384];       // fused offsets(256) + attn(128)
__device__ __half g_acc    [MROWS * Dm];        // sampled output (half)
__device__ __half g_query_h[MROWS * Dm];        // query -> half
__device__ __half g_value_h[MROWS * Dm];        // value -> half
__device__ __half g_bt_val [256 * 256];         // W_val^T  half [n][k]
__device__ __half g_bt_oa  [384 * 256];         // [W_off|W_attn]^T half [n][k]
__device__ __half g_bt_out [256 * 256];         // W_out^T  half [n][k]
__device__ float  g_bias_oa[384];               // fused b_off|b_attn

__device__ __forceinline__ uint32_t pack_h2(float lo, float hi) {
    uint32_t r;
    asm("cvt.rn.f16x2.f32 %0, %1, %2;" : "=r"(r) : "f"(hi), "f"(lo));
    return r;
}

__device__ __forceinline__ void cp16(void* s, const void* g, bool p) {
    uint32_t sa = (uint32_t)__cvta_generic_to_shared(s);
    const int sz = p ? 16 : 0;
    asm volatile("cp.async.ca.shared.global [%0], [%1], 16, %2;"
                 :: "r"(sa), "l"(g), "r"(sz));
}

// packed f32x2 helpers
__device__ __forceinline__ void ffma2(unsigned long long& acc,
                                      unsigned long long v,
                                      unsigned long long w) {
    asm("fma.rn.f32x2 %0, %1, %2, %0;" : "+l"(acc) : "l"(v), "l"(w));
}
__device__ __forceinline__ void fmul2(unsigned long long& acc,
                                      unsigned long long w) {
    asm("mul.rn.f32x2 %0, %0, %1;" : "+l"(acc) : "l"(w));
}
__device__ __forceinline__ unsigned long long bcast2(float w) {
    unsigned long long r;
    const uint32_t u = __float_as_uint(w);
    asm("mov.b64 %0, {%1, %1};" : "=l"(r) : "r"(u));
    return r;
}

// s-row -> padded row (within one batch). Constant divisors -> magic muls.
__device__ __forceinline__ int pad_row(int r) {
    int b = 0;
    if (r >= Ss) { b = 1; r -= Ss; }
    int pr;
    if (r < 10000)      { int y = r / 100;
                          pr = (y + 1) * 102 + (r - y * 100) + 1; }
    else if (r < 12500) { int t = r - 10000; int y = t / 50;
                          pr = 10404 + (y + 1) * 52 + (t - y * 50) + 1; }
    else if (r < 13125) { int t = r - 12500; int y = t / 25;
                          pr = 13108 + (y + 1) * 27 + (t - y * 25) + 1; }
    else                { int t = r - 13125; int y = t / 13;
                          pr = 13837 + (y + 1) * 15 + (t - y * 13) + 1; }
    return b * PADB + pr;
}

// ---------------------------------------------------------------------------
// prep+convert: weights -> half^T; biases fused; query/value -> half
// ---------------------------------------------------------------------------
__global__ __launch_bounds__(256) void prep_convert_kernel(
    const float* __restrict__ W_val, const float* __restrict__ W_off,
    const float* __restrict__ W_attn, const float* __restrict__ W_out,
    const float* __restrict__ b_off, const float* __restrict__ b_attn,
    const float* __restrict__ query, const float* __restrict__ value)
{
    const size_t t = (size_t)blockIdx.x * 256 + threadIdx.x;
    if (t < 65536) {
        const int n = (int)t >> 8, k = (int)t & 255;
        g_bt_val[t] = __float2half(W_val[k * 256 + n]);
        g_bt_out[t] = __float2half(W_out[k * 256 + n]);
    }
    if (t < 98304) {
        const int n = (int)t >> 8, k = (int)t & 255;
        const float v = (n < 256) ? W_off[k * 256 + n] : W_attn[k * 128 + (n - 256)];
        g_bt_oa[t] = __float2half(v);
    }
    if (t < 384)
        g_bias_oa[t] = (t < 256) ? b_off[t] : b_attn[t - 256];

    const size_t n4 = (size_t)MROWS * 64;
    if (t < n4) {
        const float4 q = reinterpret_cast<const float4*>(query)[t];
        const float4 v = reinterpret_cast<const float4*>(value)[t];
        reinterpret_cast<uint2*>(g_query_h)[t] =
            make_uint2(pack_h2(q.x, q.y), pack_h2(q.z, q.w));
        reinterpret_cast<uint2*>(g_value_h)[t] =
            make_uint2(pack_h2(v.x, v.y), pack_h2(v.z, v.w));
    }
}

// ---------------------------------------------------------------------------
// zero the border rows of the padded value buffer.
// grid (768, 2): 768 border cells per batch, 64 threads = 256 floats per cell.
// ---------------------------------------------------------------------------
__global__ __launch_bounds__(64) void zero_border_kernel()
{
    const int cidx = blockIdx.x;         // border cell index within batch
    const int b    = blockIdx.y;

    // level table: {W2, H2, pst, border_start}
    int W2, H2, pst, c;
    if      (cidx < 404) { W2 = 102; H2 = 102; pst = 0;     c = cidx;       }
    else if (cidx < 608) { W2 = 52;  H2 = 52;  pst = 10404; c = cidx - 404; }
    else if (cidx < 712) { W2 = 27;  H2 = 27;  pst = 13108; c = cidx - 608; }
    else                 { W2 = 15;  H2 = 15;  pst = 13837; c = cidx - 712; }

    int y, x;
    if      (c < W2)     { y = 0;      x = c;       }
    else if (c < 2 * W2) { y = H2 - 1; x = c - W2;  }
    else {
        const int r = c - 2 * W2;
        y = 1 + (r >> 1);
        x = (r & 1) ? (W2 - 1) : 0;
    }

    float4* row = reinterpret_cast<float4*>(
        g_valp + ((size_t)(b * PADB + pst + y * W2 + x)) * 256);
    row[threadIdx.x] = make_float4(0.f, 0.f, 0.f, 0.f);
}

// ---------------------------------------------------------------------------
// FP16 tensor-core GEMM (m16n8k16): A half [m][k], B half [n][k] pre-transposed,
// XOR-swizzled smem, cp.async 3-stage. PADOUT remaps output rows into the
// padded value layout (GEMM1 only).
// ---------------------------------------------------------------------------
#define STAGES 3
#define STAGE_BYTES (128 * 32 * 2 * 2)                 // A 8KB + B 8KB
#define GEMM_SMEM (STAGES * STAGE_BYTES)               // 49152

template<bool PADOUT>
__global__ __launch_bounds__(256, 2) void gemm_h_kernel(
    const __half* __restrict__ A, const __half* __restrict__ Bt,
    const float* __restrict__ bias, float* __restrict__ C,
    int M, int N)
{
    extern __shared__ char smem[];
    constexpr int A_BYTES = 128 * 32 * 2;

    const int tid  = threadIdx.x;
    const int wid  = tid >> 5;
    const int lane = tid & 31;
    const int gid  = lane >> 2;
    const int tig  = lane & 3;
    const int warpM = wid >> 2;
    const int warpN = wid & 3;
    const int bm = blockIdx.y * 128;
    const int bn = blockIdx.x * 128;

    float c[4][4][4];
    #pragma unroll
    for (int i = 0; i < 4; i++)
        #pragma unroll
        for (int j = 0; j < 4; j++)
            #pragma unroll
            for (int r = 0; r < 4; r++) c[i][j][r] = 0.f;

    const int K = 256, NT = 8;

    auto copy_tile = [&](int kt, char* stg) {
        const int k0 = kt * 32;
        __half* sA = (__half*)stg;
        __half* sB = (__half*)(stg + A_BYTES);
        #pragma unroll
        for (int i = 0; i < 2; i++) {
            const int o = tid * 2 + i;
            const int row = o >> 2, ch = o & 3;
            const int dst = row * 32 + ((((ch * 4) ^ (((row >> 1) & 3) * 4))) << 1);
            cp16(&sA[dst], A + (size_t)(bm + row) * K + k0 + ch * 8, bm + row < M);
            cp16(&sB[dst], Bt + (size_t)(bn + row) * K + k0 + ch * 8, true);
        }
    };

    copy_tile(0, smem);
    asm volatile("cp.async.commit_group;");
    copy_tile(1, smem + STAGE_BYTES);
    asm volatile("cp.async.commit_group;");

    const int sw = (gid >> 1) << 2;

    for (int it = 0; it < NT; it++) {
        if (it < NT - 1) asm volatile("cp.async.wait_group 1;");
        else             asm volatile("cp.async.wait_group 0;");
        __syncthreads();

        char* stg = smem + (it % STAGES) * STAGE_BYTES;
        const __half* sA = (const __half*)stg;
        const __half* sB = (const __half*)(stg + A_BYTES);

        #pragma unroll
        for (int ks = 0; ks < 2; ks++) {
            const int c0 = ks * 8;
            const int u0 = ((c0    ) ^ sw) + tig;
            const int u1 = ((c0 + 4) ^ sw) + tig;

            uint32_t a[4][4];
            #pragma unroll
            for (int mt = 0; mt < 4; mt++) {
                const int m0 = warpM * 64 + mt * 16 + gid;
                a[mt][0] = *(const uint32_t*)&sA[(m0    ) * 32 + (u0 << 1)];
                a[mt][1] = *(const uint32_t*)&sA[(m0 + 8) * 32 + (u0 << 1)];
                a[mt][2] = *(const uint32_t*)&sA[(m0    ) * 32 + (u1 << 1)];
                a[mt][3] = *(const uint32_t*)&sA[(m0 + 8) * 32 + (u1 << 1)];
            }
            uint32_t b[4][2];
            #pragma unroll
            for (int nt = 0; nt < 4; nt++) {
                const int n0 = warpN * 32 + nt * 8 + gid;
                b[nt][0] = *(const uint32_t*)&sB[n0 * 32 + (u0 << 1)];
                b[nt][1] = *(const uint32_t*)&sB[n0 * 32 + (u1 << 1)];
            }
            #pragma unroll
            for (int mt = 0; mt < 4; mt++)
                #pragma unroll
                for (int nt = 0; nt < 4; nt++) {
                    asm volatile(
                        "mma.sync.aligned.m16n8k16.row.col.f32.f16.f16.f32 "
                        "{%0,%1,%2,%3}, {%4,%5,%6,%7}, {%8,%9}, {%0,%1,%2,%3};"
                        : "+f"(c[mt][nt][0]), "+f"(c[mt][nt][1]),
                          "+f"(c[mt][nt][2]), "+f"(c[mt][nt][3])
                        : "r"(a[mt][0]), "r"(a[mt][1]), "r"(a[mt][2]), "r"(a[mt][3]),
                          "r"(b[nt][0]), "r"(b[nt][1]));
                }
        }
        if (it + 2 < NT) {
            copy_tile(it + 2, smem + ((it + 2) % STAGES) * STAGE_BYTES);
            asm volatile("cp.async.commit_group;");
        }
    }

    #pragma unroll
    for (int mt = 0; mt < 4; mt++) {
        const int r0 = bm + warpM * 64 + mt * 16 + gid;
        size_t orow0 = 0, orow1 = 0;
        if (PADOUT) {
            if (r0 < M)     orow0 = (size_t)pad_row(r0) * 256;
            if (r0 + 8 < M) orow1 = (size_t)pad_row(r0 + 8) * 256;
        } else {
            orow0 = (size_t)r0 * N;
            orow1 = (size_t)(r0 + 8) * N;
        }
        #pragma unroll
        for (int nt = 0; nt < 4; nt++) {
            const int cc = bn + warpN * 32 + nt * 8 + tig * 2;
            const float bz0 = bias[cc], bz1 = bias[cc + 1];
            if (r0 < M) {
                float2 v = make_float2(c[mt][nt][0] + bz0, c[mt][nt][1] + bz1);
                *reinterpret_cast<float2*>(C + orow0 + cc) = v;
            }
            if (r0 + 8 < M) {
                float2 v = make_float2(c[mt][nt][2] + bz0, c[mt][nt][3] + bz1);
                *reinterpret_cast<float2*>(C + orow1 + cc) = v;
            }
        }
    }
}

// ---------------------------------------------------------------------------
// Sampling v5: one warp per (b, q, head-half); lanes = 4 heads x 8 channel-
// quads. PADDED value layout: no masks — every corner is clamp(coord+1,
// 0, W+1); OOB corners land on exact-zero border cells. Deferred softmax
// normalization; packed f32x2 FFMA2 accumulation.
// ---------------------------------------------------------------------------
__global__ __launch_bounds__(128, 10) void sample_kernel(
    const float* __restrict__ refp,    // (B, L, NL, 2)
    const float* __restrict__ valp,    // padded (B, PADB, 256) fp32
    const float* __restrict__ offattn, // (B, L, 384)
    __half* __restrict__ out_acc)      // (B, L, 256) half
{
    const int g = blockIdx.x * 4 + (threadIdx.x >> 5);
    if (g >= Bb * LQ * 2) return;
    const int bq   = g >> 1;
    const int half = g & 1;
    const int lane = threadIdx.x & 31;
    const int hg   = lane >> 3;
    const int c    = (lane & 7) * 4;
    const int b    = bq / LQ;
    const int h    = half * 4 + hg;

    const float4* at4 = reinterpret_cast<const float4*>(
        offattn + (size_t)bq * 384 + 256 + h * 16);
    float lg[16];
    {
        float4 t0 = at4[0], t1 = at4[1], t2 = at4[2], t3 = at4[3];
        lg[0]=t0.x; lg[1]=t0.y; lg[2]=t0.z; lg[3]=t0.w;
        lg[4]=t1.x; lg[5]=t1.y; lg[6]=t1.z; lg[7]=t1.w;
        lg[8]=t2.x; lg[9]=t2.y; lg[10]=t2.z; lg[11]=t2.w;
        lg[12]=t3.x; lg[13]=t3.y; lg[14]=t3.z; lg[15]=t3.w;
    }
    float mxv = lg[0];
    #pragma unroll
    for (int j = 1; j < 16; j++) mxv = fmaxf(mxv, lg[j]);
    float s = 0.f;
    #pragma unroll
    for (int j = 0; j < 16; j++) { lg[j] = __expf(lg[j] - mxv); s += lg[j]; }
    const float inv = 1.0f / s;

    const float* of = offattn + (size_t)bq * 384 + h * 32;
    const float* rp = refp + (size_t)bq * 8;
    unsigned long long acc01 = 0ull, acc23 = 0ull;

    const int lWc[4]  = {100, 50, 25, 13};
    const int lHc[4]  = {100, 50, 25, 13};
    const int lPst[4] = {0, 10404, 13108, 13837};
    const int lW2[4]  = {102, 52, 27, 15};

    #pragma unroll
    for (int l = 0; l < 4; l++) {
        const int W = lWc[l], H = lHc[l], W2 = lW2[l];
        const float* vb = valp + ((size_t)(b * PADB + lPst[l])) * 256 + h * 32 + c;
        const float rx = rp[l * 2 + 0] * (float)W - 0.5f;
        const float ry = rp[l * 2 + 1] * (float)H - 0.5f;
        const float4 o01 = reinterpret_cast<const float4*>(of + l * 8)[0];
        const float4 o23 = reinterpret_cast<const float4*>(of + l * 8)[1];
        const float ox[4] = {o01.x, o01.z, o23.x, o23.z};
        const float oy[4] = {o01.y, o01.w, o23.y, o23.w};

        #pragma unroll
        for (int p = 0; p < 4; p++) {
            const float x = rx + ox[p];
            const float y = ry + oy[p];
            const float wgt = lg[l * 4 + p];

            const int x0 = __float2int_rd(x);
            const int y0 = __float2int_rd(y);
            const float wx1 = x - (float)x0, wy1 = y - (float)y0;
            const float wx0 = 1.f - wx1, wy0 = 1.f - wy1;

            // padded-clamped coordinates (+1 folded in); OOB -> border (zero)
            const int xp0 = min(max(x0 + 1, 0), W + 1);
            const int xp1 = min(max(x0 + 2, 0), W + 1);
            const int yp0 = min(max(y0 + 1, 0), H + 1);
            const int yp1 = min(max(y0 + 2, 0), H + 1);

            const int i00 = yp0 * W2 + xp0;
            const int i10 = i00 + (xp1 - xp0);
            const int i01 = yp1 * W2 + xp0;
            const int i11 = i01 + (xp1 - xp0);

            const float wy0g = wgt * wy0;
            const float wy1g = wgt * wy1;
            const unsigned long long w00 = bcast2(wx0 * wy0g);
            const unsigned long long w10 = bcast2(wx1 * wy0g);
            const unsigned long long w01 = bcast2(wx0 * wy1g);
            const unsigned long long w11 = bcast2(wx1 * wy1g);

            const ulonglong2 v00 = *reinterpret_cast<const ulonglong2*>(vb + (size_t)i00 * 256);
            const ulonglong2 v10 = *reinterpret_cast<const ulonglong2*>(vb + (size_t)i10 * 256);
            const ulonglong2 v01 = *reinterpret_cast<const ulonglong2*>(vb + (size_t)i01 * 256);
            const ulonglong2 v11 = *reinterpret_cast<const ulonglong2*>(vb + (size_t)i11 * 256);

            ffma2(acc01, v00.x, w00); ffma2(acc23, v00.y, w00);
            ffma2(acc01, v10.x, w10); ffma2(acc23, v10.y, w10);
            ffma2(acc01, v01.x, w01); ffma2(acc23, v01.y, w01);
            ffma2(acc01, v11.x, w11); ffma2(acc23, v11.y, w11);
        }
    }

    const unsigned long long inv2 = bcast2(inv);
    fmul2(acc01, inv2);
    fmul2(acc23, inv2);

    uint32_t a0, a1, a2, a3;
    asm("mov.b64 {%0, %1}, %2;" : "=r"(a0), "=r"(a1) : "l"(acc01));
    asm("mov.b64 {%0, %1}, %2;" : "=r"(a2), "=r"(a3) : "l"(acc23));
    const uint32_t h01 = pack_h2(__uint_as_float(a0), __uint_as_float(a1));
    const uint32_t h23 = pack_h2(__uint_as_float(a2), __uint_as_float(a3));
    *reinterpret_cast<uint2*>(out_acc + (size_t)bq * 256 + h * 32 + c) =
        make_uint2(h01, h23);
}

// ---------------------------------------------------------------------------
// Launch
// ---------------------------------------------------------------------------
extern "C" void kernel_launch(void* const* d_in, const int* in_sizes, int n_in,
                              void* d_out, int out_size)
{
    const float* query  = (const float*)d_in[0];
    const float* refp   = (const float*)d_in[1];
    const float* value  = (const float*)d_in[2];
    const float* W_val  = (const float*)d_in[3];
    const float* b_val  = (const float*)d_in[4];
    const float* W_off  = (const float*)d_in[5];
    const float* b_off  = (const float*)d_in[6];
    const float* W_attn = (const float*)d_in[7];
    const float* b_attn = (const float*)d_in[8];
    const float* W_out  = (const float*)d_in[9];
    const float* b_out  = (const float*)d_in[10];
    float* out = (float*)d_out;

    float  *pvalp, *poa, *pbias_oa;
    __half *pacc, *pqh, *pvh, *pbtv, *pbtoa, *pbto;
    cudaGetSymbolAddress((void**)&pvalp,    g_valp);
    cudaGetSymbolAddress((void**)&poa,      g_offattn);
    cudaGetSymbolAddress((void**)&pacc,     g_acc);
    cudaGetSymbolAddress((void**)&pqh,      g_query_h);
    cudaGetSymbolAddress((void**)&pvh,      g_value_h);
    cudaGetSymbolAddress((void**)&pbtv,     g_bt_val);
    cudaGetSymbolAddress((void**)&pbtoa,    g_bt_oa);
    cudaGetSymbolAddress((void**)&pbto,     g_bt_out);
    cudaGetSymbolAddress((void**)&pbias_oa, g_bias_oa);

    cudaFuncSetAttribute(gemm_h_kernel<false>,
                         cudaFuncAttributeMaxDynamicSharedMemorySize, GEMM_SMEM);
    cudaFuncSetAttribute(gemm_h_kernel<true>,
                         cudaFuncAttributeMaxDynamicSharedMemorySize, GEMM_SMEM);

    const dim3 blk(256);
    const int  gy = (MROWS + 127) / 128;
    const int  n4 = MROWS * 64;

    // 0a. weights -> half^T, bias fuse, query/value -> half
    prep_convert_kernel<<<(n4 + 255) / 256, blk>>>(
        W_val, W_off, W_attn, W_out, b_off, b_attn, query, value);
    // 0b. zero the padded-value border cells
    zero_border_kernel<<<dim3(768, 2), 64>>>();
    // 1. val = value @ W_val + b_val  -> PADDED layout
    gemm_h_kernel<true><<<dim3(2, gy), blk, GEMM_SMEM>>>(
        pvh, pbtv, b_val, pvalp, MROWS, 256);
    // 2+3. [offsets | attn] = query @ [W_off|W_attn] + fused bias
    gemm_h_kernel<false><<<dim3(3, gy), blk, GEMM_SMEM>>>(
        pqh, pbtoa, pbias_oa, poa, MROWS, 384);
    // 4. softmax + deformable bilinear sampling -> g_acc (half)
    sample_kernel<<<(MROWS * 2 + 3) / 4, dim3(128)>>>(refp, pvalp, poa, pacc);
    // 5. out = g_acc @ W_out + b_out
    gemm_h_kernel<false><<<dim3(2, gy), blk, GEMM_SMEM>>>(
        pacc, pbto, b_out, out, MROWS, 256);
}

// round 13
// speedup vs baseline: 4.4551x; 1.1346x over previous
#include <cuda_runtime.h>
#include <cuda_bf16.h>
#include <cuda_fp16.h>
#include <cstdint>
#include <cstddef>

// Problem constants
#define NHh 8
#define Dm  256
#define Bb  2
#define Ss  13294          // 100*100 + 50*50 + 25*25 + 13*13
#define LQ  13294
#define MROWS (Bb * LQ)    // 26588
#define PADB 14062         // padded rows/batch: 102*102 + 52*52 + 27*27 + 15*15

// Scratch (allocation-free: __device__ globals)
__device__ __half g_valp   [Bb * PADB * Dm];    // projected value, PADDED, HALF
__device__ float  g_offattn[MROWS * 384];       // fused offsets(256) + attn(128)
__device__ __half g_acc    [MROWS * Dm];        // sampled output (half)
__device__ __half g_query_h[MROWS * Dm];        // query -> half
__device__ __half g_value_h[MROWS * Dm];        // value -> half
__device__ __half g_bt_val [256 * 256];         // W_val^T  half [n][k]
__device__ __half g_bt_oa  [384 * 256];         // [W_off|W_attn]^T half [n][k]
__device__ __half g_bt_out [256 * 256];         // W_out^T  half [n][k]
__device__ float  g_bias_oa[384];               // fused b_off|b_attn

__device__ __forceinline__ uint32_t pack_h2(float lo, float hi) {
    uint32_t r;
    asm("cvt.rn.f16x2.f32 %0, %1, %2;" : "=r"(r) : "f"(hi), "f"(lo));
    return r;
}

__device__ __forceinline__ void cp16(void* s, const void* g, bool p) {
    uint32_t sa = (uint32_t)__cvta_generic_to_shared(s);
    const int sz = p ? 16 : 0;
    asm volatile("cp.async.ca.shared.global [%0], [%1], 16, %2;"
                 :: "r"(sa), "l"(g), "r"(sz));
}

// packed f32x2 helpers
__device__ __forceinline__ void ffma2(unsigned long long& acc,
                                      unsigned long long v,
                                      unsigned long long w) {
    asm("fma.rn.f32x2 %0, %1, %2, %0;" : "+l"(acc) : "l"(v), "l"(w));
}
__device__ __forceinline__ void fmul2(unsigned long long& acc,
                                      unsigned long long w) {
    asm("mul.rn.f32x2 %0, %0, %1;" : "+l"(acc) : "l"(w));
}
__device__ __forceinline__ unsigned long long bcast2(float w) {
    unsigned long long r;
    const uint32_t u = __float_as_uint(w);
    asm("mov.b64 %0, {%1, %1};" : "=l"(r) : "r"(u));
    return r;
}
// half2 bits -> packed f32x2
__device__ __forceinline__ unsigned long long h2f2(uint32_t h) {
    const __half2 hh = *reinterpret_cast<const __half2*>(&h);
    const float2 f = __half22float2(hh);
    unsigned long long r;
    asm("mov.b64 %0, {%1, %2};" : "=l"(r) : "f"(f.x), "f"(f.y));
    return r;
}

// s-row -> padded row (within one batch)
__device__ __forceinline__ int pad_row(int r) {
    int b = 0;
    if (r >= Ss) { b = 1; r -= Ss; }
    int pr;
    if (r < 10000)      { int y = r / 100;
                          pr = (y + 1) * 102 + (r - y * 100) + 1; }
    else if (r < 12500) { int t = r - 10000; int y = t / 50;
                          pr = 10404 + (y + 1) * 52 + (t - y * 50) + 1; }
    else if (r < 13125) { int t = r - 12500; int y = t / 25;
                          pr = 13108 + (y + 1) * 27 + (t - y * 25) + 1; }
    else                { int t = r - 13125; int y = t / 13;
                          pr = 13837 + (y + 1) * 15 + (t - y * 13) + 1; }
    return b * PADB + pr;
}

// ---------------------------------------------------------------------------
// prep+convert: weights -> half^T; biases fused; query/value -> half
// ---------------------------------------------------------------------------
__global__ __launch_bounds__(256) void prep_convert_kernel(
    const float* __restrict__ W_val, const float* __restrict__ W_off,
    const float* __restrict__ W_attn, const float* __restrict__ W_out,
    const float* __restrict__ b_off, const float* __restrict__ b_attn,
    const float* __restrict__ query, const float* __restrict__ value)
{
    const size_t t = (size_t)blockIdx.x * 256 + threadIdx.x;
    if (t < 65536) {
        const int n = (int)t >> 8, k = (int)t & 255;
        g_bt_val[t] = __float2half(W_val[k * 256 + n]);
        g_bt_out[t] = __float2half(W_out[k * 256 + n]);
    }
    if (t < 98304) {
        const int n = (int)t >> 8, k = (int)t & 255;
        const float v = (n < 256) ? W_off[k * 256 + n] : W_attn[k * 128 + (n - 256)];
        g_bt_oa[t] = __float2half(v);
    }
    if (t < 384)
        g_bias_oa[t] = (t < 256) ? b_off[t] : b_attn[t - 256];

    const size_t n4 = (size_t)MROWS * 64;
    if (t < n4) {
        const float4 q = reinterpret_cast<const float4*>(query)[t];
        const float4 v = reinterpret_cast<const float4*>(value)[t];
        reinterpret_cast<uint2*>(g_query_h)[t] =
            make_uint2(pack_h2(q.x, q.y), pack_h2(q.z, q.w));
        reinterpret_cast<uint2*>(g_value_h)[t] =
            make_uint2(pack_h2(v.x, v.y), pack_h2(v.z, v.w));
    }
}

// ---------------------------------------------------------------------------
// zero the border rows of the padded (half) value buffer.
// grid (768, 2); 64 threads x 8B = 512B = one row of 256 halfs.
// ---------------------------------------------------------------------------
__global__ __launch_bounds__(64) void zero_border_kernel()
{
    const int cidx = blockIdx.x;
    const int b    = blockIdx.y;

    int W2, H2, pst, c;
    if      (cidx < 404) { W2 = 102; H2 = 102; pst = 0;     c = cidx;       }
    else if (cidx < 608) { W2 = 52;  H2 = 52;  pst = 10404; c = cidx - 404; }
    else if (cidx < 712) { W2 = 27;  H2 = 27;  pst = 13108; c = cidx - 608; }
    else                 { W2 = 15;  H2 = 15;  pst = 13837; c = cidx - 712; }

    int y, x;
    if      (c < W2)     { y = 0;      x = c;       }
    else if (c < 2 * W2) { y = H2 - 1; x = c - W2;  }
    else {
        const int r = c - 2 * W2;
        y = 1 + (r >> 1);
        x = (r & 1) ? (W2 - 1) : 0;
    }

    uint2* row = reinterpret_cast<uint2*>(
        g_valp + ((size_t)(b * PADB + pst + y * W2 + x)) * 256);
    row[threadIdx.x] = make_uint2(0u, 0u);
}

// ---------------------------------------------------------------------------
// Stage-1 fused GEMM: one launch covers
//   problem 0 (blockIdx.x < 2):  valp(half,padded) = value_h @ bt_val + b_val
//   problem 1 (blockIdx.x >= 2): offattn(f32)      = query_h @ bt_oa  + bias_oa
// m16n8k16 HMMA, XOR-swizzled smem, cp.async 3-stage. K=256.
// ---------------------------------------------------------------------------
#define STAGES 3
#define STAGE_BYTES (128 * 32 * 2 * 2)
#define GEMM_SMEM (STAGES * STAGE_BYTES)

__global__ __launch_bounds__(256, 2) void gemm_stage1_kernel(
    const __half* __restrict__ Aval, const __half* __restrict__ Btval,
    const float* __restrict__ bval,
    const __half* __restrict__ Aq, const __half* __restrict__ Btoa,
    const float* __restrict__ boa, float* __restrict__ Coa)
{
    extern __shared__ char smem[];
    constexpr int A_BYTES = 128 * 32 * 2;

    const bool padout = (blockIdx.x < 2);
    const __half* A   = padout ? Aval  : Aq;
    const __half* Bt  = padout ? Btval : Btoa;
    const float* bias = padout ? bval  : boa;
    const int bn = (padout ? blockIdx.x : (blockIdx.x - 2)) * 128;

    const int tid  = threadIdx.x;
    const int wid  = tid >> 5;
    const int lane = tid & 31;
    const int gid  = lane >> 2;
    const int tig  = lane & 3;
    const int warpM = wid >> 2;
    const int warpN = wid & 3;
    const int bm = blockIdx.y * 128;
    const int M = MROWS;

    float c[4][4][4];
    #pragma unroll
    for (int i = 0; i < 4; i++)
        #pragma unroll
        for (int j = 0; j < 4; j++)
            #pragma unroll
            for (int r = 0; r < 4; r++) c[i][j][r] = 0.f;

    const int K = 256, NT = 8;

    auto copy_tile = [&](int kt, char* stg) {
        const int k0 = kt * 32;
        __half* sA = (__half*)stg;
        __half* sB = (__half*)(stg + A_BYTES);
        #pragma unroll
        for (int i = 0; i < 2; i++) {
            const int o = tid * 2 + i;
            const int row = o >> 2, ch = o & 3;
            const int dst = row * 32 + ((((ch * 4) ^ (((row >> 1) & 3) * 4))) << 1);
            cp16(&sA[dst], A + (size_t)(bm + row) * K + k0 + ch * 8, bm + row < M);
            cp16(&sB[dst], Bt + (size_t)(bn + row) * K + k0 + ch * 8, true);
        }
    };

    copy_tile(0, smem);
    asm volatile("cp.async.commit_group;");
    copy_tile(1, smem + STAGE_BYTES);
    asm volatile("cp.async.commit_group;");

    const int sw = (gid >> 1) << 2;

    for (int it = 0; it < NT; it++) {
        if (it < NT - 1) asm volatile("cp.async.wait_group 1;");
        else             asm volatile("cp.async.wait_group 0;");
        __syncthreads();

        char* stg = smem + (it % STAGES) * STAGE_BYTES;
        const __half* sA = (const __half*)stg;
        const __half* sB = (const __half*)(stg + A_BYTES);

        #pragma unroll
        for (int ks = 0; ks < 2; ks++) {
            const int c0 = ks * 8;
            const int u0 = ((c0    ) ^ sw) + tig;
            const int u1 = ((c0 + 4) ^ sw) + tig;

            uint32_t a[4][4];
            #pragma unroll
            for (int mt = 0; mt < 4; mt++) {
                const int m0 = warpM * 64 + mt * 16 + gid;
                a[mt][0] = *(const uint32_t*)&sA[(m0    ) * 32 + (u0 << 1)];
                a[mt][1] = *(const uint32_t*)&sA[(m0 + 8) * 32 + (u0 << 1)];
                a[mt][2] = *(const uint32_t*)&sA[(m0    ) * 32 + (u1 << 1)];
                a[mt][3] = *(const uint32_t*)&sA[(m0 + 8) * 32 + (u1 << 1)];
            }
            uint32_t b[4][2];
            #pragma unroll
            for (int nt = 0; nt < 4; nt++) {
                const int n0 = warpN * 32 + nt * 8 + gid;
                b[nt][0] = *(const uint32_t*)&sB[n0 * 32 + (u0 << 1)];
                b[nt][1] = *(const uint32_t*)&sB[n0 * 32 + (u1 << 1)];
            }
            #pragma unroll
            for (int mt = 0; mt < 4; mt++)
                #pragma unroll
                for (int nt = 0; nt < 4; nt++) {
                    asm volatile(
                        "mma.sync.aligned.m16n8k16.row.col.f32.f16.f16.f32 "
                        "{%0,%1,%2,%3}, {%4,%5,%6,%7}, {%8,%9}, {%0,%1,%2,%3};"
                        : "+f"(c[mt][nt][0]), "+f"(c[mt][nt][1]),
                          "+f"(c[mt][nt][2]), "+f"(c[mt][nt][3])
                        : "r"(a[mt][0]), "r"(a[mt][1]), "r"(a[mt][2]), "r"(a[mt][3]),
                          "r"(b[nt][0]), "r"(b[nt][1]));
                }
        }
        if (it + 2 < NT) {
            copy_tile(it + 2, smem + ((it + 2) % STAGES) * STAGE_BYTES);
            asm volatile("cp.async.commit_group;");
        }
    }

    #pragma unroll
    for (int mt = 0; mt < 4; mt++) {
        const int r0 = bm + warpM * 64 + mt * 16 + gid;
        if (padout) {
            size_t orow0 = 0, orow1 = 0;
            if (r0 < MROWS)     orow0 = (size_t)pad_row(r0) * 256;
            if (r0 + 8 < MROWS) orow1 = (size_t)pad_row(r0 + 8) * 256;
            #pragma unroll
            for (int nt = 0; nt < 4; nt++) {
                const int cc = bn + warpN * 32 + nt * 8 + tig * 2;
                const float bz0 = bval[cc], bz1 = bval[cc + 1];
                if (r0 < MROWS)
                    *reinterpret_cast<uint32_t*>(g_valp + orow0 + cc) =
                        pack_h2(c[mt][nt][0] + bz0, c[mt][nt][1] + bz1);
                if (r0 + 8 < MROWS)
                    *reinterpret_cast<uint32_t*>(g_valp + orow1 + cc) =
                        pack_h2(c[mt][nt][2] + bz0, c[mt][nt][3] + bz1);
            }
        } else {
            #pragma unroll
            for (int nt = 0; nt < 4; nt++) {
                const int cc = bn + warpN * 32 + nt * 8 + tig * 2;
                const float bz0 = bias[cc], bz1 = bias[cc + 1];
                if (r0 < MROWS) {
                    float2 v = make_float2(c[mt][nt][0] + bz0, c[mt][nt][1] + bz1);
                    *reinterpret_cast<float2*>(Coa + (size_t)r0 * 384 + cc) = v;
                }
                if (r0 + 8 < MROWS) {
                    float2 v = make_float2(c[mt][nt][2] + bz0, c[mt][nt][3] + bz1);
                    *reinterpret_cast<float2*>(Coa + (size_t)(r0 + 8) * 384 + cc) = v;
                }
            }
        }
    }
}

// ---------------------------------------------------------------------------
// Output GEMM (unchanged lean path): out = g_acc @ bt_out + b_out (fp32 out)
// ---------------------------------------------------------------------------
__global__ __launch_bounds__(256, 2) void gemm_out_kernel(
    const __half* __restrict__ A, const __half* __restrict__ Bt,
    const float* __restrict__ bias, float* __restrict__ C,
    int M, int N)
{
    extern __shared__ char smem[];
    constexpr int A_BYTES = 128 * 32 * 2;

    const int tid  = threadIdx.x;
    const int wid  = tid >> 5;
    const int lane = tid & 31;
    const int gid  = lane >> 2;
    const int tig  = lane & 3;
    const int warpM = wid >> 2;
    const int warpN = wid & 3;
    const int bm = blockIdx.y * 128;
    const int bn = blockIdx.x * 128;

    float c[4][4][4];
    #pragma unroll
    for (int i = 0; i < 4; i++)
        #pragma unroll
        for (int j = 0; j < 4; j++)
            #pragma unroll
            for (int r = 0; r < 4; r++) c[i][j][r] = 0.f;

    const int K = 256, NT = 8;

    auto copy_tile = [&](int kt, char* stg) {
        const int k0 = kt * 32;
        __half* sA = (__half*)stg;
        __half* sB = (__half*)(stg + A_BYTES);
        #pragma unroll
        for (int i = 0; i < 2; i++) {
            const int o = tid * 2 + i;
            const int row = o >> 2, ch = o & 3;
            const int dst = row * 32 + ((((ch * 4) ^ (((row >> 1) & 3) * 4))) << 1);
            cp16(&sA[dst], A + (size_t)(bm + row) * K + k0 + ch * 8, bm + row < M);
            cp16(&sB[dst], Bt + (size_t)(bn + row) * K + k0 + ch * 8, true);
        }
    };

    copy_tile(0, smem);
    asm volatile("cp.async.commit_group;");
    copy_tile(1, smem + STAGE_BYTES);
    asm volatile("cp.async.commit_group;");

    const int sw = (gid >> 1) << 2;

    for (int it = 0; it < NT; it++) {
        if (it < NT - 1) asm volatile("cp.async.wait_group 1;");
        else             asm volatile("cp.async.wait_group 0;");
        __syncthreads();

        char* stg = smem + (it % STAGES) * STAGE_BYTES;
        const __half* sA = (const __half*)stg;
        const __half* sB = (const __half*)(stg + A_BYTES);

        #pragma unroll
        for (int ks = 0; ks < 2; ks++) {
            const int c0 = ks * 8;
            const int u0 = ((c0    ) ^ sw) + tig;
            const int u1 = ((c0 + 4) ^ sw) + tig;

            uint32_t a[4][4];
            #pragma unroll
            for (int mt = 0; mt < 4; mt++) {
                const int m0 = warpM * 64 + mt * 16 + gid;
                a[mt][0] = *(const uint32_t*)&sA[(m0    ) * 32 + (u0 << 1)];
                a[mt][1] = *(const uint32_t*)&sA[(m0 + 8) * 32 + (u0 << 1)];
                a[mt][2] = *(const uint32_t*)&sA[(m0    ) * 32 + (u1 << 1)];
                a[mt][3] = *(const uint32_t*)&sA[(m0 + 8) * 32 + (u1 << 1)];
            }
            uint32_t b[4][2];
            #pragma unroll
            for (int nt = 0; nt < 4; nt++) {
                const int n0 = warpN * 32 + nt * 8 + gid;
                b[nt][0] = *(const uint32_t*)&sB[n0 * 32 + (u0 << 1)];
                b[nt][1] = *(const uint32_t*)&sB[n0 * 32 + (u1 << 1)];
            }
            #pragma unroll
            for (int mt = 0; mt < 4; mt++)
                #pragma unroll
                for (int nt = 0; nt < 4; nt++) {
                    asm volatile(
                        "mma.sync.aligned.m16n8k16.row.col.f32.f16.f16.f32 "
                        "{%0,%1,%2,%3}, {%4,%5,%6,%7}, {%8,%9}, {%0,%1,%2,%3};"
                        : "+f"(c[mt][nt][0]), "+f"(c[mt][nt][1]),
                          "+f"(c[mt][nt][2]), "+f"(c[mt][nt][3])
                        : "r"(a[mt][0]), "r"(a[mt][1]), "r"(a[mt][2]), "r"(a[mt][3]),
                          "r"(b[nt][0]), "r"(b[nt][1]));
                }
        }
        if (it + 2 < NT) {
            copy_tile(it + 2, smem + ((it + 2) % STAGES) * STAGE_BYTES);
            asm volatile("cp.async.commit_group;");
        }
    }

    #pragma unroll
    for (int mt = 0; mt < 4; mt++) {
        const int r0 = bm + warpM * 64 + mt * 16 + gid;
        #pragma unroll
        for (int nt = 0; nt < 4; nt++) {
            const int cc = bn + warpN * 32 + nt * 8 + tig * 2;
            const float bz0 = bias[cc], bz1 = bias[cc + 1];
            if (r0 < M) {
                float2 v = make_float2(c[mt][nt][0] + bz0, c[mt][nt][1] + bz1);
                *reinterpret_cast<float2*>(C + (size_t)r0 * N + cc) = v;
            }
            if (r0 + 8 < M) {
                float2 v = make_float2(c[mt][nt][2] + bz0, c[mt][nt][3] + bz1);
                *reinterpret_cast<float2*>(C + (size_t)(r0 + 8) * N + cc) = v;
            }
        }
    }
}

// ---------------------------------------------------------------------------
// Sampling v6: HALF padded value buffer. One warp per (b, q, head-half);
// lanes = 4 heads x 8 channel-quads (8B half loads -> 2 L1 wavefronts/corner).
// Border-padded (maskless); deferred softmax; packed f32x2 FFMA2.
// ---------------------------------------------------------------------------
__global__ __launch_bounds__(128, 8) void sample_kernel(
    const float* __restrict__ refp,    // (B, L, NL, 2)
    const __half* __restrict__ valp,   // padded (B, PADB, 256) half
    const float* __restrict__ offattn, // (B, L, 384)
    __half* __restrict__ out_acc)      // (B, L, 256) half
{
    const int g = blockIdx.x * 4 + (threadIdx.x >> 5);
    if (g >= Bb * LQ * 2) return;
    const int bq   = g >> 1;
    const int half = g & 1;
    const int lane = threadIdx.x & 31;
    const int hg   = lane >> 3;
    const int c    = (lane & 7) * 4;
    const int b    = bq / LQ;
    const int h    = half * 4 + hg;

    const float4* at4 = reinterpret_cast<const float4*>(
        offattn + (size_t)bq * 384 + 256 + h * 16);
    float lg[16];
    {
        float4 t0 = at4[0], t1 = at4[1], t2 = at4[2], t3 = at4[3];
        lg[0]=t0.x; lg[1]=t0.y; lg[2]=t0.z; lg[3]=t0.w;
        lg[4]=t1.x; lg[5]=t1.y; lg[6]=t1.z; lg[7]=t1.w;
        lg[8]=t2.x; lg[9]=t2.y; lg[10]=t2.z; lg[11]=t2.w;
        lg[12]=t3.x; lg[13]=t3.y; lg[14]=t3.z; lg[15]=t3.w;
    }
    float mxv = lg[0];
    #pragma unroll
    for (int j = 1; j < 16; j++) mxv = fmaxf(mxv, lg[j]);
    float s = 0.f;
    #pragma unroll
    for (int j = 0; j < 16; j++) { lg[j] = __expf(lg[j] - mxv); s += lg[j]; }
    const float inv = 1.0f / s;

    const float* of = offattn + (size_t)bq * 384 + h * 32;
    const float* rp = refp + (size_t)bq * 8;
    unsigned long long acc01 = 0ull, acc23 = 0ull;

    const int lWc[4]  = {100, 50, 25, 13};
    const int lHc[4]  = {100, 50, 25, 13};
    const int lPst[4] = {0, 10404, 13108, 13837};
    const int lW2[4]  = {102, 52, 27, 15};

    #pragma unroll
    for (int l = 0; l < 4; l++) {
        const int W = lWc[l], H = lHc[l], W2 = lW2[l];
        const __half* vb = valp + ((size_t)(b * PADB + lPst[l])) * 256 + h * 32 + c;
        const float rx = rp[l * 2 + 0] * (float)W - 0.5f;
        const float ry = rp[l * 2 + 1] * (float)H - 0.5f;
        const float4 o01 = reinterpret_cast<const float4*>(of + l * 8)[0];
        const float4 o23 = reinterpret_cast<const float4*>(of + l * 8)[1];
        const float ox[4] = {o01.x, o01.z, o23.x, o23.z};
        const float oy[4] = {o01.y, o01.w, o23.y, o23.w};

        #pragma unroll
        for (int p = 0; p < 4; p++) {
            const float x = rx + ox[p];
            const float y = ry + oy[p];
            const float wgt = lg[l * 4 + p];

            const int x0 = __float2int_rd(x);
            const int y0 = __float2int_rd(y);
            const float wx1 = x - (float)x0, wy1 = y - (float)y0;
            const float wx0 = 1.f - wx1, wy0 = 1.f - wy1;

            const int xp0 = min(max(x0 + 1, 0), W + 1);
            const int xp1 = min(max(x0 + 2, 0), W + 1);
            const int yp0 = min(max(y0 + 1, 0), H + 1);
            const int yp1 = min(max(y0 + 2, 0), H + 1);

            const int i00 = yp0 * W2 + xp0;
            const int i10 = i00 + (xp1 - xp0);
            const int i01 = yp1 * W2 + xp0;
            const int i11 = i01 + (xp1 - xp0);

            const float wy0g = wgt * wy0;
            const float wy1g = wgt * wy1;
            const unsigned long long w00 = bcast2(wx0 * wy0g);
            const unsigned long long w10 = bcast2(wx1 * wy0g);
            const unsigned long long w01 = bcast2(wx0 * wy1g);
            const unsigned long long w11 = bcast2(wx1 * wy1g);

            const uint2 v00 = *reinterpret_cast<const uint2*>(vb + (size_t)i00 * 256);
            const uint2 v10 = *reinterpret_cast<const uint2*>(vb + (size_t)i10 * 256);
            const uint2 v01 = *reinterpret_cast<const uint2*>(vb + (size_t)i01 * 256);
            const uint2 v11 = *reinterpret_cast<const uint2*>(vb + (size_t)i11 * 256);

            ffma2(acc01, h2f2(v00.x), w00); ffma2(acc23, h2f2(v00.y), w00);
            ffma2(acc01, h2f2(v10.x), w10); ffma2(acc23, h2f2(v10.y), w10);
            ffma2(acc01, h2f2(v01.x), w01); ffma2(acc23, h2f2(v01.y), w01);
            ffma2(acc01, h2f2(v11.x), w11); ffma2(acc23, h2f2(v11.y), w11);
        }
    }

    const unsigned long long inv2 = bcast2(inv);
    fmul2(acc01, inv2);
    fmul2(acc23, inv2);

    uint32_t a0, a1, a2, a3;
    asm("mov.b64 {%0, %1}, %2;" : "=r"(a0), "=r"(a1) : "l"(acc01));
    asm("mov.b64 {%0, %1}, %2;" : "=r"(a2), "=r"(a3) : "l"(acc23));
    const uint32_t h01 = pack_h2(__uint_as_float(a0), __uint_as_float(a1));
    const uint32_t h23 = pack_h2(__uint_as_float(a2), __uint_as_float(a3));
    *reinterpret_cast<uint2*>(out_acc + (size_t)bq * 256 + h * 32 + c) =
        make_uint2(h01, h23);
}

// ---------------------------------------------------------------------------
// Launch
// ---------------------------------------------------------------------------
extern "C" void kernel_launch(void* const* d_in, const int* in_sizes, int n_in,
                              void* d_out, int out_size)
{
    const float* query  = (const float*)d_in[0];
    const float* refp   = (const float*)d_in[1];
    const float* value  = (const float*)d_in[2];
    const float* W_val  = (const float*)d_in[3];
    const float* b_val  = (const float*)d_in[4];
    const float* W_off  = (const float*)d_in[5];
    const float* b_off  = (const float*)d_in[6];
    const float* W_attn = (const float*)d_in[7];
    const float* b_attn = (const float*)d_in[8];
    const float* W_out  = (const float*)d_in[9];
    const float* b_out  = (const float*)d_in[10];
    float* out = (float*)d_out;

    float  *poa, *pbias_oa;
    __half *pvalp, *pacc, *pqh, *pvh, *pbtv, *pbtoa, *pbto;
    cudaGetSymbolAddress((void**)&pvalp,    g_valp);
    cudaGetSymbolAddress((void**)&poa,      g_offattn);
    cudaGetSymbolAddress((void**)&pacc,     g_acc);
    cudaGetSymbolAddress((void**)&pqh,      g_query_h);
    cudaGetSymbolAddress((void**)&pvh,      g_value_h);
    cudaGetSymbolAddress((void**)&pbtv,     g_bt_val);
    cudaGetSymbolAddress((void**)&pbtoa,    g_bt_oa);
    cudaGetSymbolAddress((void**)&pbto,     g_bt_out);
    cudaGetSymbolAddress((void**)&pbias_oa, g_bias_oa);

    cudaFuncSetAttribute(gemm_stage1_kernel,
                         cudaFuncAttributeMaxDynamicSharedMemorySize, GEMM_SMEM);
    cudaFuncSetAttribute(gemm_out_kernel,
                         cudaFuncAttributeMaxDynamicSharedMemorySize, GEMM_SMEM);

    const dim3 blk(256);
    const int  gy = (MROWS + 127) / 128;
    const int  n4 = MROWS * 64;

    // 0a. weights -> half^T, bias fuse, query/value -> half
    prep_convert_kernel<<<(n4 + 255) / 256, blk>>>(
        W_val, W_off, W_attn, W_out, b_off, b_attn, query, value);
    // 0b. zero the padded-value border cells (half)
    zero_border_kernel<<<dim3(768, 2), 64>>>();
    // 1+2+3. fused stage-1 GEMMs (value proj -> half padded; off+attn -> f32)
    gemm_stage1_kernel<<<dim3(5, gy), blk, GEMM_SMEM>>>(
        pvh, pbtv, b_val, pqh, pbtoa, pbias_oa, poa);
    // 4. softmax + deformable bilinear sampling -> g_acc (half)
    sample_kernel<<<(MROWS * 2 + 3) / 4, dim3(128)>>>(refp, pvalp, poa, pacc);
    // 5. out = g_acc @ W_out + b_out
    gemm_out_kernel<<<dim3(2, gy), blk, GEMM_SMEM>>>(
        pacc, pbto, b_out, out, MROWS, 256);
}

// round 14
// speedup vs baseline: 4.7031x; 1.0557x over previous
#include <cuda_runtime.h>
#include <cuda_bf16.h>
#include <cuda_fp16.h>
#include <cstdint>
#include <cstddef>

// Problem constants
#define NHh 8
#define Dm  256
#define Bb  2
#define Ss  13294          // 100*100 + 50*50 + 25*25 + 13*13
#define LQ  13294
#define MROWS (Bb * LQ)    // 26588
#define PADB 14062         // padded rows/batch: 102*102 + 52*52 + 27*27 + 15*15

// Scratch (allocation-free: __device__ globals)
// g_valp layout: (B, NH, PADB, 32) half — HEAD-MAJOR, 64B rows
__device__ __half g_valp   [Bb * NHh * PADB * 32];
__device__ float  g_offattn[MROWS * 384];       // fused offsets(256) + attn(128)
__device__ __half g_acc    [MROWS * Dm];        // sampled output (half)
__device__ __half g_query_h[MROWS * Dm];        // query -> half
__device__ __half g_value_h[MROWS * Dm];        // value -> half
__device__ __half g_bt_val [256 * 256];         // W_val^T  half [n][k]
__device__ __half g_bt_oa  [384 * 256];         // [W_off|W_attn]^T half [n][k]
__device__ __half g_bt_out [256 * 256];         // W_out^T  half [n][k]
__device__ float  g_bias_oa[384];               // fused b_off|b_attn

__device__ __forceinline__ uint32_t pack_h2(float lo, float hi) {
    uint32_t r;
    asm("cvt.rn.f16x2.f32 %0, %1, %2;" : "=r"(r) : "f"(hi), "f"(lo));
    return r;
}

__device__ __forceinline__ void cp16(void* s, const void* g, bool p) {
    uint32_t sa = (uint32_t)__cvta_generic_to_shared(s);
    const int sz = p ? 16 : 0;
    asm volatile("cp.async.ca.shared.global [%0], [%1], 16, %2;"
                 :: "r"(sa), "l"(g), "r"(sz));
}

// packed f32x2 helpers
__device__ __forceinline__ void ffma2(unsigned long long& acc,
                                      unsigned long long v,
                                      unsigned long long w) {
    asm("fma.rn.f32x2 %0, %1, %2, %0;" : "+l"(acc) : "l"(v), "l"(w));
}
__device__ __forceinline__ void fmul2(unsigned long long& acc,
                                      unsigned long long w) {
    asm("mul.rn.f32x2 %0, %0, %1;" : "+l"(acc) : "l"(w));
}
__device__ __forceinline__ void fadd2(unsigned long long& acc,
                                      unsigned long long v) {
    asm("add.rn.f32x2 %0, %0, %1;" : "+l"(acc) : "l"(v));
}
__device__ __forceinline__ unsigned long long bcast2(float w) {
    unsigned long long r;
    const uint32_t u = __float_as_uint(w);
    asm("mov.b64 %0, {%1, %1};" : "=l"(r) : "r"(u));
    return r;
}
// half2 bits -> packed f32x2
__device__ __forceinline__ unsigned long long h2f2(uint32_t h) {
    const __half2 hh = *reinterpret_cast<const __half2*>(&h);
    const float2 f = __half22float2(hh);
    unsigned long long r;
    asm("mov.b64 %0, {%1, %2};" : "=l"(r) : "f"(f.x), "f"(f.y));
    return r;
}

// s-row -> (batch, padded row)
__device__ __forceinline__ void pad_row_bh(int r, int& bb, int& pr) {
    bb = 0;
    if (r >= Ss) { bb = 1; r -= Ss; }
    if (r < 10000)      { int y = r / 100;
                          pr = (y + 1) * 102 + (r - y * 100) + 1; }
    else if (r < 12500) { int t = r - 10000; int y = t / 50;
                          pr = 10404 + (y + 1) * 52 + (t - y * 50) + 1; }
    else if (r < 13125) { int t = r - 12500; int y = t / 25;
                          pr = 13108 + (y + 1) * 27 + (t - y * 25) + 1; }
    else                { int t = r - 13125; int y = t / 13;
                          pr = 13837 + (y + 1) * 15 + (t - y * 13) + 1; }
}

// ---------------------------------------------------------------------------
// prep+convert: weights -> half^T; biases fused; query/value -> half
// ---------------------------------------------------------------------------
__global__ __launch_bounds__(256) void prep_convert_kernel(
    const float* __restrict__ W_val, const float* __restrict__ W_off,
    const float* __restrict__ W_attn, const float* __restrict__ W_out,
    const float* __restrict__ b_off, const float* __restrict__ b_attn,
    const float* __restrict__ query, const float* __restrict__ value)
{
    const size_t t = (size_t)blockIdx.x * 256 + threadIdx.x;
    if (t < 65536) {
        const int n = (int)t >> 8, k = (int)t & 255;
        g_bt_val[t] = __float2half(W_val[k * 256 + n]);
        g_bt_out[t] = __float2half(W_out[k * 256 + n]);
    }
    if (t < 98304) {
        const int n = (int)t >> 8, k = (int)t & 255;
        const float v = (n < 256) ? W_off[k * 256 + n] : W_attn[k * 128 + (n - 256)];
        g_bt_oa[t] = __float2half(v);
    }
    if (t < 384)
        g_bias_oa[t] = (t < 256) ? b_off[t] : b_attn[t - 256];

    const size_t n4 = (size_t)MROWS * 64;
    if (t < n4) {
        const float4 q = reinterpret_cast<const float4*>(query)[t];
        const float4 v = reinterpret_cast<const float4*>(value)[t];
        reinterpret_cast<uint2*>(g_query_h)[t] =
            make_uint2(pack_h2(q.x, q.y), pack_h2(q.z, q.w));
        reinterpret_cast<uint2*>(g_value_h)[t] =
            make_uint2(pack_h2(v.x, v.y), pack_h2(v.z, v.w));
    }
}

// ---------------------------------------------------------------------------
// zero border rows of padded head-major value buffer.
// grid (768, 2); 64 threads: head = tid>>3, 8B chunk = tid&7 (8 heads x 64B).
// ---------------------------------------------------------------------------
__global__ __launch_bounds__(64) void zero_border_kernel()
{
    const int cidx = blockIdx.x;
    const int b    = blockIdx.y;

    int W2, H2, pst, c;
    if      (cidx < 404) { W2 = 102; H2 = 102; pst = 0;     c = cidx;       }
    else if (cidx < 608) { W2 = 52;  H2 = 52;  pst = 10404; c = cidx - 404; }
    else if (cidx < 712) { W2 = 27;  H2 = 27;  pst = 13108; c = cidx - 608; }
    else                 { W2 = 15;  H2 = 15;  pst = 13837; c = cidx - 712; }

    int y, x;
    if      (c < W2)     { y = 0;      x = c;       }
    else if (c < 2 * W2) { y = H2 - 1; x = c - W2;  }
    else {
        const int r = c - 2 * W2;
        y = 1 + (r >> 1);
        x = (r & 1) ? (W2 - 1) : 0;
    }

    const int head = threadIdx.x >> 3;
    const int chunk = threadIdx.x & 7;
    uint2* row = reinterpret_cast<uint2*>(
        g_valp + ((size_t)((b * NHh + head) * PADB) + pst + y * W2 + x) * 32);
    row[chunk] = make_uint2(0u, 0u);
}

// ---------------------------------------------------------------------------
// Stage-1 fused GEMM:
//   blockIdx.x < 2 : valp(half, head-major padded) = value_h @ bt_val + b_val
//   blockIdx.x >= 2: offattn(f32)                  = query_h @ bt_oa  + bias_oa
// ---------------------------------------------------------------------------
#define STAGES 3
#define STAGE_BYTES (128 * 32 * 2 * 2)
#define GEMM_SMEM (STAGES * STAGE_BYTES)

__global__ __launch_bounds__(256, 2) void gemm_stage1_kernel(
    const __half* __restrict__ Aval, const __half* __restrict__ Btval,
    const float* __restrict__ bval,
    const __half* __restrict__ Aq, const __half* __restrict__ Btoa,
    const float* __restrict__ boa, float* __restrict__ Coa)
{
    extern __shared__ char smem[];
    constexpr int A_BYTES = 128 * 32 * 2;

    const bool padout = (blockIdx.x < 2);
    const __half* A   = padout ? Aval  : Aq;
    const __half* Bt  = padout ? Btval : Btoa;
    const float* bias = padout ? bval  : boa;
    const int bn = (padout ? blockIdx.x : (blockIdx.x - 2)) * 128;

    const int tid  = threadIdx.x;
    const int wid  = tid >> 5;
    const int lane = tid & 31;
    const int gid  = lane >> 2;
    const int tig  = lane & 3;
    const int warpM = wid >> 2;
    const int warpN = wid & 3;
    const int bm = blockIdx.y * 128;
    const int M = MROWS;

    float c[4][4][4];
    #pragma unroll
    for (int i = 0; i < 4; i++)
        #pragma unroll
        for (int j = 0; j < 4; j++)
            #pragma unroll
            for (int r = 0; r < 4; r++) c[i][j][r] = 0.f;

    const int K = 256, NT = 8;

    auto copy_tile = [&](int kt, char* stg) {
        const int k0 = kt * 32;
        __half* sA = (__half*)stg;
        __half* sB = (__half*)(stg + A_BYTES);
        #pragma unroll
        for (int i = 0; i < 2; i++) {
            const int o = tid * 2 + i;
            const int row = o >> 2, ch = o & 3;
            const int dst = row * 32 + ((((ch * 4) ^ (((row >> 1) & 3) * 4))) << 1);
            cp16(&sA[dst], A + (size_t)(bm + row) * K + k0 + ch * 8, bm + row < M);
            cp16(&sB[dst], Bt + (size_t)(bn + row) * K + k0 + ch * 8, true);
        }
    };

    copy_tile(0, smem);
    asm volatile("cp.async.commit_group;");
    copy_tile(1, smem + STAGE_BYTES);
    asm volatile("cp.async.commit_group;");

    const int sw = (gid >> 1) << 2;

    for (int it = 0; it < NT; it++) {
        if (it < NT - 1) asm volatile("cp.async.wait_group 1;");
        else             asm volatile("cp.async.wait_group 0;");
        __syncthreads();

        char* stg = smem + (it % STAGES) * STAGE_BYTES;
        const __half* sA = (const __half*)stg;
        const __half* sB = (const __half*)(stg + A_BYTES);

        #pragma unroll
        for (int ks = 0; ks < 2; ks++) {
            const int c0 = ks * 8;
            const int u0 = ((c0    ) ^ sw) + tig;
            const int u1 = ((c0 + 4) ^ sw) + tig;

            uint32_t a[4][4];
            #pragma unroll
            for (int mt = 0; mt < 4; mt++) {
                const int m0 = warpM * 64 + mt * 16 + gid;
                a[mt][0] = *(const uint32_t*)&sA[(m0    ) * 32 + (u0 << 1)];
                a[mt][1] = *(const uint32_t*)&sA[(m0 + 8) * 32 + (u0 << 1)];
                a[mt][2] = *(const uint32_t*)&sA[(m0    ) * 32 + (u1 << 1)];
                a[mt][3] = *(const uint32_t*)&sA[(m0 + 8) * 32 + (u1 << 1)];
            }
            uint32_t b[4][2];
            #pragma unroll
            for (int nt = 0; nt < 4; nt++) {
                const int n0 = warpN * 32 + nt * 8 + gid;
                b[nt][0] = *(const uint32_t*)&sB[n0 * 32 + (u0 << 1)];
                b[nt][1] = *(const uint32_t*)&sB[n0 * 32 + (u1 << 1)];
            }
            #pragma unroll
            for (int mt = 0; mt < 4; mt++)
                #pragma unroll
                for (int nt = 0; nt < 4; nt++) {
                    asm volatile(
                        "mma.sync.aligned.m16n8k16.row.col.f32.f16.f16.f32 "
                        "{%0,%1,%2,%3}, {%4,%5,%6,%7}, {%8,%9}, {%0,%1,%2,%3};"
                        : "+f"(c[mt][nt][0]), "+f"(c[mt][nt][1]),
                          "+f"(c[mt][nt][2]), "+f"(c[mt][nt][3])
                        : "r"(a[mt][0]), "r"(a[mt][1]), "r"(a[mt][2]), "r"(a[mt][3]),
                          "r"(b[nt][0]), "r"(b[nt][1]));
                }
        }
        if (it + 2 < NT) {
            copy_tile(it + 2, smem + ((it + 2) % STAGES) * STAGE_BYTES);
            asm volatile("cp.async.commit_group;");
        }
    }

    #pragma unroll
    for (int mt = 0; mt < 4; mt++) {
        const int r0 = bm + warpM * 64 + mt * 16 + gid;
        if (padout) {
            int bb0 = 0, pr0 = 0, bb1 = 0, pr1 = 0;
            if (r0 < MROWS)     pad_row_bh(r0, bb0, pr0);
            if (r0 + 8 < MROWS) pad_row_bh(r0 + 8, bb1, pr1);
            #pragma unroll
            for (int nt = 0; nt < 4; nt++) {
                const int cc = bn + warpN * 32 + nt * 8 + tig * 2;
                const int h = cc >> 5, col = cc & 31;
                const float bz0 = bval[cc], bz1 = bval[cc + 1];
                if (r0 < MROWS)
                    *reinterpret_cast<uint32_t*>(
                        g_valp + ((size_t)((bb0 * NHh + h) * PADB) + pr0) * 32 + col) =
                        pack_h2(c[mt][nt][0] + bz0, c[mt][nt][1] + bz1);
                if (r0 + 8 < MROWS)
                    *reinterpret_cast<uint32_t*>(
                        g_valp + ((size_t)((bb1 * NHh + h) * PADB) + pr1) * 32 + col) =
                        pack_h2(c[mt][nt][2] + bz0, c[mt][nt][3] + bz1);
            }
        } else {
            #pragma unroll
            for (int nt = 0; nt < 4; nt++) {
                const int cc = bn + warpN * 32 + nt * 8 + tig * 2;
                const float bz0 = bias[cc], bz1 = bias[cc + 1];
                if (r0 < MROWS) {
                    float2 v = make_float2(c[mt][nt][0] + bz0, c[mt][nt][1] + bz1);
                    *reinterpret_cast<float2*>(Coa + (size_t)r0 * 384 + cc) = v;
                }
                if (r0 + 8 < MROWS) {
                    float2 v = make_float2(c[mt][nt][2] + bz0, c[mt][nt][3] + bz1);
                    *reinterpret_cast<float2*>(Coa + (size_t)(r0 + 8) * 384 + cc) = v;
                }
            }
        }
    }
}

// ---------------------------------------------------------------------------
// Output GEMM: out = g_acc @ bt_out + b_out (fp32 out)
// ---------------------------------------------------------------------------
__global__ __launch_bounds__(256, 2) void gemm_out_kernel(
    const __half* __restrict__ A, const __half* __restrict__ Bt,
    const float* __restrict__ bias, float* __restrict__ C,
    int M, int N)
{
    extern __shared__ char smem[];
    constexpr int A_BYTES = 128 * 32 * 2;

    const int tid  = threadIdx.x;
    const int wid  = tid >> 5;
    const int lane = tid & 31;
    const int gid  = lane >> 2;
    const int tig  = lane & 3;
    const int warpM = wid >> 2;
    const int warpN = wid & 3;
    const int bm = blockIdx.y * 128;
    const int bn = blockIdx.x * 128;

    float c[4][4][4];
    #pragma unroll
    for (int i = 0; i < 4; i++)
        #pragma unroll
        for (int j = 0; j < 4; j++)
            #pragma unroll
            for (int r = 0; r < 4; r++) c[i][j][r] = 0.f;

    const int K = 256, NT = 8;

    auto copy_tile = [&](int kt, char* stg) {
        const int k0 = kt * 32;
        __half* sA = (__half*)stg;
        __half* sB = (__half*)(stg + A_BYTES);
        #pragma unroll
        for (int i = 0; i < 2; i++) {
            const int o = tid * 2 + i;
            const int row = o >> 2, ch = o & 3;
            const int dst = row * 32 + ((((ch * 4) ^ (((row >> 1) & 3) * 4))) << 1);
            cp16(&sA[dst], A + (size_t)(bm + row) * K + k0 + ch * 8, bm + row < M);
            cp16(&sB[dst], Bt + (size_t)(bn + row) * K + k0 + ch * 8, true);
        }
    };

    copy_tile(0, smem);
    asm volatile("cp.async.commit_group;");
    copy_tile(1, smem + STAGE_BYTES);
    asm volatile("cp.async.commit_group;");

    const int sw = (gid >> 1) << 2;

    for (int it = 0; it < NT; it++) {
        if (it < NT - 1) asm volatile("cp.async.wait_group 1;");
        else             asm volatile("cp.async.wait_group 0;");
        __syncthreads();

        char* stg = smem + (it % STAGES) * STAGE_BYTES;
        const __half* sA = (const __half*)stg;
        const __half* sB = (const __half*)(stg + A_BYTES);

        #pragma unroll
        for (int ks = 0; ks < 2; ks++) {
            const int c0 = ks * 8;
            const int u0 = ((c0    ) ^ sw) + tig;
            const int u1 = ((c0 + 4) ^ sw) + tig;

            uint32_t a[4][4];
            #pragma unroll
            for (int mt = 0; mt < 4; mt++) {
                const int m0 = warpM * 64 + mt * 16 + gid;
                a[mt][0] = *(const uint32_t*)&sA[(m0    ) * 32 + (u0 << 1)];
                a[mt][1] = *(const uint32_t*)&sA[(m0 + 8) * 32 + (u0 << 1)];
                a[mt][2] = *(const uint32_t*)&sA[(m0    ) * 32 + (u1 << 1)];
                a[mt][3] = *(const uint32_t*)&sA[(m0 + 8) * 32 + (u1 << 1)];
            }
            uint32_t b[4][2];
            #pragma unroll
            for (int nt = 0; nt < 4; nt++) {
                const int n0 = warpN * 32 + nt * 8 + gid;
                b[nt][0] = *(const uint32_t*)&sB[n0 * 32 + (u0 << 1)];
                b[nt][1] = *(const uint32_t*)&sB[n0 * 32 + (u1 << 1)];
            }
            #pragma unroll
            for (int mt = 0; mt < 4; mt++)
                #pragma unroll
                for (int nt = 0; nt < 4; nt++) {
                    asm volatile(
                        "mma.sync.aligned.m16n8k16.row.col.f32.f16.f16.f32 "
                        "{%0,%1,%2,%3}, {%4,%5,%6,%7}, {%8,%9}, {%0,%1,%2,%3};"
                        : "+f"(c[mt][nt][0]), "+f"(c[mt][nt][1]),
                          "+f"(c[mt][nt][2]), "+f"(c[mt][nt][3])
                        : "r"(a[mt][0]), "r"(a[mt][1]), "r"(a[mt][2]), "r"(a[mt][3]),
                          "r"(b[nt][0]), "r"(b[nt][1]));
                }
        }
        if (it + 2 < NT) {
            copy_tile(it + 2, smem + ((it + 2) % STAGES) * STAGE_BYTES);
            asm volatile("cp.async.commit_group;");
        }
    }

    #pragma unroll
    for (int mt = 0; mt < 4; mt++) {
        const int r0 = bm + warpM * 64 + mt * 16 + gid;
        #pragma unroll
        for (int nt = 0; nt < 4; nt++) {
            const int cc = bn + warpN * 32 + nt * 8 + tig * 2;
            const float bz0 = bias[cc], bz1 = bias[cc + 1];
            if (r0 < M) {
                float2 v = make_float2(c[mt][nt][0] + bz0, c[mt][nt][1] + bz1);
                *reinterpret_cast<float2*>(C + (size_t)r0 * N + cc) = v;
            }
            if (r0 + 8 < M) {
                float2 v = make_float2(c[mt][nt][2] + bz0, c[mt][nt][3] + bz1);
                *reinterpret_cast<float2*>(C + (size_t)(r0 + 8) * N + cc) = v;
            }
        }
    }
}

// ---------------------------------------------------------------------------
// Sampling v7: HEAD-MAJOR padded half value (64B rows). One warp per
// (b, q, head-half). 8-lane group per head; lane = (x-slot, channel-oct):
// one LDG.128 per y-corner covers BOTH x-corners (adjacent 64B rows = one
// 128B line). Per-lane 8-channel f32x2 accumulators; shfl-add merges the two
// x-slots at the end. Border-padded rows for y; 2 masks for x. Deferred
// softmax normalization.
// ---------------------------------------------------------------------------
__global__ __launch_bounds__(128, 8) void sample_kernel(
    const float* __restrict__ refp,    // (B, L, NL, 2)
    const __half* __restrict__ valp,   // (B, NH, PADB, 32) half
    const float* __restrict__ offattn, // (B, L, 384)
    __half* __restrict__ out_acc)      // (B, L, 256) half
{
    const int g = blockIdx.x * 4 + (threadIdx.x >> 5);
    if (g >= Bb * LQ * 2) return;
    const int bq   = g >> 1;
    const int half = g & 1;
    const int lane = threadIdx.x & 31;
    const int hg   = lane >> 3;          // head subgroup 0..3
    const int k    = lane & 7;           // 0..7: x-slot = k>>2, channel-oct = k&3
    const int xs   = (k >> 2) & 1;
    const int b    = bq / LQ;
    const int h    = half * 4 + hg;

    // softmax over this head's 16 logits (redundant per lane)
    const float4* at4 = reinterpret_cast<const float4*>(
        offattn + (size_t)bq * 384 + 256 + h * 16);
    float lg[16];
    {
        float4 t0 = at4[0], t1 = at4[1], t2 = at4[2], t3 = at4[3];
        lg[0]=t0.x; lg[1]=t0.y; lg[2]=t0.z; lg[3]=t0.w;
        lg[4]=t1.x; lg[5]=t1.y; lg[6]=t1.z; lg[7]=t1.w;
        lg[8]=t2.x; lg[9]=t2.y; lg[10]=t2.z; lg[11]=t2.w;
        lg[12]=t3.x; lg[13]=t3.y; lg[14]=t3.z; lg[15]=t3.w;
    }
    float mxv = lg[0];
    #pragma unroll
    for (int j = 1; j < 16; j++) mxv = fmaxf(mxv, lg[j]);
    float s = 0.f;
    #pragma unroll
    for (int j = 0; j < 16; j++) { lg[j] = __expf(lg[j] - mxv); s += lg[j]; }
    const float inv = 1.0f / s;

    const float* of = offattn + (size_t)bq * 384 + h * 32;
    const float* rp = refp + (size_t)bq * 8;
    unsigned long long acc[4] = {0ull, 0ull, 0ull, 0ull};   // 8 channels

    const int lWc[4]  = {100, 50, 25, 13};
    const int lHc[4]  = {100, 50, 25, 13};
    const int lPst[4] = {0, 10404, 13108, 13837};
    const int lW2[4]  = {102, 52, 27, 15};

    #pragma unroll
    for (int l = 0; l < 4; l++) {
        const int W = lWc[l], H = lHc[l], W2 = lW2[l];
        // per-lane base: head-major + lane's 16B chunk (slot+channels)
        const __half* vb = valp
            + ((size_t)((b * NHh + h) * PADB) + lPst[l]) * 32 + k * 8;
        const float rx = rp[l * 2 + 0] * (float)W - 0.5f;
        const float ry = rp[l * 2 + 1] * (float)H - 0.5f;
        const float4 o01 = reinterpret_cast<const float4*>(of + l * 8)[0];
        const float4 o23 = reinterpret_cast<const float4*>(of + l * 8)[1];
        const float ox[4] = {o01.x, o01.z, o23.x, o23.z};
        const float oy[4] = {o01.y, o01.w, o23.y, o23.w};

        #pragma unroll
        for (int p = 0; p < 4; p++) {
            const float x = rx + ox[p];
            const float y = ry + oy[p];
            const float wgt = lg[l * 4 + p];

            const int x0 = __float2int_rd(x);
            const int y0 = __float2int_rd(y);
            const float wx1 = x - (float)x0, wy1 = y - (float)y0;
            const float wx0 = 1.f - wx1, wy0 = 1.f - wy1;

            const int px0 = x0 + 1;                 // padded col of left corner
            const int bx  = min(max(px0, 0), W);    // pair [bx, bx+1] in bounds
            const int yp0 = min(max(y0 + 1, 0), H + 1);
            const int yp1 = min(max(y0 + 2, 0), H + 1);

            // x masks: only needed when pair base was clamped
            const float wx0m = (px0 > W) ? 0.f : wx0;
            const float wx1m = (px0 < 0) ? 0.f : wx1;
            const float wsel = xs ? wx1m : wx0m;

            const float wA = wgt * wy0 * wsel;
            const float wB = wgt * wy1 * wsel;
            const unsigned long long uA = bcast2(wA);
            const unsigned long long uB = bcast2(wB);

            const uint4 v0 = *reinterpret_cast<const uint4*>(
                vb + (size_t)(yp0 * W2 + bx) * 32);
            const uint4 v1 = *reinterpret_cast<const uint4*>(
                vb + (size_t)(yp1 * W2 + bx) * 32);

            ffma2(acc[0], h2f2(v0.x), uA);
            ffma2(acc[1], h2f2(v0.y), uA);
            ffma2(acc[2], h2f2(v0.z), uA);
            ffma2(acc[3], h2f2(v0.w), uA);
            ffma2(acc[0], h2f2(v1.x), uB);
            ffma2(acc[1], h2f2(v1.y), uB);
            ffma2(acc[2], h2f2(v1.z), uB);
            ffma2(acc[3], h2f2(v1.w), uB);
        }
    }

    // deferred softmax normalization
    const unsigned long long inv2 = bcast2(inv);
    #pragma unroll
    for (int j = 0; j < 4; j++) fmul2(acc[j], inv2);

    // merge the two x-slots (lane ^ 4 within the 8-lane group)
    #pragma unroll
    for (int j = 0; j < 4; j++) {
        const unsigned long long other =
            __shfl_xor_sync(0xffffffffu, acc[j], 4);
        fadd2(acc[j], other);
    }

    if (!xs) {
        uint4 outv;
        uint32_t a0, a1;
        asm("mov.b64 {%0, %1}, %2;" : "=r"(a0), "=r"(a1) : "l"(acc[0]));
        outv.x = pack_h2(__uint_as_float(a0), __uint_as_float(a1));
        asm("mov.b64 {%0, %1}, %2;" : "=r"(a0), "=r"(a1) : "l"(acc[1]));
        outv.y = pack_h2(__uint_as_float(a0), __uint_as_float(a1));
        asm("mov.b64 {%0, %1}, %2;" : "=r"(a0), "=r"(a1) : "l"(acc[2]));
        outv.z = pack_h2(__uint_as_float(a0), __uint_as_float(a1));
        asm("mov.b64 {%0, %1}, %2;" : "=r"(a0), "=r"(a1) : "l"(acc[3]));
        outv.w = pack_h2(__uint_as_float(a0), __uint_as_float(a1));
        *reinterpret_cast<uint4*>(
            out_acc + (size_t)bq * 256 + h * 32 + (k & 3) * 8) = outv;
    }
}

// ---------------------------------------------------------------------------
// Launch
// ---------------------------------------------------------------------------
extern "C" void kernel_launch(void* const* d_in, const int* in_sizes, int n_in,
                              void* d_out, int out_size)
{
    const float* query  = (const float*)d_in[0];
    const float* refp   = (const float*)d_in[1];
    const float* value  = (const float*)d_in[2];
    const float* W_val  = (const float*)d_in[3];
    const float* b_val  = (const float*)d_in[4];
    const float* W_off  = (const float*)d_in[5];
    const float* b_off  = (const float*)d_in[6];
    const float* W_attn = (const float*)d_in[7];
    const float* b_attn = (const float*)d_in[8];
    const float* W_out  = (const float*)d_in[9];
    const float* b_out  = (const float*)d_in[10];
    float* out = (float*)d_out;

    float  *poa, *pbias_oa;
    __half *pvalp, *pacc, *pqh, *pvh, *pbtv, *pbtoa, *pbto;
    cudaGetSymbolAddress((void**)&pvalp,    g_valp);
    cudaGetSymbolAddress((void**)&poa,      g_offattn);
    cudaGetSymbolAddress((void**)&pacc,     g_acc);
    cudaGetSymbolAddress((void**)&pqh,      g_query_h);
    cudaGetSymbolAddress((void**)&pvh,      g_value_h);
    cudaGetSymbolAddress((void**)&pbtv,     g_bt_val);
    cudaGetSymbolAddress((void**)&pbtoa,    g_bt_oa);
    cudaGetSymbolAddress((void**)&pbto,     g_bt_out);
    cudaGetSymbolAddress((void**)&pbias_oa, g_bias_oa);

    cudaFuncSetAttribute(gemm_stage1_kernel,
                         cudaFuncAttributeMaxDynamicSharedMemorySize, GEMM_SMEM);
    cudaFuncSetAttribute(gemm_out_kernel,
                         cudaFuncAttributeMaxDynamicSharedMemorySize, GEMM_SMEM);

    const dim3 blk(256);
    const int  gy = (MROWS + 127) / 128;
    const int  n4 = MROWS * 64;

    // 0a. weights -> half^T, bias fuse, query/value -> half
    prep_convert_kernel<<<(n4 + 255) / 256, blk>>>(
        W_val, W_off, W_attn, W_out, b_off, b_attn, query, value);
    // 0b. zero padded-value border rows (head-major)
    zero_border_kernel<<<dim3(768, 2), 64>>>();
    // 1+2+3. fused stage-1 GEMMs (value proj -> head-major padded half;
    //        offsets+attn -> f32)
    gemm_stage1_kernel<<<dim3(5, gy), blk, GEMM_SMEM>>>(
        pvh, pbtv, b_val, pqh, pbtoa, pbias_oa, poa);
    // 4. softmax + deformable bilinear sampling -> g_acc (half)
    sample_kernel<<<(MROWS * 2 + 3) / 4, dim3(128)>>>(refp, pvalp, poa, pacc);
    // 5. out = g_acc @ W_out + b_out
    gemm_out_kernel<<<dim3(2, gy), blk, GEMM_SMEM>>>(
        pacc, pbto, b_out, out, MROWS, 256);
}

// round 16
// speedup vs baseline: 5.1551x; 1.0961x over previous
#include <cuda_runtime.h>
#include <cuda_bf16.h>
#include <cuda_fp16.h>
#include <cstdint>
#include <cstddef>

// Problem constants
#define NHh 8
#define Dm  256
#define Bb  2
#define Ss  13294          // 100*100 + 50*50 + 25*25 + 13*13
#define LQ  13294
#define MROWS (Bb * LQ)    // 26588
#define PADB 14062         // padded rows/batch: 102*102 + 52*52 + 27*27 + 15*15

// Scratch (allocation-free: __device__ globals)
// g_valp layout: (B, NH, PADB, 32) half — HEAD-MAJOR, 64B rows
__device__ __half g_valp   [Bb * NHh * PADB * 32];
__device__ float  g_offattn[MROWS * 384];       // fused offsets(256) + attn(128)
__device__ __half g_acc    [MROWS * Dm];        // sampled output (half)
__device__ __half g_query_h[MROWS * Dm];        // query -> half
__device__ __half g_value_h[MROWS * Dm];        // value -> half
__device__ __half g_bt_val [256 * 256];         // W_val^T  half [n][k]
__device__ __half g_bt_oa  [384 * 256];         // [W_off|W_attn]^T half [n][k]
__device__ __half g_bt_out [256 * 256];         // W_out^T  half [n][k]
__device__ float  g_bias_oa[384];               // fused b_off|b_attn

__device__ __forceinline__ uint32_t pack_h2(float lo, float hi) {
    uint32_t r;
    asm("cvt.rn.f16x2.f32 %0, %1, %2;" : "=r"(r) : "f"(hi), "f"(lo));
    return r;
}

__device__ __forceinline__ void cp16(void* s, const void* g, bool p) {
    uint32_t sa = (uint32_t)__cvta_generic_to_shared(s);
    const int sz = p ? 16 : 0;
    asm volatile("cp.async.ca.shared.global [%0], [%1], 16, %2;"
                 :: "r"(sa), "l"(g), "r"(sz));
}

// packed f32x2 helpers
__device__ __forceinline__ void fmul2(unsigned long long& acc,
                                      unsigned long long w) {
    asm("mul.rn.f32x2 %0, %0, %1;" : "+l"(acc) : "l"(w));
}
__device__ __forceinline__ void fadd2(unsigned long long& acc,
                                      unsigned long long v) {
    asm("add.rn.f32x2 %0, %0, %1;" : "+l"(acc) : "l"(v));
}
__device__ __forceinline__ unsigned long long bcast2(float w) {
    unsigned long long r;
    const uint32_t u = __float_as_uint(w);
    asm("mov.b64 %0, {%1, %1};" : "=l"(r) : "r"(u));
    return r;
}
// half2 bits -> packed f32x2
__device__ __forceinline__ unsigned long long h2f2(uint32_t h) {
    const __half2 hh = *reinterpret_cast<const __half2*>(&h);
    const float2 f = __half22float2(hh);
    unsigned long long r;
    asm("mov.b64 %0, {%1, %2};" : "=l"(r) : "f"(f.x), "f"(f.y));
    return r;
}
// packed half2 fma
__device__ __forceinline__ uint32_t hfma2(uint32_t a, uint32_t b, uint32_t c) {
    uint32_t d;
    asm("fma.rn.f16x2 %0, %1, %2, %3;" : "=r"(d) : "r"(a), "r"(b), "r"(c));
    return d;
}

// s-row -> (batch, padded row)
__device__ __forceinline__ void pad_row_bh(int r, int& bb, int& pr) {
    bb = 0;
    if (r >= Ss) { bb = 1; r -= Ss; }
    if (r < 10000)      { int y = r / 100;
                          pr = (y + 1) * 102 + (r - y * 100) + 1; }
    else if (r < 12500) { int t = r - 10000; int y = t / 50;
                          pr = 10404 + (y + 1) * 52 + (t - y * 50) + 1; }
    else if (r < 13125) { int t = r - 12500; int y = t / 25;
                          pr = 13108 + (y + 1) * 27 + (t - y * 25) + 1; }
    else                { int t = r - 13125; int y = t / 13;
                          pr = 13837 + (y + 1) * 15 + (t - y * 13) + 1; }
}

// ---------------------------------------------------------------------------
// prep+convert: weights -> half^T; biases fused; query/value -> half
// ---------------------------------------------------------------------------
__global__ __launch_bounds__(256) void prep_convert_kernel(
    const float* __restrict__ W_val, const float* __restrict__ W_off,
    const float* __restrict__ W_attn, const float* __restrict__ W_out,
    const float* __restrict__ b_off, const float* __restrict__ b_attn,
    const float* __restrict__ query, const float* __restrict__ value)
{
    const size_t t = (size_t)blockIdx.x * 256 + threadIdx.x;
    if (t < 65536) {
        const int n = (int)t >> 8, k = (int)t & 255;
        g_bt_val[t] = __float2half(W_val[k * 256 + n]);
        g_bt_out[t] = __float2half(W_out[k * 256 + n]);
    }
    if (t < 98304) {
        const int n = (int)t >> 8, k = (int)t & 255;
        const float v = (n < 256) ? W_off[k * 256 + n] : W_attn[k * 128 + (n - 256)];
        g_bt_oa[t] = __float2half(v);
    }
    if (t < 384)
        g_bias_oa[t] = (t < 256) ? b_off[t] : b_attn[t - 256];

    const size_t n4 = (size_t)MROWS * 64;
    if (t < n4) {
        const float4 q = reinterpret_cast<const float4*>(query)[t];
        const float4 v = reinterpret_cast<const float4*>(value)[t];
        reinterpret_cast<uint2*>(g_query_h)[t] =
            make_uint2(pack_h2(q.x, q.y), pack_h2(q.z, q.w));
        reinterpret_cast<uint2*>(g_value_h)[t] =
            make_uint2(pack_h2(v.x, v.y), pack_h2(v.z, v.w));
    }
}

// ---------------------------------------------------------------------------
// zero border rows of padded head-major value buffer.
// grid (768, 2); 64 threads: head = tid>>3, 8B chunk = tid&7.
// ---------------------------------------------------------------------------
__global__ __launch_bounds__(64) void zero_border_kernel()
{
    const int cidx = blockIdx.x;
    const int b    = blockIdx.y;

    int W2, H2, pst, c;
    if      (cidx < 404) { W2 = 102; H2 = 102; pst = 0;     c = cidx;       }
    else if (cidx < 608) { W2 = 52;  H2 = 52;  pst = 10404; c = cidx - 404; }
    else if (cidx < 712) { W2 = 27;  H2 = 27;  pst = 13108; c = cidx - 608; }
    else                 { W2 = 15;  H2 = 15;  pst = 13837; c = cidx - 712; }

    int y, x;
    if      (c < W2)     { y = 0;      x = c;       }
    else if (c < 2 * W2) { y = H2 - 1; x = c - W2;  }
    else {
        const int r = c - 2 * W2;
        y = 1 + (r >> 1);
        x = (r & 1) ? (W2 - 1) : 0;
    }

    const int head = threadIdx.x >> 3;
    const int chunk = threadIdx.x & 7;
    uint2* row = reinterpret_cast<uint2*>(
        g_valp + ((size_t)((b * NHh + head) * PADB) + pst + y * W2 + x) * 32);
    row[chunk] = make_uint2(0u, 0u);
}

// ---------------------------------------------------------------------------
// Stage-1 fused GEMM:
//   blockIdx.x < 2 : valp(half, head-major padded) = value_h @ bt_val + b_val
//   blockIdx.x >= 2: offattn(f32)                  = query_h @ bt_oa  + bias_oa
// ---------------------------------------------------------------------------
#define STAGES 3
#define STAGE_BYTES (128 * 32 * 2 * 2)
#define GEMM_SMEM (STAGES * STAGE_BYTES)

__global__ __launch_bounds__(256, 2) void gemm_stage1_kernel(
    const __half* __restrict__ Aval, const __half* __restrict__ Btval,
    const float* __restrict__ bval,
    const __half* __restrict__ Aq, const __half* __restrict__ Btoa,
    const float* __restrict__ boa, float* __restrict__ Coa)
{
    extern __shared__ char smem[];
    constexpr int A_BYTES = 128 * 32 * 2;

    const bool padout = (blockIdx.x < 2);
    const __half* A   = padout ? Aval  : Aq;
    const __half* Bt  = padout ? Btval : Btoa;
    const float* bias = padout ? bval  : boa;
    const int bn = (padout ? blockIdx.x : (blockIdx.x - 2)) * 128;

    const int tid  = threadIdx.x;
    const int wid  = tid >> 5;
    const int lane = tid & 31;
    const int gid  = lane >> 2;
    const int tig  = lane & 3;
    const int warpM = wid >> 2;
    const int warpN = wid & 3;
    const int bm = blockIdx.y * 128;
    const int M = MROWS;

    float c[4][4][4];
    #pragma unroll
    for (int i = 0; i < 4; i++)
        #pragma unroll
        for (int j = 0; j < 4; j++)
            #pragma unroll
            for (int r = 0; r < 4; r++) c[i][j][r] = 0.f;

    const int K = 256, NT = 8;

    auto copy_tile = [&](int kt, char* stg) {
        const int k0 = kt * 32;
        __half* sA = (__half*)stg;
        __half* sB = (__half*)(stg + A_BYTES);
        #pragma unroll
        for (int i = 0; i < 2; i++) {
            const int o = tid * 2 + i;
            const int row = o >> 2, ch = o & 3;
            const int dst = row * 32 + ((((ch * 4) ^ (((row >> 1) & 3) * 4))) << 1);
            cp16(&sA[dst], A + (size_t)(bm + row) * K + k0 + ch * 8, bm + row < M);
            cp16(&sB[dst], Bt + (size_t)(bn + row) * K + k0 + ch * 8, true);
        }
    };

    copy_tile(0, smem);
    asm volatile("cp.async.commit_group;");
    copy_tile(1, smem + STAGE_BYTES);
    asm volatile("cp.async.commit_group;");

    const int sw = (gid >> 1) << 2;

    for (int it = 0; it < NT; it++) {
        if (it < NT - 1) asm volatile("cp.async.wait_group 1;");
        else             asm volatile("cp.async.wait_group 0;");
        __syncthreads();

        char* stg = smem + (it % STAGES) * STAGE_BYTES;
        const __half* sA = (const __half*)stg;
        const __half* sB = (const __half*)(stg + A_BYTES);

        #pragma unroll
        for (int ks = 0; ks < 2; ks++) {
            const int c0 = ks * 8;
            const int u0 = ((c0    ) ^ sw) + tig;
            const int u1 = ((c0 + 4) ^ sw) + tig;

            uint32_t a[4][4];
            #pragma unroll
            for (int mt = 0; mt < 4; mt++) {
                const int m0 = warpM * 64 + mt * 16 + gid;
                a[mt][0] = *(const uint32_t*)&sA[(m0    ) * 32 + (u0 << 1)];
                a[mt][1] = *(const uint32_t*)&sA[(m0 + 8) * 32 + (u0 << 1)];
                a[mt][2] = *(const uint32_t*)&sA[(m0    ) * 32 + (u1 << 1)];
                a[mt][3] = *(const uint32_t*)&sA[(m0 + 8) * 32 + (u1 << 1)];
            }
            uint32_t b[4][2];
            #pragma unroll
            for (int nt = 0; nt < 4; nt++) {
                const int n0 = warpN * 32 + nt * 8 + gid;
                b[nt][0] = *(const uint32_t*)&sB[n0 * 32 + (u0 << 1)];
                b[nt][1] = *(const uint32_t*)&sB[n0 * 32 + (u1 << 1)];
            }
            #pragma unroll
            for (int mt = 0; mt < 4; mt++)
                #pragma unroll
                for (int nt = 0; nt < 4; nt++) {
                    asm volatile(
                        "mma.sync.aligned.m16n8k16.row.col.f32.f16.f16.f32 "
                        "{%0,%1,%2,%3}, {%4,%5,%6,%7}, {%8,%9}, {%0,%1,%2,%3};"
                        : "+f"(c[mt][nt][0]), "+f"(c[mt][nt][1]),
                          "+f"(c[mt][nt][2]), "+f"(c[mt][nt][3])
                        : "r"(a[mt][0]), "r"(a[mt][1]), "r"(a[mt][2]), "r"(a[mt][3]),
                          "r"(b[nt][0]), "r"(b[nt][1]));
                }
        }
        if (it + 2 < NT) {
            copy_tile(it + 2, smem + ((it + 2) % STAGES) * STAGE_BYTES);
            asm volatile("cp.async.commit_group;");
        }
    }

    #pragma unroll
    for (int mt = 0; mt < 4; mt++) {
        const int r0 = bm + warpM * 64 + mt * 16 + gid;
        if (padout) {
            int bb0 = 0, pr0 = 0, bb1 = 0, pr1 = 0;
            if (r0 < MROWS)     pad_row_bh(r0, bb0, pr0);
            if (r0 + 8 < MROWS) pad_row_bh(r0 + 8, bb1, pr1);
            #pragma unroll
            for (int nt = 0; nt < 4; nt++) {
                const int cc = bn + warpN * 32 + nt * 8 + tig * 2;
                const int h = cc >> 5, col = cc & 31;
                const float bz0 = bval[cc], bz1 = bval[cc + 1];
                if (r0 < MROWS)
                    *reinterpret_cast<uint32_t*>(
                        g_valp + ((size_t)((bb0 * NHh + h) * PADB) + pr0) * 32 + col) =
                        pack_h2(c[mt][nt][0] + bz0, c[mt][nt][1] + bz1);
                if (r0 + 8 < MROWS)
                    *reinterpret_cast<uint32_t*>(
                        g_valp + ((size_t)((bb1 * NHh + h) * PADB) + pr1) * 32 + col) =
                        pack_h2(c[mt][nt][2] + bz0, c[mt][nt][3] + bz1);
            }
        } else {
            #pragma unroll
            for (int nt = 0; nt < 4; nt++) {
                const int cc = bn + warpN * 32 + nt * 8 + tig * 2;
                const float bz0 = bias[cc], bz1 = bias[cc + 1];
                if (r0 < MROWS) {
                    float2 v = make_float2(c[mt][nt][0] + bz0, c[mt][nt][1] + bz1);
                    *reinterpret_cast<float2*>(Coa + (size_t)r0 * 384 + cc) = v;
                }
                if (r0 + 8 < MROWS) {
                    float2 v = make_float2(c[mt][nt][2] + bz0, c[mt][nt][3] + bz1);
                    *reinterpret_cast<float2*>(Coa + (size_t)(r0 + 8) * 384 + cc) = v;
                }
            }
        }
    }
}

// ---------------------------------------------------------------------------
// Output GEMM: out = g_acc @ bt_out + b_out (fp32 out)
// ---------------------------------------------------------------------------
__global__ __launch_bounds__(256, 2) void gemm_out_kernel(
    const __half* __restrict__ A, const __half* __restrict__ Bt,
    const float* __restrict__ bias, float* __restrict__ C,
    int M, int N)
{
    extern __shared__ char smem[];
    constexpr int A_BYTES = 128 * 32 * 2;

    const int tid  = threadIdx.x;
    const int wid  = tid >> 5;
    const int lane = tid & 31;
    const int gid  = lane >> 2;
    const int tig  = lane & 3;
    const int warpM = wid >> 2;
    const int warpN = wid & 3;
    const int bm = blockIdx.y * 128;
    const int bn = blockIdx.x * 128;

    float c[4][4][4];
    #pragma unroll
    for (int i = 0; i < 4; i++)
        #pragma unroll
        for (int j = 0; j < 4; j++)
            #pragma unroll
            for (int r = 0; r < 4; r++) c[i][j][r] = 0.f;

    const int K = 256, NT = 8;

    auto copy_tile = [&](int kt, char* stg) {
        const int k0 = kt * 32;
        __half* sA = (__half*)stg;
        __half* sB = (__half*)(stg + A_BYTES);
        #pragma unroll
        for (int i = 0; i < 2; i++) {
            const int o = tid * 2 + i;
            const int row = o >> 2, ch = o & 3;
            const int dst = row * 32 + ((((ch * 4) ^ (((row >> 1) & 3) * 4))) << 1);
            cp16(&sA[dst], A + (size_t)(bm + row) * K + k0 + ch * 8, bm + row < M);
            cp16(&sB[dst], Bt + (size_t)(bn + row) * K + k0 + ch * 8, true);
        }
    };

    copy_tile(0, smem);
    asm volatile("cp.async.commit_group;");
    copy_tile(1, smem + STAGE_BYTES);
    asm volatile("cp.async.commit_group;");

    const int sw = (gid >> 1) << 2;

    for (int it = 0; it < NT; it++) {
        if (it < NT - 1) asm volatile("cp.async.wait_group 1;");
        else             asm volatile("cp.async.wait_group 0;");
        __syncthreads();

        char* stg = smem + (it % STAGES) * STAGE_BYTES;
        const __half* sA = (const __half*)stg;
        const __half* sB = (const __half*)(stg + A_BYTES);

        #pragma unroll
        for (int ks = 0; ks < 2; ks++) {
            const int c0 = ks * 8;
            const int u0 = ((c0    ) ^ sw) + tig;
            const int u1 = ((c0 + 4) ^ sw) + tig;

            uint32_t a[4][4];
            #pragma unroll
            for (int mt = 0; mt < 4; mt++) {
                const int m0 = warpM * 64 + mt * 16 + gid;
                a[mt][0] = *(const uint32_t*)&sA[(m0    ) * 32 + (u0 << 1)];
                a[mt][1] = *(const uint32_t*)&sA[(m0 + 8) * 32 + (u0 << 1)];
                a[mt][2] = *(const uint32_t*)&sA[(m0    ) * 32 + (u1 << 1)];
                a[mt][3] = *(const uint32_t*)&sA[(m0 + 8) * 32 + (u1 << 1)];
            }
            uint32_t b[4][2];
            #pragma unroll
            for (int nt = 0; nt < 4; nt++) {
                const int n0 = warpN * 32 + nt * 8 + gid;
                b[nt][0] = *(const uint32_t*)&sB[n0 * 32 + (u0 << 1)];
                b[nt][1] = *(const uint32_t*)&sB[n0 * 32 + (u1 << 1)];
            }
            #pragma unroll
            for (int mt = 0; mt < 4; mt++)
                #pragma unroll
                for (int nt = 0; nt < 4; nt++) {
                    asm volatile(
                        "mma.sync.aligned.m16n8k16.row.col.f32.f16.f16.f32 "
                        "{%0,%1,%2,%3}, {%4,%5,%6,%7}, {%8,%9}, {%0,%1,%2,%3};"
                        : "+f"(c[mt][nt][0]), "+f"(c[mt][nt][1]),
                          "+f"(c[mt][nt][2]), "+f"(c[mt][nt][3])
                        : "r"(a[mt][0]), "r"(a[mt][1]), "r"(a[mt][2]), "r"(a[mt][3]),
                          "r"(b[nt][0]), "r"(b[nt][1]));
                }
        }
        if (it + 2 < NT) {
            copy_tile(it + 2, smem + ((it + 2) % STAGES) * STAGE_BYTES);
            asm volatile("cp.async.commit_group;");
        }
    }

    #pragma unroll
    for (int mt = 0; mt < 4; mt++) {
        const int r0 = bm + warpM * 64 + mt * 16 + gid;
        #pragma unroll
        for (int nt = 0; nt < 4; nt++) {
            const int cc = bn + warpN * 32 + nt * 8 + tig * 2;
            const float bz0 = bias[cc], bz1 = bias[cc + 1];
            if (r0 < M) {
                float2 v = make_float2(c[mt][nt][0] + bz0, c[mt][nt][1] + bz1);
                *reinterpret_cast<float2*>(C + (size_t)r0 * N + cc) = v;
            }
            if (r0 + 8 < M) {
                float2 v = make_float2(c[mt][nt][2] + bz0, c[mt][nt][3] + bz1);
                *reinterpret_cast<float2*>(C + (size_t)(r0 + 8) * N + cc) = v;
            }
        }
    }
}

// ---------------------------------------------------------------------------
// Sampling v8: HEAD-MAJOR padded half value. One warp per (b, q, head-half);
// 8-lane group per head, lane = (x-slot, channel-oct). One LDG.128 per
// y-corner covers both x-corners. NEW: per-level half2 (HFMA2) accumulation
// with half2-broadcast weights — F2F converts drop from 16/sample to
// 8/level; softmax max-subtraction removed (logits are O(1), exp-safe,
// normalization deferred so result is mathematically identical).
// ---------------------------------------------------------------------------
__global__ __launch_bounds__(128, 8) void sample_kernel(
    const float* __restrict__ refp,    // (B, L, NL, 2)
    const __half* __restrict__ valp,   // (B, NH, PADB, 32) half
    const float* __restrict__ offattn, // (B, L, 384)
    __half* __restrict__ out_acc)      // (B, L, 256) half
{
    const int g = blockIdx.x * 4 + (threadIdx.x >> 5);
    if (g >= Bb * LQ * 2) return;
    const int bq   = g >> 1;
    const int half = g & 1;
    const int lane = threadIdx.x & 31;
    const int hg   = lane >> 3;          // head subgroup 0..3
    const int k    = lane & 7;           // x-slot = k>>2, channel-oct = k&3
    const int xs   = (k >> 2) & 1;
    const int b    = bq / LQ;
    const int h    = half * 4 + hg;

    // exp(logits) without max-subtraction (safe: |logit| ~ O(1));
    // normalization deferred to the end.
    const float4* at4 = reinterpret_cast<const float4*>(
        offattn + (size_t)bq * 384 + 256 + h * 16);
    float lg[16];
    {
        float4 t0 = at4[0], t1 = at4[1], t2 = at4[2], t3 = at4[3];
        lg[0]=t0.x; lg[1]=t0.y; lg[2]=t0.z; lg[3]=t0.w;
        lg[4]=t1.x; lg[5]=t1.y; lg[6]=t1.z; lg[7]=t1.w;
        lg[8]=t2.x; lg[9]=t2.y; lg[10]=t2.z; lg[11]=t2.w;
        lg[12]=t3.x; lg[13]=t3.y; lg[14]=t3.z; lg[15]=t3.w;
    }
    float s = 0.f;
    #pragma unroll
    for (int j = 0; j < 16; j++) { lg[j] = __expf(lg[j]); s += lg[j]; }
    const float inv = 1.0f / s;

    const float* of = offattn + (size_t)bq * 384 + h * 32;
    const float* rp = refp + (size_t)bq * 8;
    unsigned long long acc[4] = {0ull, 0ull, 0ull, 0ull};   // 8 fp32 channels

    const int lWc[4]  = {100, 50, 25, 13};
    const int lHc[4]  = {100, 50, 25, 13};
    const int lPst[4] = {0, 10404, 13108, 13837};
    const int lW2[4]  = {102, 52, 27, 15};

    #pragma unroll
    for (int l = 0; l < 4; l++) {
        const int W = lWc[l], H = lHc[l], W2 = lW2[l];
        const __half* vb = valp
            + ((size_t)((b * NHh + h) * PADB) + lPst[l]) * 32 + k * 8;
        const float rx = rp[l * 2 + 0] * (float)W - 0.5f;
        const float ry = rp[l * 2 + 1] * (float)H - 0.5f;
        const float4 o01 = reinterpret_cast<const float4*>(of + l * 8)[0];
        const float4 o23 = reinterpret_cast<const float4*>(of + l * 8)[1];
        const float ox[4] = {o01.x, o01.z, o23.x, o23.z};
        const float oy[4] = {o01.y, o01.w, o23.y, o23.w};

        // per-level half2 accumulators (4 x half2 = 8 channels)
        uint32_t acch[4] = {0u, 0u, 0u, 0u};

        #pragma unroll
        for (int p = 0; p < 4; p++) {
            const float x = rx + ox[p];
            const float y = ry + oy[p];
            const float wgt = lg[l * 4 + p];

            const int x0 = __float2int_rd(x);
            const int y0 = __float2int_rd(y);
            const float wx1 = x - (float)x0, wy1 = y - (float)y0;
            const float wx0 = 1.f - wx1, wy0 = 1.f - wy1;

            const int px0 = x0 + 1;                 // padded col of left corner
            const int bx  = min(max(px0, 0), W);    // pair [bx, bx+1] in bounds
            const int yp0 = min(max(y0 + 1, 0), H + 1);
            const int yp1 = min(max(y0 + 2, 0), H + 1);

            const float wx0m = (px0 > W) ? 0.f : wx0;
            const float wx1m = (px0 < 0) ? 0.f : wx1;
            const float wsel = xs ? wx1m : wx0m;

            const float wA = wgt * wy0 * wsel;
            const float wB = wgt * wy1 * wsel;
            const uint32_t hA = pack_h2(wA, wA);
            const uint32_t hB = pack_h2(wB, wB);

            const uint4 v0 = *reinterpret_cast<const uint4*>(
                vb + (size_t)(yp0 * W2 + bx) * 32);
            const uint4 v1 = *reinterpret_cast<const uint4*>(
                vb + (size_t)(yp1 * W2 + bx) * 32);

            acch[0] = hfma2(v0.x, hA, acch[0]);
            acch[1] = hfma2(v0.y, hA, acch[1]);
            acch[2] = hfma2(v0.z, hA, acch[2]);
            acch[3] = hfma2(v0.w, hA, acch[3]);
            acch[0] = hfma2(v1.x, hB, acch[0]);
            acch[1] = hfma2(v1.y, hB, acch[1]);
            acch[2] = hfma2(v1.z, hB, acch[2]);
            acch[3] = hfma2(v1.w, hB, acch[3]);
        }

        // fold level sum into fp32 accumulators
        fadd2(acc[0], h2f2(acch[0]));
        fadd2(acc[1], h2f2(acch[1]));
        fadd2(acc[2], h2f2(acch[2]));
        fadd2(acc[3], h2f2(acch[3]));
    }

    // deferred softmax normalization
    const unsigned long long inv2 = bcast2(inv);
    #pragma unroll
    for (int j = 0; j < 4; j++) fmul2(acc[j], inv2);

    // merge the two x-slots (lane ^ 4 within the 8-lane group)
    #pragma unroll
    for (int j = 0; j < 4; j++) {
        const unsigned long long other =
            __shfl_xor_sync(0xffffffffu, acc[j], 4);
        fadd2(acc[j], other);
    }

    if (!xs) {
        uint4 outv;
        uint32_t a0, a1;
        asm("mov.b64 {%0, %1}, %2;" : "=r"(a0), "=r"(a1) : "l"(acc[0]));
        outv.x = pack_h2(__uint_as_float(a0), __uint_as_float(a1));
        asm("mov.b64 {%0, %1}, %2;" : "=r"(a0), "=r"(a1) : "l"(acc[1]));
        outv.y = pack_h2(__uint_as_float(a0), __uint_as_float(a1));
        asm("mov.b64 {%0, %1}, %2;" : "=r"(a0), "=r"(a1) : "l"(acc[2]));
        outv.z = pack_h2(__uint_as_float(a0), __uint_as_float(a1));
        asm("mov.b64 {%0, %1}, %2;" : "=r"(a0), "=r"(a1) : "l"(acc[3]));
        outv.w = pack_h2(__uint_as_float(a0), __uint_as_float(a1));
        *reinterpret_cast<uint4*>(
            out_acc + (size_t)bq * 256 + h * 32 + (k & 3) * 8) = outv;
    }
}

// ---------------------------------------------------------------------------
// Launch
// ---------------------------------------------------------------------------
extern "C" void kernel_launch(void* const* d_in, const int* in_sizes, int n_in,
                              void* d_out, int out_size)
{
    const float* query  = (const float*)d_in[0];
    const float* refp   = (const float*)d_in[1];
    const float* value  = (const float*)d_in[2];
    const float* W_val  = (const float*)d_in[3];
    const float* b_val  = (const float*)d_in[4];
    const float* W_off  = (const float*)d_in[5];
    const float* b_off  = (const float*)d_in[6];
    const float* W_attn = (const float*)d_in[7];
    const float* b_attn = (const float*)d_in[8];
    const float* W_out  = (const float*)d_in[9];
    const float* b_out  = (const float*)d_in[10];
    float* out = (float*)d_out;

    float  *poa, *pbias_oa;
    __half *pvalp, *pacc, *pqh, *pvh, *pbtv, *pbtoa, *pbto;
    cudaGetSymbolAddress((void**)&pvalp,    g_valp);
    cudaGetSymbolAddress((void**)&poa,      g_offattn);
    cudaGetSymbolAddress((void**)&pacc,     g_acc);
    cudaGetSymbolAddress((void**)&pqh,      g_query_h);
    cudaGetSymbolAddress((void**)&pvh,      g_value_h);
    cudaGetSymbolAddress((void**)&pbtv,     g_bt_val);
    cudaGetSymbolAddress((void**)&pbtoa,    g_bt_oa);
    cudaGetSymbolAddress((void**)&pbto,     g_bt_out);
    cudaGetSymbolAddress((void**)&pbias_oa, g_bias_oa);

    cudaFuncSetAttribute(gemm_stage1_kernel,
                         cudaFuncAttributeMaxDynamicSharedMemorySize, GEMM_SMEM);
    cudaFuncSetAttribute(gemm_out_kernel,
                         cudaFuncAttributeMaxDynamicSharedMemorySize, GEMM_SMEM);

    const dim3 blk(256);
    const int  gy = (MROWS + 127) / 128;
    const int  n4 = MROWS * 64;

    // 0a. weights -> half^T, bias fuse, query/value -> half
    prep_convert_kernel<<<(n4 + 255) / 256, blk>>>(
        W_val, W_off, W_attn, W_out, b_off, b_attn, query, value);
    // 0b. zero padded-value border rows (head-major)
    zero_border_kernel<<<dim3(768, 2), 64>>>();
    // 1+2+3. fused stage-1 GEMMs
    gemm_stage1_kernel<<<dim3(5, gy), blk, GEMM_SMEM>>>(
        pvh, pbtv, b_val, pqh, pbtoa, pbias_oa, poa);
    // 4. softmax + deformable bilinear sampling -> g_acc (half)
    sample_kernel<<<(MROWS * 2 + 3) / 4, dim3(128)>>>(refp, pvalp, poa, pacc);
    // 5. out = g_acc @ W_out + b_out
    gemm_out_kernel<<<dim3(2, gy), blk, GEMM_SMEM>>>(
        pacc, pbto, b_out, out, MROWS, 256);
}